// round 8
// baseline (speedup 1.0000x reference)
#include <cuda_runtime.h>
#include <cuda_bf16.h>
#include <stdint.h>
#include <math.h>

#define NN    4096
#define CC    512
#define HH    8
#define COH   64
#define EE    131072
#define QKVW  1536

// ---------------- fp32 scratch ----------------
#define S_XL   0L
#define S_XR   (S_XL  + (long)NN*CC)
#define S_HB   (S_XR  + (long)NN*CC)
#define S_X1   (S_HB  + (long)NN*CC)
#define S_X2   (S_X1  + (long)NN*CC)
#define S_TOT  (S_X2  + (long)NN*CC)
__device__ float g_scratch[S_TOT];

// ---------------- bf16 hi/lo scratch (hi at base, lo at base+size) ----------------
#define ZX    0L
#define ZX1   (ZX   + 2L*NN*CC)
#define ZATT  (ZX1  + 2L*NN*CC)
#define ZX2   (ZATT + 2L*NN*CC)
#define ZQKV  (ZX2  + 2L*NN*CC)
#define ZFFN  (ZQKV + 2L*NN*3*CC)
#define ZWL   (ZFFN + 2L*NN*4*CC)
#define ZWR   (ZWL  + 2L*CC*CC)
#define ZIN   (ZWR  + 2L*CC*CC)
#define ZOW   (ZIN  + 2L*3*CC*CC)
#define ZW1   (ZOW  + 2L*CC*CC)
#define ZW2   (ZW1  + 2L*4*CC*CC)
#define ZTOT  (ZW2  + 2L*4*CC*CC)
__device__ __nv_bfloat16 g_bf[ZTOT];

// int scratch
#define I_DEG  0
#define I_OFF  4096
#define I_POS  (I_OFF + 4097)
#define I_ESRC (I_POS + 4096)
__device__ int g_ints[I_ESRC + EE];

// ---------------- helpers ----------------
__device__ __forceinline__ void split2(float x0, float x1, unsigned &hi, unsigned &lo) {
    __nv_bfloat16 h0 = __float2bfloat16(x0);
    __nv_bfloat16 h1 = __float2bfloat16(x1);
    float r0 = x0 - __bfloat162float(h0);
    float r1 = x1 - __bfloat162float(h1);
    __nv_bfloat16 l0 = __float2bfloat16(r0);
    __nv_bfloat16 l1 = __float2bfloat16(r1);
    hi = ((unsigned)__bfloat16_as_ushort(h1) << 16) | (unsigned)__bfloat16_as_ushort(h0);
    lo = ((unsigned)__bfloat16_as_ushort(l1) << 16) | (unsigned)__bfloat16_as_ushort(l0);
}

__device__ __forceinline__ void mma16816(float* c, const unsigned* a, const unsigned* b) {
    asm volatile(
        "mma.sync.aligned.m16n8k16.row.col.f32.bf16.bf16.f32 "
        "{%0,%1,%2,%3}, {%4,%5,%6,%7}, {%8,%9}, {%0,%1,%2,%3};\n"
        : "+f"(c[0]), "+f"(c[1]), "+f"(c[2]), "+f"(c[3])
        : "r"(a[0]), "r"(a[1]), "r"(a[2]), "r"(a[3]), "r"(b[0]), "r"(b[1]));
}

__device__ __forceinline__ float geluf(float v) {
    return 0.5f * v * (1.f + erff(v * 0.70710678118654752f));
}

// ---------------- CSR build (edge_index int32 [2,E]) ----------------
__global__ void k_zero_deg() {
    int i = blockIdx.x * blockDim.x + threadIdx.x;
    if (i < NN) g_ints[I_DEG + i] = 0;
}
__global__ void k_count(const int* __restrict__ ei) {
    int e = blockIdx.x * blockDim.x + threadIdx.x;
    if (e < EE) atomicAdd(&g_ints[I_DEG + (ei[EE + e] & (NN - 1))], 1);
}
__global__ void k_scan() {
    __shared__ int ws[32];
    int t = threadIdx.x;
    int v[4]; int tot = 0;
#pragma unroll
    for (int j = 0; j < 4; j++) { v[j] = g_ints[I_DEG + t*4 + j]; tot += v[j]; }
    int lane = t & 31, wid = t >> 5;
    int sc = tot;
#pragma unroll
    for (int o = 1; o < 32; o <<= 1) {
        int y = __shfl_up_sync(0xffffffffu, sc, o);
        if (lane >= o) sc += y;
    }
    if (lane == 31) ws[wid] = sc;
    __syncthreads();
    if (wid == 0) {
        int z = ws[lane];
#pragma unroll
        for (int o = 1; o < 32; o <<= 1) {
            int y = __shfl_up_sync(0xffffffffu, z, o);
            if (lane >= o) z += y;
        }
        ws[lane] = z;
    }
    __syncthreads();
    int excl = sc - tot + (wid ? ws[wid - 1] : 0);
    int run = excl;
#pragma unroll
    for (int j = 0; j < 4; j++) {
        g_ints[I_OFF + t*4 + j] = run;
        g_ints[I_POS + t*4 + j] = run;
        run += v[j];
    }
    if (t == 1023) g_ints[I_OFF + 4096] = run;
}
__global__ void k_scatter(const int* __restrict__ ei) {
    int e = blockIdx.x * blockDim.x + threadIdx.x;
    if (e < EE) {
        int d = ei[EE + e] & (NN - 1);
        int s = ei[e] & (NN - 1);
        int p = atomicAdd(&g_ints[I_POS + d], 1);
        if (p >= 0 && p < EE) g_ints[I_ESRC + p] = s;
    }
}

// ---------------- fp32 -> bf16 hi/lo split ----------------
__global__ void k_split(const float* __restrict__ in, __nv_bfloat16* __restrict__ hi,
                        __nv_bfloat16* __restrict__ lo, int n4) {
    int i = blockIdx.x * blockDim.x + threadIdx.x;
    if (i >= n4) return;
    float4 v = ((const float4*)in)[i];
    unsigned h0, l0, h1, l1;
    split2(v.x, v.y, h0, l0); split2(v.z, v.w, h1, l1);
    ((uint2*)hi)[i] = make_uint2(h0, h1);
    ((uint2*)lo)[i] = make_uint2(l0, l1);
}

// ---------------- mma.sync NT GEMM on pre-split bf16 hi/lo ----------------
// C[M,Nd] = A[M,K] @ B[Nd,K]^T + bias;  BM=128 BN=64 BK=32, 256 thr, 8 warps (4Mx2N).
// 3-product hi/lo split. EPI: 0 fp32 out; 1 GELU->split bf16 out; 2 bias->split bf16 out.
template <int EPI>
__global__ void __launch_bounds__(256) k_gemm(
    const __nv_bfloat16* __restrict__ Ah, const __nv_bfloat16* __restrict__ Al,
    const __nv_bfloat16* __restrict__ Bh, const __nv_bfloat16* __restrict__ Bl,
    const float* __restrict__ bias, float* __restrict__ Cf,
    __nv_bfloat16* __restrict__ Ch, __nv_bfloat16* __restrict__ Cl,
    int Nd, int K) {
    __shared__ unsigned Ahs[128 * 20], Als[128 * 20];
    __shared__ unsigned Bhs[64 * 20],  Bls[64 * 20];

    int tid = threadIdx.x;
    int lane = tid & 31, wid = tid >> 5;
    int wm = wid & 3, wn = wid >> 2;
    int mBase = wm * 32, nBase = wn * 32;
    int g = lane >> 2, t = lane & 3;
    int bm = blockIdx.y * 128, bn = blockIdx.x * 64;

    float c[2][4][4];
#pragma unroll
    for (int mi = 0; mi < 2; mi++)
#pragma unroll
        for (int ni = 0; ni < 4; ni++)
#pragma unroll
            for (int j = 0; j < 4; j++) c[mi][ni][j] = 0.f;

    int lrow = tid >> 1;          // 0..127
    int lhalf = (tid & 1) * 16;   // bf16 offset within 32-wide k-chunk
    int soff0 = lrow * 20 + (tid & 1) * 8;

    for (int k0 = 0; k0 < K; k0 += 32) {
        {   // A tile 128x32 bf16 (hi+lo)
            long goff = (long)(bm + lrow) * K + k0 + lhalf;
            const uint4* ph = (const uint4*)&Ah[goff];
            const uint4* pl = (const uint4*)&Al[goff];
            uint4 h0 = ph[0], h1 = ph[1], l0 = pl[0], l1 = pl[1];
            *(uint4*)&Ahs[soff0] = h0; *(uint4*)&Ahs[soff0 + 4] = h1;
            *(uint4*)&Als[soff0] = l0; *(uint4*)&Als[soff0 + 4] = l1;
        }
        if (tid < 128) {   // B tile 64x32 bf16 (hi+lo)
            long goff = (long)(bn + lrow) * K + k0 + lhalf;
            const uint4* ph = (const uint4*)&Bh[goff];
            const uint4* pl = (const uint4*)&Bl[goff];
            uint4 h0 = ph[0], h1 = ph[1], l0 = pl[0], l1 = pl[1];
            *(uint4*)&Bhs[soff0] = h0; *(uint4*)&Bhs[soff0 + 4] = h1;
            *(uint4*)&Bls[soff0] = l0; *(uint4*)&Bls[soff0 + 4] = l1;
        }
        __syncthreads();

#pragma unroll
        for (int ks = 0; ks < 2; ks++) {
            unsigned ah[2][4], al[2][4], bh[4][2], bl[4][2];
#pragma unroll
            for (int mi = 0; mi < 2; mi++) {
                int r0 = (mBase + mi * 16 + g) * 20 + 8 * ks + t;
                int r1 = r0 + 8 * 20;
                ah[mi][0] = Ahs[r0];     al[mi][0] = Als[r0];
                ah[mi][1] = Ahs[r1];     al[mi][1] = Als[r1];
                ah[mi][2] = Ahs[r0 + 4]; al[mi][2] = Als[r0 + 4];
                ah[mi][3] = Ahs[r1 + 4]; al[mi][3] = Als[r1 + 4];
            }
#pragma unroll
            for (int ni = 0; ni < 4; ni++) {
                int rn = (nBase + ni * 8 + g) * 20 + 8 * ks + t;
                bh[ni][0] = Bhs[rn];     bl[ni][0] = Bls[rn];
                bh[ni][1] = Bhs[rn + 4]; bl[ni][1] = Bls[rn + 4];
            }
#pragma unroll
            for (int mi = 0; mi < 2; mi++)
#pragma unroll
                for (int ni = 0; ni < 4; ni++) {
                    mma16816(c[mi][ni], al[mi], bh[ni]);
                    mma16816(c[mi][ni], ah[mi], bl[ni]);
                    mma16816(c[mi][ni], ah[mi], bh[ni]);
                }
        }
        __syncthreads();
    }

    // epilogue
#pragma unroll
    for (int mi = 0; mi < 2; mi++)
#pragma unroll
        for (int ni = 0; ni < 4; ni++) {
            int n0 = bn + nBase + ni * 8 + 2 * t;
            long r0 = bm + mBase + mi * 16 + g;
            float v0 = c[mi][ni][0] + bias[n0];
            float v1 = c[mi][ni][1] + bias[n0 + 1];
            float v2 = c[mi][ni][2] + bias[n0];
            float v3 = c[mi][ni][3] + bias[n0 + 1];
            if (EPI == 0) {
                Cf[r0 * Nd + n0]           = v0;
                Cf[r0 * Nd + n0 + 1]       = v1;
                Cf[(r0 + 8) * Nd + n0]     = v2;
                Cf[(r0 + 8) * Nd + n0 + 1] = v3;
            } else {
                if (EPI == 1) { v0 = geluf(v0); v1 = geluf(v1); v2 = geluf(v2); v3 = geluf(v3); }
                unsigned hp, lp;
                split2(v0, v1, hp, lp);
                *(unsigned*)&Ch[r0 * Nd + n0] = hp;
                *(unsigned*)&Cl[r0 * Nd + n0] = lp;
                split2(v2, v3, hp, lp);
                *(unsigned*)&Ch[(r0 + 8) * Nd + n0] = hp;
                *(unsigned*)&Cl[(r0 + 8) * Nd + n0] = lp;
            }
        }
}

// ---------------- GAT per-node online softmax aggregation ----------------
__global__ void k_gat(const float* __restrict__ xl, const float* __restrict__ xr,
                      const float* __restrict__ att, const float* __restrict__ gbias,
                      float* __restrict__ outp) {
    int i = blockIdx.x;
    int w = threadIdx.x >> 5;
    int lane = threadIdx.x & 31;
    int c0 = lane, c1 = lane + 32;
    const float* xli = xl + (long)i * CC + w * COH;
    float xl0 = xli[c0], xl1 = xli[c1];
    float a0 = att[w * COH + c0], a1 = att[w * COH + c1];
    float m = -1e30f, l = 0.f, acc0 = 0.f, acc1 = 0.f;
    int beg = g_ints[I_OFF + i], end = g_ints[I_OFF + i + 1];
    for (int j = beg; j <= end; j++) {
        int s = (j < end) ? g_ints[I_ESRC + j] : i;
        const float* xrs = xr + (long)s * CC + w * COH;
        float xr0 = xrs[c0], xr1 = xrs[c1];
        float e0 = xl0 + xr0; e0 = (e0 > 0.f) ? e0 : 0.2f * e0;
        float e1 = xl1 + xr1; e1 = (e1 > 0.f) ? e1 : 0.2f * e1;
        float p = e0 * a0 + e1 * a1;
#pragma unroll
        for (int o = 16; o; o >>= 1) p += __shfl_xor_sync(0xffffffffu, p, o);
        float mn = fmaxf(m, p);
        float sc = __expf(m - mn);
        float wg = __expf(p - mn);
        l = l * sc + wg;
        acc0 = acc0 * sc + xr0 * wg;
        acc1 = acc1 * sc + xr1 * wg;
        m = mn;
    }
    float inv = 1.f / l;
    outp[(long)i * CC + w * COH + c0] = acc0 * inv + gbias[w * COH + c0];
    outp[(long)i * CC + w * COH + c1] = acc1 * inv + gbias[w * COH + c1];
}

// ---------------- residual add + layernorm (+ optional bf16 split out) ----------------
__global__ void k_add_ln(const float* __restrict__ x, const float* __restrict__ h,
                         const float* __restrict__ g, const float* __restrict__ b,
                         float* __restrict__ outp,
                         __nv_bfloat16* __restrict__ oh, __nv_bfloat16* __restrict__ ol) {
    int row = blockIdx.x;
    int t = threadIdx.x;
    __shared__ float sh[8];
    float v0 = x[(long)row * CC + t]       + h[(long)row * CC + t];
    float v1 = x[(long)row * CC + 256 + t] + h[(long)row * CC + 256 + t];
    float s = v0 + v1;
#pragma unroll
    for (int o = 16; o; o >>= 1) s += __shfl_xor_sync(0xffffffffu, s, o);
    if ((t & 31) == 0) sh[t >> 5] = s;
    __syncthreads();
    float tot = 0.f;
#pragma unroll
    for (int i = 0; i < 8; i++) tot += sh[i];
    float mu = tot * (1.f / 512.f);
    __syncthreads();
    float d0 = v0 - mu, d1 = v1 - mu;
    float q = d0 * d0 + d1 * d1;
#pragma unroll
    for (int o = 16; o; o >>= 1) q += __shfl_xor_sync(0xffffffffu, q, o);
    if ((t & 31) == 0) sh[t >> 5] = q;
    __syncthreads();
    float var = 0.f;
#pragma unroll
    for (int i = 0; i < 8; i++) var += sh[i];
    var *= (1.f / 512.f);
    float rstd = rsqrtf(var + 1e-5f);
    float y0 = d0 * rstd * g[t]       + b[t];
    float y1 = d1 * rstd * g[t + 256] + b[t + 256];
    outp[(long)row * CC + t]       = y0;
    outp[(long)row * CC + 256 + t] = y1;
    if (oh) {
        __nv_bfloat16 h0 = __float2bfloat16(y0);
        __nv_bfloat16 h1 = __float2bfloat16(y1);
        oh[(long)row * CC + t]       = h0;
        oh[(long)row * CC + 256 + t] = h1;
        ol[(long)row * CC + t]       = __float2bfloat16(y0 - __bfloat162float(h0));
        ol[(long)row * CC + 256 + t] = __float2bfloat16(y1 - __bfloat162float(h1));
    }
}

// ---------------- flash attention, mma.sync, pre-split bf16 QKV in/out ----------------
#define FQH 0
#define FQL 2304
#define FKH 4608
#define FKL 6912
#define FVH 9216
#define FVL 11520
#define FLASH_SMEM (13824 * 4)

__global__ void __launch_bounds__(128) k_flash(const __nv_bfloat16* __restrict__ qkvh,
                                               const __nv_bfloat16* __restrict__ qkvl,
                                               __nv_bfloat16* __restrict__ ath,
                                               __nv_bfloat16* __restrict__ atl) {
    extern __shared__ unsigned sm[];
    int h = blockIdx.y;
    int q0 = blockIdx.x * 64;
    int tid = threadIdx.x;
    int lane = tid & 31, wid = tid >> 5;
    int g = lane >> 2, t = lane & 3;
    int mBase = wid * 16;
    const float qs2 = 0.125f * 1.44269504088896f;   // applied to raw scores

    // Q tile copy (64 rows x 32 uints per array)
#pragma unroll
    for (int i = 0; i < 4; i++) {
        int cchunk = tid + i * 128;        // 512 uint4s
        int r = cchunk >> 3;
        int q4 = cchunk & 7;
        long goff = (long)(q0 + r) * QKVW + h * COH + q4 * 8;
        *(uint4*)&sm[FQH + r * 36 + q4 * 4] = *(const uint4*)&qkvh[goff];
        *(uint4*)&sm[FQL + r * 36 + q4 * 4] = *(const uint4*)&qkvl[goff];
    }

    float m0 = -1e30f, m1 = -1e30f, l0s = 0.f, l1s = 0.f;
    float o[8][4];
#pragma unroll
    for (int nd = 0; nd < 8; nd++)
#pragma unroll
        for (int j = 0; j < 4; j++) o[nd][j] = 0.f;

    for (int kv0 = 0; kv0 < NN; kv0 += 64) {
        __syncthreads();
        // K tile copy
#pragma unroll
        for (int i = 0; i < 4; i++) {
            int cchunk = tid + i * 128;
            int r = cchunk >> 3;
            int q4 = cchunk & 7;
            long goff = (long)(kv0 + r) * QKVW + CC + h * COH + q4 * 8;
            *(uint4*)&sm[FKH + r * 36 + q4 * 4] = *(const uint4*)&qkvh[goff];
            *(uint4*)&sm[FKL + r * 36 + q4 * 4] = *(const uint4*)&qkvl[goff];
        }
        // V tile transposed: V[d][kv] shorts
        {
            unsigned short* Vhu = (unsigned short*)&sm[FVH];
            unsigned short* Vlu = (unsigned short*)&sm[FVL];
            int r = tid >> 1;
            int dbase = (tid & 1) * 32;
            long goff = (long)(kv0 + r) * QKVW + 2 * CC + h * COH + dbase;
#pragma unroll
            for (int q4 = 0; q4 < 4; q4++) {
                uint4 vh = *(const uint4*)&qkvh[goff + q4 * 8];
                uint4 vl = *(const uint4*)&qkvl[goff + q4 * 8];
                int d = dbase + q4 * 8;
                const unsigned hw[4] = {vh.x, vh.y, vh.z, vh.w};
                const unsigned lw[4] = {vl.x, vl.y, vl.z, vl.w};
#pragma unroll
                for (int e = 0; e < 4; e++) {
                    Vhu[(d + 2*e)     * 72 + r] = (unsigned short)(hw[e] & 0xFFFF);
                    Vhu[(d + 2*e + 1) * 72 + r] = (unsigned short)(hw[e] >> 16);
                    Vlu[(d + 2*e)     * 72 + r] = (unsigned short)(lw[e] & 0xFFFF);
                    Vlu[(d + 2*e + 1) * 72 + r] = (unsigned short)(lw[e] >> 16);
                }
            }
        }
        __syncthreads();

        // S = Q K^T (raw), then scale by qs2
        float s[8][4];
#pragma unroll
        for (int ni = 0; ni < 8; ni++)
#pragma unroll
            for (int j = 0; j < 4; j++) s[ni][j] = 0.f;

#pragma unroll
        for (int ks = 0; ks < 4; ks++) {
            unsigned ah[4], al[4];
            int r0 = (mBase + g) * 36 + 8 * ks + t;
            int r1 = r0 + 8 * 36;
            ah[0] = sm[FQH + r0];     al[0] = sm[FQL + r0];
            ah[1] = sm[FQH + r1];     al[1] = sm[FQL + r1];
            ah[2] = sm[FQH + r0 + 4]; al[2] = sm[FQL + r0 + 4];
            ah[3] = sm[FQH + r1 + 4]; al[3] = sm[FQL + r1 + 4];
#pragma unroll
            for (int ni = 0; ni < 8; ni++) {
                int rn = (ni * 8 + g) * 36 + 8 * ks + t;
                unsigned bh[2], bl[2];
                bh[0] = sm[FKH + rn];     bl[0] = sm[FKL + rn];
                bh[1] = sm[FKH + rn + 4]; bl[1] = sm[FKL + rn + 4];
                mma16816(s[ni], al, bh);
                mma16816(s[ni], ah, bl);
                mma16816(s[ni], ah, bh);
            }
        }
#pragma unroll
        for (int ni = 0; ni < 8; ni++)
#pragma unroll
            for (int j = 0; j < 4; j++) s[ni][j] *= qs2;

        // online softmax (base-2)
        float mx0 = -1e30f, mx1 = -1e30f;
#pragma unroll
        for (int ni = 0; ni < 8; ni++) {
            mx0 = fmaxf(mx0, fmaxf(s[ni][0], s[ni][1]));
            mx1 = fmaxf(mx1, fmaxf(s[ni][2], s[ni][3]));
        }
        mx0 = fmaxf(mx0, __shfl_xor_sync(0xffffffffu, mx0, 1));
        mx0 = fmaxf(mx0, __shfl_xor_sync(0xffffffffu, mx0, 2));
        mx1 = fmaxf(mx1, __shfl_xor_sync(0xffffffffu, mx1, 1));
        mx1 = fmaxf(mx1, __shfl_xor_sync(0xffffffffu, mx1, 2));
        float mn0 = fmaxf(m0, mx0), mn1 = fmaxf(m1, mx1);
        float sc0 = exp2f(m0 - mn0), sc1 = exp2f(m1 - mn1);
        m0 = mn0; m1 = mn1;
        float sum0 = 0.f, sum1 = 0.f;
#pragma unroll
        for (int ni = 0; ni < 8; ni++) {
            s[ni][0] = exp2f(s[ni][0] - m0); sum0 += s[ni][0];
            s[ni][1] = exp2f(s[ni][1] - m0); sum0 += s[ni][1];
            s[ni][2] = exp2f(s[ni][2] - m1); sum1 += s[ni][2];
            s[ni][3] = exp2f(s[ni][3] - m1); sum1 += s[ni][3];
        }
        sum0 += __shfl_xor_sync(0xffffffffu, sum0, 1);
        sum0 += __shfl_xor_sync(0xffffffffu, sum0, 2);
        sum1 += __shfl_xor_sync(0xffffffffu, sum1, 1);
        sum1 += __shfl_xor_sync(0xffffffffu, sum1, 2);
        l0s = l0s * sc0 + sum0;
        l1s = l1s * sc1 + sum1;
#pragma unroll
        for (int nd = 0; nd < 8; nd++) {
            o[nd][0] *= sc0; o[nd][1] *= sc0;
            o[nd][2] *= sc1; o[nd][3] *= sc1;
        }

        // O += P V
#pragma unroll
        for (int ks = 0; ks < 4; ks++) {
            unsigned ph[4], pl[4];
            split2(s[2*ks][0],   s[2*ks][1],   ph[0], pl[0]);
            split2(s[2*ks][2],   s[2*ks][3],   ph[1], pl[1]);
            split2(s[2*ks+1][0], s[2*ks+1][1], ph[2], pl[2]);
            split2(s[2*ks+1][2], s[2*ks+1][3], ph[3], pl[3]);
#pragma unroll
            for (int nd = 0; nd < 8; nd++) {
                int rn = (nd * 8 + g) * 36 + 8 * ks + t;
                unsigned bh[2], bl[2];
                bh[0] = sm[FVH + rn];     bl[0] = sm[FVL + rn];
                bh[1] = sm[FVH + rn + 4]; bl[1] = sm[FVL + rn + 4];
                mma16816(o[nd], pl, bh);
                mma16816(o[nd], ph, bl);
                mma16816(o[nd], ph, bh);
            }
        }
    }

    float inv0 = 1.f / l0s, inv1 = 1.f / l1s;
#pragma unroll
    for (int nd = 0; nd < 8; nd++) {
        int ccol = h * COH + nd * 8 + 2 * t;
        long r0 = q0 + mBase + g;
        unsigned hp, lp;
        split2(o[nd][0] * inv0, o[nd][1] * inv0, hp, lp);
        *(unsigned*)&ath[r0 * CC + ccol] = hp;
        *(unsigned*)&atl[r0 * CC + ccol] = lp;
        split2(o[nd][2] * inv1, o[nd][3] * inv1, hp, lp);
        *(unsigned*)&ath[(r0 + 8) * CC + ccol] = hp;
        *(unsigned*)&atl[(r0 + 8) * CC + ccol] = lp;
    }
}

// ---------------- launch ----------------
extern "C" void kernel_launch(void* const* d_in, const int* in_sizes, int n_in,
                              void* d_out, int out_size) {
    const float* x      = (const float*)d_in[0];
    const int*   ei     = (const int*)d_in[1];
    const float* gat_wl = (const float*)d_in[2];
    const float* gat_bl = (const float*)d_in[3];
    const float* gat_wr = (const float*)d_in[4];
    const float* gat_br = (const float*)d_in[5];
    const float* gat_at = (const float*)d_in[6];
    const float* gat_b  = (const float*)d_in[7];
    const float* in_w   = (const float*)d_in[8];
    const float* in_b   = (const float*)d_in[9];
    const float* out_w  = (const float*)d_in[10];
    const float* out_b  = (const float*)d_in[11];
    const float* ln1_g  = (const float*)d_in[12];
    const float* ln1_b  = (const float*)d_in[13];
    const float* ln2_g  = (const float*)d_in[14];
    const float* ln2_b  = (const float*)d_in[15];
    const float* ln3_g  = (const float*)d_in[16];
    const float* ln3_b  = (const float*)d_in[17];
    const float* w1     = (const float*)d_in[18];
    const float* b1     = (const float*)d_in[19];
    const float* w2     = (const float*)d_in[20];
    const float* b2     = (const float*)d_in[21];
    float* outp = (float*)d_out;

    float* gs = nullptr;
    cudaGetSymbolAddress((void**)&gs, g_scratch);
    __nv_bfloat16* gb = nullptr;
    cudaGetSymbolAddress((void**)&gb, g_bf);

    cudaFuncSetAttribute(k_flash, cudaFuncAttributeMaxDynamicSharedMemorySize, FLASH_SMEM);

    __nv_bfloat16 *Xh = gb + ZX,    *Xl = Xh + (long)NN*CC;
    __nv_bfloat16 *X1h = gb + ZX1,  *X1l = X1h + (long)NN*CC;
    __nv_bfloat16 *Ath = gb + ZATT, *Atl = Ath + (long)NN*CC;
    __nv_bfloat16 *X2h = gb + ZX2,  *X2l = X2h + (long)NN*CC;
    __nv_bfloat16 *Qh = gb + ZQKV,  *Ql = Qh + (long)NN*3*CC;
    __nv_bfloat16 *Fh = gb + ZFFN,  *Fl = Fh + (long)NN*4*CC;
    __nv_bfloat16 *WLh = gb + ZWL,  *WLl = WLh + (long)CC*CC;
    __nv_bfloat16 *WRh = gb + ZWR,  *WRl = WRh + (long)CC*CC;
    __nv_bfloat16 *INh = gb + ZIN,  *INl = INh + (long)3*CC*CC;
    __nv_bfloat16 *OWh = gb + ZOW,  *OWl = OWh + (long)CC*CC;
    __nv_bfloat16 *W1h = gb + ZW1,  *W1l = W1h + (long)4*CC*CC;
    __nv_bfloat16 *W2h = gb + ZW2,  *W2l = W2h + (long)4*CC*CC;

    // CSR build
    k_zero_deg<<<16, 256>>>();
    k_count<<<EE / 256, 256>>>(ei);
    k_scan<<<1, 1024>>>();
    k_scatter<<<EE / 256, 256>>>(ei);

    // pre-split x + weights
    k_split<<<(NN*CC/4 + 255)/256, 256>>>(x, Xh, Xl, NN*CC/4);
    k_split<<<(CC*CC/4 + 255)/256, 256>>>(gat_wl, WLh, WLl, CC*CC/4);
    k_split<<<(CC*CC/4 + 255)/256, 256>>>(gat_wr, WRh, WRl, CC*CC/4);
    k_split<<<(3*CC*CC/4 + 255)/256, 256>>>(in_w, INh, INl, 3*CC*CC/4);
    k_split<<<(CC*CC/4 + 255)/256, 256>>>(out_w, OWh, OWl, CC*CC/4);
    k_split<<<(4*CC*CC/4 + 255)/256, 256>>>(w1, W1h, W1l, 4*CC*CC/4);
    k_split<<<(4*CC*CC/4 + 255)/256, 256>>>(w2, W2h, W2l, 4*CC*CC/4);

    // GAT projections (fp32 out)
    dim3 g512(CC / 64, NN / 128);
    k_gemm<0><<<g512, 256>>>(Xh, Xl, WLh, WLl, gat_bl, gs + S_XL, 0, 0, CC, CC);
    k_gemm<0><<<g512, 256>>>(Xh, Xl, WRh, WRl, gat_br, gs + S_XR, 0, 0, CC, CC);

    // GAT aggregation
    k_gat<<<NN, 256>>>(gs + S_XL, gs + S_XR, gat_at, gat_b, gs + S_HB);

    // x1 = LN(x + h_local), + split
    k_add_ln<<<NN, 256>>>(x, gs + S_HB, ln1_g, ln1_b, gs + S_X1, X1h, X1l);

    // QKV (split bf16 out)
    dim3 gqkv(QKVW / 64, NN / 128);
    k_gemm<2><<<gqkv, 256>>>(X1h, X1l, INh, INl, in_b, 0, Qh, Ql, QKVW, CC);

    // flash attention (split in, split out)
    dim3 gfl(NN / 64, HH);
    k_flash<<<gfl, 128, FLASH_SMEM>>>(Qh, Ql, Ath, Atl);

    // out proj (fp32 out)
    k_gemm<0><<<g512, 256>>>(Ath, Atl, OWh, OWl, out_b, gs + S_HB, 0, 0, CC, CC);

    // x2 = LN(x1 + h_global), + split
    k_add_ln<<<NN, 256>>>(gs + S_X1, gs + S_HB, ln2_g, ln2_b, gs + S_X2, X2h, X2l);

    // FFN1 (GELU, split bf16 out)
    dim3 gffn1(4 * CC / 64, NN / 128);
    k_gemm<1><<<gffn1, 256>>>(X2h, X2l, W1h, W1l, b1, 0, Fh, Fl, 4 * CC, CC);
    // FFN2 (fp32 out)
    k_gemm<0><<<g512, 256>>>(Fh, Fl, W2h, W2l, b2, gs + S_HB, 0, 0, CC, 4 * CC);

    // out = LN(x2 + ffn)
    k_add_ln<<<NN, 256>>>(gs + S_X2, gs + S_HB, ln3_g, ln3_b, outp, 0, 0);
}

// round 9
// speedup vs baseline: 1.2884x; 1.2884x over previous
#include <cuda_runtime.h>
#include <cuda_fp16.h>
#include <stdint.h>
#include <math.h>

#define NN    4096
#define CC    512
#define HH    8
#define COH   64
#define EE    131072
#define QKVW  1536

// ---------------- fp32 scratch ----------------
#define S_XL   0L
#define S_XR   (S_XL  + (long)NN*CC)
#define S_HB   (S_XR  + (long)NN*CC)
#define S_X1   (S_HB  + (long)NN*CC)
#define S_X2   (S_X1  + (long)NN*CC)
#define S_TOT  (S_X2  + (long)NN*CC)
__device__ float g_scratch[S_TOT];

// ---------------- fp16 scratch: activations hi+lo, weights hi only ----------------
#define ZX    0L
#define ZX1   (ZX   + 2L*NN*CC)
#define ZATT  (ZX1  + 2L*NN*CC)
#define ZX2   (ZATT + 2L*NN*CC)
#define ZQKV  (ZX2  + 2L*NN*CC)
#define ZFFN  (ZQKV + 2L*NN*3*CC)
#define ZWL   (ZFFN + 2L*NN*4*CC)
#define ZWR   (ZWL  + 1L*CC*CC)
#define ZIN   (ZWR  + 1L*CC*CC)
#define ZOW   (ZIN  + 3L*CC*CC)
#define ZW1   (ZOW  + 1L*CC*CC)
#define ZW2   (ZW1  + 4L*CC*CC)
#define ZTOT  (ZW2  + 4L*CC*CC)
__device__ __half g_hf[ZTOT];

// int scratch
#define I_DEG  0
#define I_OFF  4096
#define I_POS  (I_OFF + 4097)
#define I_ESRC (I_POS + 4096)
__device__ int g_ints[I_ESRC + EE];

// ---------------- helpers ----------------
__device__ __forceinline__ void split2h(float x0, float x1, unsigned &hi, unsigned &lo) {
    __half h0 = __float2half_rn(x0);
    __half h1 = __float2half_rn(x1);
    float r0 = x0 - __half2float(h0);
    float r1 = x1 - __half2float(h1);
    __half l0 = __float2half_rn(r0);
    __half l1 = __float2half_rn(r1);
    hi = ((unsigned)__half_as_ushort(h1) << 16) | (unsigned)__half_as_ushort(h0);
    lo = ((unsigned)__half_as_ushort(l1) << 16) | (unsigned)__half_as_ushort(l0);
}

__device__ __forceinline__ unsigned pack2h(float x0, float x1) {
    return ((unsigned)__half_as_ushort(__float2half_rn(x1)) << 16) |
           (unsigned)__half_as_ushort(__float2half_rn(x0));
}

__device__ __forceinline__ void mma16816h(float* c, const unsigned* a, const unsigned* b) {
    asm volatile(
        "mma.sync.aligned.m16n8k16.row.col.f32.f16.f16.f32 "
        "{%0,%1,%2,%3}, {%4,%5,%6,%7}, {%8,%9}, {%0,%1,%2,%3};\n"
        : "+f"(c[0]), "+f"(c[1]), "+f"(c[2]), "+f"(c[3])
        : "r"(a[0]), "r"(a[1]), "r"(a[2]), "r"(a[3]), "r"(b[0]), "r"(b[1]));
}

__device__ __forceinline__ float geluf(float v) {
    return 0.5f * v * (1.f + erff(v * 0.70710678118654752f));
}

// ---------------- CSR build (edge_index int32 [2,E]) ----------------
__global__ void k_zero_deg() {
    int i = blockIdx.x * blockDim.x + threadIdx.x;
    if (i < NN) g_ints[I_DEG + i] = 0;
}
__global__ void k_count(const int* __restrict__ ei) {
    int e = blockIdx.x * blockDim.x + threadIdx.x;
    if (e < EE) atomicAdd(&g_ints[I_DEG + (ei[EE + e] & (NN - 1))], 1);
}
__global__ void k_scan() {
    __shared__ int ws[32];
    int t = threadIdx.x;
    int v[4]; int tot = 0;
#pragma unroll
    for (int j = 0; j < 4; j++) { v[j] = g_ints[I_DEG + t*4 + j]; tot += v[j]; }
    int lane = t & 31, wid = t >> 5;
    int sc = tot;
#pragma unroll
    for (int o = 1; o < 32; o <<= 1) {
        int y = __shfl_up_sync(0xffffffffu, sc, o);
        if (lane >= o) sc += y;
    }
    if (lane == 31) ws[wid] = sc;
    __syncthreads();
    if (wid == 0) {
        int z = ws[lane];
#pragma unroll
        for (int o = 1; o < 32; o <<= 1) {
            int y = __shfl_up_sync(0xffffffffu, z, o);
            if (lane >= o) z += y;
        }
        ws[lane] = z;
    }
    __syncthreads();
    int excl = sc - tot + (wid ? ws[wid - 1] : 0);
    int run = excl;
#pragma unroll
    for (int j = 0; j < 4; j++) {
        g_ints[I_OFF + t*4 + j] = run;
        g_ints[I_POS + t*4 + j] = run;
        run += v[j];
    }
    if (t == 1023) g_ints[I_OFF + 4096] = run;
}
__global__ void k_scatter(const int* __restrict__ ei) {
    int e = blockIdx.x * blockDim.x + threadIdx.x;
    if (e < EE) {
        int d = ei[EE + e] & (NN - 1);
        int s = ei[e] & (NN - 1);
        int p = atomicAdd(&g_ints[I_POS + d], 1);
        if (p >= 0 && p < EE) g_ints[I_ESRC + p] = s;
    }
}

// ---------------- fp32 -> fp16 hi/lo split (activations) ----------------
__global__ void k_split(const float* __restrict__ in, __half* __restrict__ hi,
                        __half* __restrict__ lo, int n4) {
    int i = blockIdx.x * blockDim.x + threadIdx.x;
    if (i >= n4) return;
    float4 v = ((const float4*)in)[i];
    unsigned h0, l0, h1, l1;
    split2h(v.x, v.y, h0, l0); split2h(v.z, v.w, h1, l1);
    ((uint2*)hi)[i] = make_uint2(h0, h1);
    ((uint2*)lo)[i] = make_uint2(l0, l1);
}

// ---------------- fp32 -> fp16 convert (weights, hi only) ----------------
__global__ void k_half(const float* __restrict__ in, __half* __restrict__ hi, int n4) {
    int i = blockIdx.x * blockDim.x + threadIdx.x;
    if (i >= n4) return;
    float4 v = ((const float4*)in)[i];
    ((uint2*)hi)[i] = make_uint2(pack2h(v.x, v.y), pack2h(v.z, v.w));
}

// ---------------- mma.sync NT GEMM, fp16 2-product ----------------
// C[M,Nd] = A[M,K] @ B[Nd,K]^T + bias;  BM=128 BN=64 BK=32, 256 thr, 8 warps (4Mx2N).
// A split hi+lo, B hi only. EPI: 0 fp32 out; 1 GELU->split fp16; 2 bias->split fp16.
template <int EPI>
__global__ void __launch_bounds__(256) k_gemm(
    const __half* __restrict__ Ah, const __half* __restrict__ Al,
    const __half* __restrict__ Bh,
    const float* __restrict__ bias, float* __restrict__ Cf,
    __half* __restrict__ Ch, __half* __restrict__ Cl,
    int Nd, int K) {
    __shared__ unsigned Ahs[128 * 20], Als[128 * 20];
    __shared__ unsigned Bhs[64 * 20];

    int tid = threadIdx.x;
    int lane = tid & 31, wid = tid >> 5;
    int wm = wid & 3, wn = wid >> 2;
    int mBase = wm * 32, nBase = wn * 32;
    int g = lane >> 2, t = lane & 3;
    int bm = blockIdx.y * 128, bn = blockIdx.x * 64;

    float c[2][4][4];
#pragma unroll
    for (int mi = 0; mi < 2; mi++)
#pragma unroll
        for (int ni = 0; ni < 4; ni++)
#pragma unroll
            for (int j = 0; j < 4; j++) c[mi][ni][j] = 0.f;

    int lrow = tid >> 1;
    int lhalf = (tid & 1) * 16;
    int soff0 = lrow * 20 + (tid & 1) * 8;

    for (int k0 = 0; k0 < K; k0 += 32) {
        {   // A tile 128x32 fp16 (hi+lo)
            long goff = (long)(bm + lrow) * K + k0 + lhalf;
            const uint4* ph = (const uint4*)&Ah[goff];
            const uint4* pl = (const uint4*)&Al[goff];
            uint4 h0 = ph[0], h1 = ph[1], l0 = pl[0], l1 = pl[1];
            *(uint4*)&Ahs[soff0] = h0; *(uint4*)&Ahs[soff0 + 4] = h1;
            *(uint4*)&Als[soff0] = l0; *(uint4*)&Als[soff0 + 4] = l1;
        }
        if (tid < 128) {   // B tile 64x32 fp16 (hi only)
            long goff = (long)(bn + lrow) * K + k0 + lhalf;
            const uint4* ph = (const uint4*)&Bh[goff];
            uint4 h0 = ph[0], h1 = ph[1];
            *(uint4*)&Bhs[soff0] = h0; *(uint4*)&Bhs[soff0 + 4] = h1;
        }
        __syncthreads();

#pragma unroll
        for (int ks = 0; ks < 2; ks++) {
            unsigned ah[2][4], al[2][4], bh[4][2];
#pragma unroll
            for (int mi = 0; mi < 2; mi++) {
                int r0 = (mBase + mi * 16 + g) * 20 + 8 * ks + t;
                int r1 = r0 + 8 * 20;
                ah[mi][0] = Ahs[r0];     al[mi][0] = Als[r0];
                ah[mi][1] = Ahs[r1];     al[mi][1] = Als[r1];
                ah[mi][2] = Ahs[r0 + 4]; al[mi][2] = Als[r0 + 4];
                ah[mi][3] = Ahs[r1 + 4]; al[mi][3] = Als[r1 + 4];
            }
#pragma unroll
            for (int ni = 0; ni < 4; ni++) {
                int rn = (nBase + ni * 8 + g) * 20 + 8 * ks + t;
                bh[ni][0] = Bhs[rn];
                bh[ni][1] = Bhs[rn + 4];
            }
#pragma unroll
            for (int mi = 0; mi < 2; mi++)
#pragma unroll
                for (int ni = 0; ni < 4; ni++) {
                    mma16816h(c[mi][ni], al[mi], bh[ni]);
                    mma16816h(c[mi][ni], ah[mi], bh[ni]);
                }
        }
        __syncthreads();
    }

    // epilogue
#pragma unroll
    for (int mi = 0; mi < 2; mi++)
#pragma unroll
        for (int ni = 0; ni < 4; ni++) {
            int n0 = bn + nBase + ni * 8 + 2 * t;
            long r0 = bm + mBase + mi * 16 + g;
            float v0 = c[mi][ni][0] + bias[n0];
            float v1 = c[mi][ni][1] + bias[n0 + 1];
            float v2 = c[mi][ni][2] + bias[n0];
            float v3 = c[mi][ni][3] + bias[n0 + 1];
            if (EPI == 0) {
                Cf[r0 * Nd + n0]           = v0;
                Cf[r0 * Nd + n0 + 1]       = v1;
                Cf[(r0 + 8) * Nd + n0]     = v2;
                Cf[(r0 + 8) * Nd + n0 + 1] = v3;
            } else {
                if (EPI == 1) { v0 = geluf(v0); v1 = geluf(v1); v2 = geluf(v2); v3 = geluf(v3); }
                unsigned hp, lp;
                split2h(v0, v1, hp, lp);
                *(unsigned*)&Ch[r0 * Nd + n0] = hp;
                *(unsigned*)&Cl[r0 * Nd + n0] = lp;
                split2h(v2, v3, hp, lp);
                *(unsigned*)&Ch[(r0 + 8) * Nd + n0] = hp;
                *(unsigned*)&Cl[(r0 + 8) * Nd + n0] = lp;
            }
        }
}

// ---------------- GAT per-node online softmax aggregation ----------------
__global__ void k_gat(const float* __restrict__ xl, const float* __restrict__ xr,
                      const float* __restrict__ att, const float* __restrict__ gbias,
                      float* __restrict__ outp) {
    int i = blockIdx.x;
    int w = threadIdx.x >> 5;
    int lane = threadIdx.x & 31;
    int c0 = lane, c1 = lane + 32;
    const float* xli = xl + (long)i * CC + w * COH;
    float xl0 = xli[c0], xl1 = xli[c1];
    float a0 = att[w * COH + c0], a1 = att[w * COH + c1];
    float m = -1e30f, l = 0.f, acc0 = 0.f, acc1 = 0.f;
    int beg = g_ints[I_OFF + i], end = g_ints[I_OFF + i + 1];
    for (int j = beg; j <= end; j++) {
        int s = (j < end) ? g_ints[I_ESRC + j] : i;
        const float* xrs = xr + (long)s * CC + w * COH;
        float xr0 = xrs[c0], xr1 = xrs[c1];
        float e0 = xl0 + xr0; e0 = (e0 > 0.f) ? e0 : 0.2f * e0;
        float e1 = xl1 + xr1; e1 = (e1 > 0.f) ? e1 : 0.2f * e1;
        float p = e0 * a0 + e1 * a1;
#pragma unroll
        for (int o = 16; o; o >>= 1) p += __shfl_xor_sync(0xffffffffu, p, o);
        float mn = fmaxf(m, p);
        float sc = __expf(m - mn);
        float wg = __expf(p - mn);
        l = l * sc + wg;
        acc0 = acc0 * sc + xr0 * wg;
        acc1 = acc1 * sc + xr1 * wg;
        m = mn;
    }
    float inv = 1.f / l;
    outp[(long)i * CC + w * COH + c0] = acc0 * inv + gbias[w * COH + c0];
    outp[(long)i * CC + w * COH + c1] = acc1 * inv + gbias[w * COH + c1];
}

// ---------------- residual add + layernorm (+ optional fp16 split out) ----------------
__global__ void k_add_ln(const float* __restrict__ x, const float* __restrict__ h,
                         const float* __restrict__ g, const float* __restrict__ b,
                         float* __restrict__ outp,
                         __half* __restrict__ oh, __half* __restrict__ ol) {
    int row = blockIdx.x;
    int t = threadIdx.x;
    __shared__ float sh[8];
    float v0 = x[(long)row * CC + t]       + h[(long)row * CC + t];
    float v1 = x[(long)row * CC + 256 + t] + h[(long)row * CC + 256 + t];
    float s = v0 + v1;
#pragma unroll
    for (int o = 16; o; o >>= 1) s += __shfl_xor_sync(0xffffffffu, s, o);
    if ((t & 31) == 0) sh[t >> 5] = s;
    __syncthreads();
    float tot = 0.f;
#pragma unroll
    for (int i = 0; i < 8; i++) tot += sh[i];
    float mu = tot * (1.f / 512.f);
    __syncthreads();
    float d0 = v0 - mu, d1 = v1 - mu;
    float q = d0 * d0 + d1 * d1;
#pragma unroll
    for (int o = 16; o; o >>= 1) q += __shfl_xor_sync(0xffffffffu, q, o);
    if ((t & 31) == 0) sh[t >> 5] = q;
    __syncthreads();
    float var = 0.f;
#pragma unroll
    for (int i = 0; i < 8; i++) var += sh[i];
    var *= (1.f / 512.f);
    float rstd = rsqrtf(var + 1e-5f);
    float y0 = d0 * rstd * g[t]       + b[t];
    float y1 = d1 * rstd * g[t + 256] + b[t + 256];
    outp[(long)row * CC + t]       = y0;
    outp[(long)row * CC + 256 + t] = y1;
    if (oh) {
        __half h0 = __float2half_rn(y0);
        __half h1 = __float2half_rn(y1);
        oh[(long)row * CC + t]       = h0;
        oh[(long)row * CC + 256 + t] = h1;
        ol[(long)row * CC + t]       = __float2half_rn(y0 - __half2float(h0));
        ol[(long)row * CC + 256 + t] = __float2half_rn(y1 - __half2float(h1));
    }
}

// ---------------- flash attention, fp16 2-product ----------------
// smem (uint units, row stride 36): Qh 0, Ql 2304, Kh 4608, Vh 6912 (transposed [d][kv])
#define FQH 0
#define FQL 2304
#define FKH 4608
#define FVH 6912
#define FLASH_SMEM (9216 * 4)

__global__ void __launch_bounds__(128) k_flash(const __half* __restrict__ qkvh,
                                               const __half* __restrict__ qkvl,
                                               __half* __restrict__ ath,
                                               __half* __restrict__ atl) {
    extern __shared__ unsigned sm[];
    int h = blockIdx.y;
    int q0 = blockIdx.x * 64;
    int tid = threadIdx.x;
    int lane = tid & 31, wid = tid >> 5;
    int g = lane >> 2, t = lane & 3;
    int mBase = wid * 16;
    const float qs2 = 0.125f * 1.44269504088896f;

    // Q tile copy (hi+lo)
#pragma unroll
    for (int i = 0; i < 4; i++) {
        int cchunk = tid + i * 128;
        int r = cchunk >> 3;
        int q4 = cchunk & 7;
        long goff = (long)(q0 + r) * QKVW + h * COH + q4 * 8;
        *(uint4*)&sm[FQH + r * 36 + q4 * 4] = *(const uint4*)&qkvh[goff];
        *(uint4*)&sm[FQL + r * 36 + q4 * 4] = *(const uint4*)&qkvl[goff];
    }

    float m0 = -1e30f, m1 = -1e30f, l0s = 0.f, l1s = 0.f;
    float o[8][4];
#pragma unroll
    for (int nd = 0; nd < 8; nd++)
#pragma unroll
        for (int j = 0; j < 4; j++) o[nd][j] = 0.f;

    for (int kv0 = 0; kv0 < NN; kv0 += 64) {
        __syncthreads();
        // K tile copy (hi only)
#pragma unroll
        for (int i = 0; i < 4; i++) {
            int cchunk = tid + i * 128;
            int r = cchunk >> 3;
            int q4 = cchunk & 7;
            long goff = (long)(kv0 + r) * QKVW + CC + h * COH + q4 * 8;
            *(uint4*)&sm[FKH + r * 36 + q4 * 4] = *(const uint4*)&qkvh[goff];
        }
        // V tile transposed (hi only): V[d][kv] halfs
        {
            unsigned short* Vhu = (unsigned short*)&sm[FVH];
            int r = tid >> 1;
            int dbase = (tid & 1) * 32;
            long goff = (long)(kv0 + r) * QKVW + 2 * CC + h * COH + dbase;
#pragma unroll
            for (int q4 = 0; q4 < 4; q4++) {
                uint4 vh = *(const uint4*)&qkvh[goff + q4 * 8];
                int d = dbase + q4 * 8;
                const unsigned hw[4] = {vh.x, vh.y, vh.z, vh.w};
#pragma unroll
                for (int e = 0; e < 4; e++) {
                    Vhu[(d + 2*e)     * 72 + r] = (unsigned short)(hw[e] & 0xFFFF);
                    Vhu[(d + 2*e + 1) * 72 + r] = (unsigned short)(hw[e] >> 16);
                }
            }
        }
        __syncthreads();

        // S = Q K^T (2-product), then scale
        float s[8][4];
#pragma unroll
        for (int ni = 0; ni < 8; ni++)
#pragma unroll
            for (int j = 0; j < 4; j++) s[ni][j] = 0.f;

#pragma unroll
        for (int ks = 0; ks < 4; ks++) {
            unsigned ah[4], al[4];
            int r0 = (mBase + g) * 36 + 8 * ks + t;
            int r1 = r0 + 8 * 36;
            ah[0] = sm[FQH + r0];     al[0] = sm[FQL + r0];
            ah[1] = sm[FQH + r1];     al[1] = sm[FQL + r1];
            ah[2] = sm[FQH + r0 + 4]; al[2] = sm[FQL + r0 + 4];
            ah[3] = sm[FQH + r1 + 4]; al[3] = sm[FQL + r1 + 4];
#pragma unroll
            for (int ni = 0; ni < 8; ni++) {
                int rn = (ni * 8 + g) * 36 + 8 * ks + t;
                unsigned bh[2];
                bh[0] = sm[FKH + rn];
                bh[1] = sm[FKH + rn + 4];
                mma16816h(s[ni], al, bh);
                mma16816h(s[ni], ah, bh);
            }
        }
#pragma unroll
        for (int ni = 0; ni < 8; ni++)
#pragma unroll
            for (int j = 0; j < 4; j++) s[ni][j] *= qs2;

        // online softmax (base-2)
        float mx0 = -1e30f, mx1 = -1e30f;
#pragma unroll
        for (int ni = 0; ni < 8; ni++) {
            mx0 = fmaxf(mx0, fmaxf(s[ni][0], s[ni][1]));
            mx1 = fmaxf(mx1, fmaxf(s[ni][2], s[ni][3]));
        }
        mx0 = fmaxf(mx0, __shfl_xor_sync(0xffffffffu, mx0, 1));
        mx0 = fmaxf(mx0, __shfl_xor_sync(0xffffffffu, mx0, 2));
        mx1 = fmaxf(mx1, __shfl_xor_sync(0xffffffffu, mx1, 1));
        mx1 = fmaxf(mx1, __shfl_xor_sync(0xffffffffu, mx1, 2));
        float mn0 = fmaxf(m0, mx0), mn1 = fmaxf(m1, mx1);
        float sc0 = exp2f(m0 - mn0), sc1 = exp2f(m1 - mn1);
        m0 = mn0; m1 = mn1;
        float sum0 = 0.f, sum1 = 0.f;
#pragma unroll
        for (int ni = 0; ni < 8; ni++) {
            s[ni][0] = exp2f(s[ni][0] - m0); sum0 += s[ni][0];
            s[ni][1] = exp2f(s[ni][1] - m0); sum0 += s[ni][1];
            s[ni][2] = exp2f(s[ni][2] - m1); sum1 += s[ni][2];
            s[ni][3] = exp2f(s[ni][3] - m1); sum1 += s[ni][3];
        }
        sum0 += __shfl_xor_sync(0xffffffffu, sum0, 1);
        sum0 += __shfl_xor_sync(0xffffffffu, sum0, 2);
        sum1 += __shfl_xor_sync(0xffffffffu, sum1, 1);
        sum1 += __shfl_xor_sync(0xffffffffu, sum1, 2);
        l0s = l0s * sc0 + sum0;
        l1s = l1s * sc1 + sum1;
#pragma unroll
        for (int nd = 0; nd < 8; nd++) {
            o[nd][0] *= sc0; o[nd][1] *= sc0;
            o[nd][2] *= sc1; o[nd][3] *= sc1;
        }

        // O += P V (P split fp16, V hi only)
#pragma unroll
        for (int ks = 0; ks < 4; ks++) {
            unsigned ph[4], pl[4];
            split2h(s[2*ks][0],   s[2*ks][1],   ph[0], pl[0]);
            split2h(s[2*ks][2],   s[2*ks][3],   ph[1], pl[1]);
            split2h(s[2*ks+1][0], s[2*ks+1][1], ph[2], pl[2]);
            split2h(s[2*ks+1][2], s[2*ks+1][3], ph[3], pl[3]);
#pragma unroll
            for (int nd = 0; nd < 8; nd++) {
                int rn = (nd * 8 + g) * 36 + 8 * ks + t;
                unsigned bh[2];
                bh[0] = sm[FVH + rn];
                bh[1] = sm[FVH + rn + 4];
                mma16816h(o[nd], pl, bh);
                mma16816h(o[nd], ph, bh);
            }
        }
    }

    float inv0 = 1.f / l0s, inv1 = 1.f / l1s;
#pragma unroll
    for (int nd = 0; nd < 8; nd++) {
        int ccol = h * COH + nd * 8 + 2 * t;
        long r0 = q0 + mBase + g;
        unsigned hp, lp;
        split2h(o[nd][0] * inv0, o[nd][1] * inv0, hp, lp);
        *(unsigned*)&ath[r0 * CC + ccol] = hp;
        *(unsigned*)&atl[r0 * CC + ccol] = lp;
        split2h(o[nd][2] * inv1, o[nd][3] * inv1, hp, lp);
        *(unsigned*)&ath[(r0 + 8) * CC + ccol] = hp;
        *(unsigned*)&atl[(r0 + 8) * CC + ccol] = lp;
    }
}

// ---------------- launch ----------------
extern "C" void kernel_launch(void* const* d_in, const int* in_sizes, int n_in,
                              void* d_out, int out_size) {
    const float* x      = (const float*)d_in[0];
    const int*   ei     = (const int*)d_in[1];
    const float* gat_wl = (const float*)d_in[2];
    const float* gat_bl = (const float*)d_in[3];
    const float* gat_wr = (const float*)d_in[4];
    const float* gat_br = (const float*)d_in[5];
    const float* gat_at = (const float*)d_in[6];
    const float* gat_b  = (const float*)d_in[7];
    const float* in_w   = (const float*)d_in[8];
    const float* in_b   = (const float*)d_in[9];
    const float* out_w  = (const float*)d_in[10];
    const float* out_b  = (const float*)d_in[11];
    const float* ln1_g  = (const float*)d_in[12];
    const float* ln1_b  = (const float*)d_in[13];
    const float* ln2_g  = (const float*)d_in[14];
    const float* ln2_b  = (const float*)d_in[15];
    const float* ln3_g  = (const float*)d_in[16];
    const float* ln3_b  = (const float*)d_in[17];
    const float* w1     = (const float*)d_in[18];
    const float* b1     = (const float*)d_in[19];
    const float* w2     = (const float*)d_in[20];
    const float* b2     = (const float*)d_in[21];
    float* outp = (float*)d_out;

    float* gs = nullptr;
    cudaGetSymbolAddress((void**)&gs, g_scratch);
    __half* gh = nullptr;
    cudaGetSymbolAddress((void**)&gh, g_hf);

    cudaFuncSetAttribute(k_flash, cudaFuncAttributeMaxDynamicSharedMemorySize, FLASH_SMEM);

    __half *Xh = gh + ZX,    *Xl = Xh + (long)NN*CC;
    __half *X1h = gh + ZX1,  *X1l = X1h + (long)NN*CC;
    __half *Ath = gh + ZATT, *Atl = Ath + (long)NN*CC;
    __half *X2h = gh + ZX2,  *X2l = X2h + (long)NN*CC;
    __half *Qh = gh + ZQKV,  *Ql = Qh + (long)NN*3*CC;
    __half *Fh = gh + ZFFN,  *Fl = Fh + (long)NN*4*CC;
    __half *WLh = gh + ZWL;
    __half *WRh = gh + ZWR;
    __half *INh = gh + ZIN;
    __half *OWh = gh + ZOW;
    __half *W1h = gh + ZW1;
    __half *W2h = gh + ZW2;

    // CSR build
    k_zero_deg<<<16, 256>>>();
    k_count<<<EE / 256, 256>>>(ei);
    k_scan<<<1, 1024>>>();
    k_scatter<<<EE / 256, 256>>>(ei);

    // pre-split x (hi+lo) + convert weights (hi only)
    k_split<<<(NN*CC/4 + 255)/256, 256>>>(x, Xh, Xl, NN*CC/4);
    k_half<<<(CC*CC/4 + 255)/256, 256>>>(gat_wl, WLh, CC*CC/4);
    k_half<<<(CC*CC/4 + 255)/256, 256>>>(gat_wr, WRh, CC*CC/4);
    k_half<<<(3*CC*CC/4 + 255)/256, 256>>>(in_w, INh, 3*CC*CC/4);
    k_half<<<(CC*CC/4 + 255)/256, 256>>>(out_w, OWh, CC*CC/4);
    k_half<<<(4*CC*CC/4 + 255)/256, 256>>>(w1, W1h, 4*CC*CC/4);
    k_half<<<(4*CC*CC/4 + 255)/256, 256>>>(w2, W2h, 4*CC*CC/4);

    // GAT projections (fp32 out)
    dim3 g512(CC / 64, NN / 128);
    k_gemm<0><<<g512, 256>>>(Xh, Xl, WLh, gat_bl, gs + S_XL, 0, 0, CC, CC);
    k_gemm<0><<<g512, 256>>>(Xh, Xl, WRh, gat_br, gs + S_XR, 0, 0, CC, CC);

    // GAT aggregation
    k_gat<<<NN, 256>>>(gs + S_XL, gs + S_XR, gat_at, gat_b, gs + S_HB);

    // x1 = LN(x + h_local), + split
    k_add_ln<<<NN, 256>>>(x, gs + S_HB, ln1_g, ln1_b, gs + S_X1, X1h, X1l);

    // QKV (split fp16 out)
    dim3 gqkv(QKVW / 64, NN / 128);
    k_gemm<2><<<gqkv, 256>>>(X1h, X1l, INh, in_b, 0, Qh, Ql, QKVW, CC);

    // flash attention (split in, split out)
    dim3 gfl(NN / 64, HH);
    k_flash<<<gfl, 128, FLASH_SMEM>>>(Qh, Ql, Ath, Atl);

    // out proj (fp32 out)
    k_gemm<0><<<g512, 256>>>(Ath, Atl, OWh, out_b, gs + S_HB, 0, 0, CC, CC);

    // x2 = LN(x1 + h_global), + split
    k_add_ln<<<NN, 256>>>(gs + S_X1, gs + S_HB, ln2_g, ln2_b, gs + S_X2, X2h, X2l);

    // FFN1 (GELU, split fp16 out)
    dim3 gffn1(4 * CC / 64, NN / 128);
    k_gemm<1><<<gffn1, 256>>>(X2h, X2l, W1h, b1, 0, Fh, Fl, 4 * CC, CC);
    // FFN2 (fp32 out)
    k_gemm<0><<<g512, 256>>>(Fh, Fl, W2h, b2, gs + S_HB, 0, 0, CC, 4 * CC);

    // out = LN(x2 + ffn)
    k_add_ln<<<NN, 256>>>(gs + S_X2, gs + S_HB, ln3_g, ln3_b, outp, 0, 0);
}

// round 10
// speedup vs baseline: 1.5271x; 1.1853x over previous
#include <cuda_runtime.h>
#include <cuda_fp16.h>
#include <stdint.h>
#include <math.h>

#define NN    4096
#define CC    512
#define HH    8
#define COH   64
#define EE    131072
#define QKVW  1536

// ---------------- fp32 scratch ----------------
#define S_XL   0L
#define S_XR   (S_XL  + (long)NN*CC)
#define S_HB   (S_XR  + (long)NN*CC)
#define S_X1   (S_HB  + (long)NN*CC)
#define S_X2   (S_X1  + (long)NN*CC)
#define S_TOT  (S_X2  + (long)NN*CC)
__device__ float g_scratch[S_TOT];

// ---------------- fp16 scratch: activations hi+lo, weights hi only ----------------
#define ZX    0L
#define ZX1   (ZX   + 2L*NN*CC)
#define ZATT  (ZX1  + 2L*NN*CC)
#define ZX2   (ZATT + 2L*NN*CC)
#define ZQKV  (ZX2  + 2L*NN*CC)
#define ZFFN  (ZQKV + 2L*NN*3*CC)
#define ZWL   (ZFFN + 2L*NN*4*CC)
#define ZWR   (ZWL  + 1L*CC*CC)
#define ZIN   (ZWR  + 1L*CC*CC)
#define ZOW   (ZIN  + 3L*CC*CC)
#define ZW1   (ZOW  + 1L*CC*CC)
#define ZW2   (ZW1  + 4L*CC*CC)
#define ZTOT  (ZW2  + 4L*CC*CC)
__device__ __half g_hf[ZTOT];

// int scratch
#define I_DEG  0
#define I_OFF  4096
#define I_POS  (I_OFF + 4097)
#define I_ESRC (I_POS + 4096)
__device__ int g_ints[I_ESRC + EE];

// ---------------- helpers ----------------
__device__ __forceinline__ void split2h(float x0, float x1, unsigned &hi, unsigned &lo) {
    __half h0 = __float2half_rn(x0);
    __half h1 = __float2half_rn(x1);
    float r0 = x0 - __half2float(h0);
    float r1 = x1 - __half2float(h1);
    __half l0 = __float2half_rn(r0);
    __half l1 = __float2half_rn(r1);
    hi = ((unsigned)__half_as_ushort(h1) << 16) | (unsigned)__half_as_ushort(h0);
    lo = ((unsigned)__half_as_ushort(l1) << 16) | (unsigned)__half_as_ushort(l0);
}

__device__ __forceinline__ unsigned pack2h(float x0, float x1) {
    return ((unsigned)__half_as_ushort(__float2half_rn(x1)) << 16) |
           (unsigned)__half_as_ushort(__float2half_rn(x0));
}

__device__ __forceinline__ void mma16816h(float* c, const unsigned* a, const unsigned* b) {
    asm volatile(
        "mma.sync.aligned.m16n8k16.row.col.f32.f16.f16.f32 "
        "{%0,%1,%2,%3}, {%4,%5,%6,%7}, {%8,%9}, {%0,%1,%2,%3};\n"
        : "+f"(c[0]), "+f"(c[1]), "+f"(c[2]), "+f"(c[3])
        : "r"(a[0]), "r"(a[1]), "r"(a[2]), "r"(a[3]), "r"(b[0]), "r"(b[1]));
}

__device__ __forceinline__ void ldsm4(unsigned &r0, unsigned &r1, unsigned &r2, unsigned &r3,
                                      uint32_t addr) {
    asm volatile("ldmatrix.sync.aligned.m8n8.x4.shared.b16 {%0,%1,%2,%3}, [%4];"
                 : "=r"(r0), "=r"(r1), "=r"(r2), "=r"(r3) : "r"(addr));
}

__device__ __forceinline__ uint32_t smem_u32(const void* p) {
    uint32_t a;
    asm("{ .reg .u64 t; cvta.to.shared.u64 t, %1; cvt.u32.u64 %0, t; }" : "=r"(a) : "l"(p));
    return a;
}

__device__ __forceinline__ float geluf(float v) {
    return 0.5f * v * (1.f + erff(v * 0.70710678118654752f));
}

// ---------------- CSR build (edge_index int32 [2,E]) ----------------
__global__ void k_zero_deg() {
    int i = blockIdx.x * blockDim.x + threadIdx.x;
    if (i < NN) g_ints[I_DEG + i] = 0;
}
__global__ void k_count(const int* __restrict__ ei) {
    int e = blockIdx.x * blockDim.x + threadIdx.x;
    if (e < EE) atomicAdd(&g_ints[I_DEG + (ei[EE + e] & (NN - 1))], 1);
}
__global__ void k_scan() {
    __shared__ int ws[32];
    int t = threadIdx.x;
    int v[4]; int tot = 0;
#pragma unroll
    for (int j = 0; j < 4; j++) { v[j] = g_ints[I_DEG + t*4 + j]; tot += v[j]; }
    int lane = t & 31, wid = t >> 5;
    int sc = tot;
#pragma unroll
    for (int o = 1; o < 32; o <<= 1) {
        int y = __shfl_up_sync(0xffffffffu, sc, o);
        if (lane >= o) sc += y;
    }
    if (lane == 31) ws[wid] = sc;
    __syncthreads();
    if (wid == 0) {
        int z = ws[lane];
#pragma unroll
        for (int o = 1; o < 32; o <<= 1) {
            int y = __shfl_up_sync(0xffffffffu, z, o);
            if (lane >= o) z += y;
        }
        ws[lane] = z;
    }
    __syncthreads();
    int excl = sc - tot + (wid ? ws[wid - 1] : 0);
    int run = excl;
#pragma unroll
    for (int j = 0; j < 4; j++) {
        g_ints[I_OFF + t*4 + j] = run;
        g_ints[I_POS + t*4 + j] = run;
        run += v[j];
    }
    if (t == 1023) g_ints[I_OFF + 4096] = run;
}
__global__ void k_scatter(const int* __restrict__ ei) {
    int e = blockIdx.x * blockDim.x + threadIdx.x;
    if (e < EE) {
        int d = ei[EE + e] & (NN - 1);
        int s = ei[e] & (NN - 1);
        int p = atomicAdd(&g_ints[I_POS + d], 1);
        if (p >= 0 && p < EE) g_ints[I_ESRC + p] = s;
    }
}

// ---------------- fp32 -> fp16 hi/lo split (activations) ----------------
__global__ void k_split(const float* __restrict__ in, __half* __restrict__ hi,
                        __half* __restrict__ lo, int n4) {
    int i = blockIdx.x * blockDim.x + threadIdx.x;
    if (i >= n4) return;
    float4 v = ((const float4*)in)[i];
    unsigned h0, l0, h1, l1;
    split2h(v.x, v.y, h0, l0); split2h(v.z, v.w, h1, l1);
    ((uint2*)hi)[i] = make_uint2(h0, h1);
    ((uint2*)lo)[i] = make_uint2(l0, l1);
}

// ---------------- fp32 -> fp16 convert (weights, hi only) ----------------
__global__ void k_half(const float* __restrict__ in, __half* __restrict__ hi, int n4) {
    int i = blockIdx.x * blockDim.x + threadIdx.x;
    if (i >= n4) return;
    float4 v = ((const float4*)in)[i];
    ((uint2*)hi)[i] = make_uint2(pack2h(v.x, v.y), pack2h(v.z, v.w));
}

// ---------------- mma.sync NT GEMM, fp16 2-product, LDSM fragments ----------------
// C[M,Nd] = A[M,K] @ B[Nd,K]^T + bias;  BM=128 BN=64 BK=32, 256 thr, 8 warps (4Mx2N).
template <int EPI>
__global__ void __launch_bounds__(256) k_gemm(
    const __half* __restrict__ Ah, const __half* __restrict__ Al,
    const __half* __restrict__ Bh,
    const float* __restrict__ bias, float* __restrict__ Cf,
    __half* __restrict__ Ch, __half* __restrict__ Cl,
    int Nd, int K) {
    __shared__ unsigned Ahs[128 * 20], Als[128 * 20];
    __shared__ unsigned Bhs[64 * 20];

    int tid = threadIdx.x;
    int lane = tid & 31, wid = tid >> 5;
    int wm = wid & 3, wn = wid >> 2;
    int mBase = wm * 32, nBase = wn * 32;
    int g = lane >> 2, t = lane & 3;
    int bm = blockIdx.y * 128, bn = blockIdx.x * 64;

    // LDSM per-thread fragment base addresses (bytes); row strides: 80 B
    uint32_t ahB = smem_u32(Ahs), alB = smem_u32(Als), bhB = smem_u32(Bhs);
    uint32_t aFh = ahB + (mBase + (lane & 15)) * 80 + (lane >> 4) * 16;
    uint32_t aFl = alB + (mBase + (lane & 15)) * 80 + (lane >> 4) * 16;
    uint32_t bF  = bhB + (nBase + 8 * (lane >> 4) + (lane & 7)) * 80 + ((lane >> 3) & 1) * 16;

    float c[2][4][4];
#pragma unroll
    for (int mi = 0; mi < 2; mi++)
#pragma unroll
        for (int ni = 0; ni < 4; ni++)
#pragma unroll
            for (int j = 0; j < 4; j++) c[mi][ni][j] = 0.f;

    int lrow = tid >> 1;
    int lhalf = (tid & 1) * 16;
    int soff0 = lrow * 20 + (tid & 1) * 8;

    for (int k0 = 0; k0 < K; k0 += 32) {
        {   // A tile 128x32 fp16 (hi+lo)
            long goff = (long)(bm + lrow) * K + k0 + lhalf;
            const uint4* ph = (const uint4*)&Ah[goff];
            const uint4* pl = (const uint4*)&Al[goff];
            uint4 h0 = ph[0], h1 = ph[1], l0 = pl[0], l1 = pl[1];
            *(uint4*)&Ahs[soff0] = h0; *(uint4*)&Ahs[soff0 + 4] = h1;
            *(uint4*)&Als[soff0] = l0; *(uint4*)&Als[soff0 + 4] = l1;
        }
        if (tid < 128) {   // B tile 64x32 fp16 (hi only)
            long goff = (long)(bn + lrow) * K + k0 + lhalf;
            const uint4* ph = (const uint4*)&Bh[goff];
            uint4 h0 = ph[0], h1 = ph[1];
            *(uint4*)&Bhs[soff0] = h0; *(uint4*)&Bhs[soff0 + 4] = h1;
        }
        __syncthreads();

#pragma unroll
        for (int ks = 0; ks < 2; ks++) {
            unsigned ah[2][4], al[2][4], bh[4][2];
#pragma unroll
            for (int mi = 0; mi < 2; mi++) {
                ldsm4(ah[mi][0], ah[mi][1], ah[mi][2], ah[mi][3], aFh + mi * 1280 + ks * 32);
                ldsm4(al[mi][0], al[mi][1], al[mi][2], al[mi][3], aFl + mi * 1280 + ks * 32);
            }
#pragma unroll
            for (int p = 0; p < 2; p++) {
                ldsm4(bh[2*p][0], bh[2*p][1], bh[2*p+1][0], bh[2*p+1][1], bF + p * 1280 + ks * 32);
            }
#pragma unroll
            for (int mi = 0; mi < 2; mi++)
#pragma unroll
                for (int ni = 0; ni < 4; ni++) {
                    mma16816h(c[mi][ni], al[mi], bh[ni]);
                    mma16816h(c[mi][ni], ah[mi], bh[ni]);
                }
        }
        __syncthreads();
    }

    // epilogue
#pragma unroll
    for (int mi = 0; mi < 2; mi++)
#pragma unroll
        for (int ni = 0; ni < 4; ni++) {
            int n0 = bn + nBase + ni * 8 + 2 * t;
            long r0 = bm + mBase + mi * 16 + g;
            float v0 = c[mi][ni][0] + bias[n0];
            float v1 = c[mi][ni][1] + bias[n0 + 1];
            float v2 = c[mi][ni][2] + bias[n0];
            float v3 = c[mi][ni][3] + bias[n0 + 1];
            if (EPI == 0) {
                Cf[r0 * Nd + n0]           = v0;
                Cf[r0 * Nd + n0 + 1]       = v1;
                Cf[(r0 + 8) * Nd + n0]     = v2;
                Cf[(r0 + 8) * Nd + n0 + 1] = v3;
            } else {
                if (EPI == 1) { v0 = geluf(v0); v1 = geluf(v1); v2 = geluf(v2); v3 = geluf(v3); }
                unsigned hp, lp;
                split2h(v0, v1, hp, lp);
                *(unsigned*)&Ch[r0 * Nd + n0] = hp;
                *(unsigned*)&Cl[r0 * Nd + n0] = lp;
                split2h(v2, v3, hp, lp);
                *(unsigned*)&Ch[(r0 + 8) * Nd + n0] = hp;
                *(unsigned*)&Cl[(r0 + 8) * Nd + n0] = lp;
            }
        }
}

// ---------------- GAT per-node online softmax aggregation ----------------
__global__ void k_gat(const float* __restrict__ xl, const float* __restrict__ xr,
                      const float* __restrict__ att, const float* __restrict__ gbias,
                      float* __restrict__ outp) {
    int i = blockIdx.x;
    int w = threadIdx.x >> 5;
    int lane = threadIdx.x & 31;
    int c0 = lane, c1 = lane + 32;
    const float* xli = xl + (long)i * CC + w * COH;
    float xl0 = xli[c0], xl1 = xli[c1];
    float a0 = att[w * COH + c0], a1 = att[w * COH + c1];
    float m = -1e30f, l = 0.f, acc0 = 0.f, acc1 = 0.f;
    int beg = g_ints[I_OFF + i], end = g_ints[I_OFF + i + 1];
    for (int j = beg; j <= end; j++) {
        int s = (j < end) ? g_ints[I_ESRC + j] : i;
        const float* xrs = xr + (long)s * CC + w * COH;
        float xr0 = xrs[c0], xr1 = xrs[c1];
        float e0 = xl0 + xr0; e0 = (e0 > 0.f) ? e0 : 0.2f * e0;
        float e1 = xl1 + xr1; e1 = (e1 > 0.f) ? e1 : 0.2f * e1;
        float p = e0 * a0 + e1 * a1;
#pragma unroll
        for (int o = 16; o; o >>= 1) p += __shfl_xor_sync(0xffffffffu, p, o);
        float mn = fmaxf(m, p);
        float sc = __expf(m - mn);
        float wg = __expf(p - mn);
        l = l * sc + wg;
        acc0 = acc0 * sc + xr0 * wg;
        acc1 = acc1 * sc + xr1 * wg;
        m = mn;
    }
    float inv = 1.f / l;
    outp[(long)i * CC + w * COH + c0] = acc0 * inv + gbias[w * COH + c0];
    outp[(long)i * CC + w * COH + c1] = acc1 * inv + gbias[w * COH + c1];
}

// ---------------- residual add + layernorm (+ optional fp16 split out) ----------------
__global__ void k_add_ln(const float* __restrict__ x, const float* __restrict__ h,
                         const float* __restrict__ g, const float* __restrict__ b,
                         float* __restrict__ outp,
                         __half* __restrict__ oh, __half* __restrict__ ol) {
    int row = blockIdx.x;
    int t = threadIdx.x;
    __shared__ float sh[8];
    float v0 = x[(long)row * CC + t]       + h[(long)row * CC + t];
    float v1 = x[(long)row * CC + 256 + t] + h[(long)row * CC + 256 + t];
    float s = v0 + v1;
#pragma unroll
    for (int o = 16; o; o >>= 1) s += __shfl_xor_sync(0xffffffffu, s, o);
    if ((t & 31) == 0) sh[t >> 5] = s;
    __syncthreads();
    float tot = 0.f;
#pragma unroll
    for (int i = 0; i < 8; i++) tot += sh[i];
    float mu = tot * (1.f / 512.f);
    __syncthreads();
    float d0 = v0 - mu, d1 = v1 - mu;
    float q = d0 * d0 + d1 * d1;
#pragma unroll
    for (int o = 16; o; o >>= 1) q += __shfl_xor_sync(0xffffffffu, q, o);
    if ((t & 31) == 0) sh[t >> 5] = q;
    __syncthreads();
    float var = 0.f;
#pragma unroll
    for (int i = 0; i < 8; i++) var += sh[i];
    var *= (1.f / 512.f);
    float rstd = rsqrtf(var + 1e-5f);
    float y0 = d0 * rstd * g[t]       + b[t];
    float y1 = d1 * rstd * g[t + 256] + b[t + 256];
    outp[(long)row * CC + t]       = y0;
    outp[(long)row * CC + 256 + t] = y1;
    if (oh) {
        __half h0 = __float2half_rn(y0);
        __half h1 = __float2half_rn(y1);
        oh[(long)row * CC + t]       = h0;
        oh[(long)row * CC + 256 + t] = h1;
        ol[(long)row * CC + t]       = __float2half_rn(y0 - __half2float(h0));
        ol[(long)row * CC + 256 + t] = __float2half_rn(y1 - __half2float(h1));
    }
}

// ---------------- flash attention, fp16, LDSM fragments, P hi-only PV ----------------
// smem (uint units, row stride 36): Qh 0, Ql 2304, Kh 4608, Vh 6912 (transposed [d][kv])
#define FQH 0
#define FQL 2304
#define FKH 4608
#define FVH 6912
#define FLASH_SMEM (9216 * 4)

__global__ void __launch_bounds__(128) k_flash(const __half* __restrict__ qkvh,
                                               const __half* __restrict__ qkvl,
                                               __half* __restrict__ ath,
                                               __half* __restrict__ atl) {
    extern __shared__ unsigned sm[];
    int h = blockIdx.y;
    int q0 = blockIdx.x * 64;
    int tid = threadIdx.x;
    int lane = tid & 31, wid = tid >> 5;
    int g = lane >> 2, t = lane & 3;
    int mBase = wid * 16;
    const float qs2 = 0.125f * 1.44269504088896f;

    uint32_t smB = smem_u32(sm);
    // fragment base addresses (row stride 144 B)
    uint32_t qFh = smB + FQH * 4 + (mBase + (lane & 15)) * 144 + (lane >> 4) * 16;
    uint32_t qFl = smB + FQL * 4 + (mBase + (lane & 15)) * 144 + (lane >> 4) * 16;
    uint32_t kF  = smB + FKH * 4 + (8 * (lane >> 4) + (lane & 7)) * 144 + ((lane >> 3) & 1) * 16;
    uint32_t vF  = smB + FVH * 4 + (8 * (lane >> 4) + (lane & 7)) * 144 + ((lane >> 3) & 1) * 16;

    // Q tile copy (hi+lo)
#pragma unroll
    for (int i = 0; i < 4; i++) {
        int cchunk = tid + i * 128;
        int r = cchunk >> 3;
        int q4 = cchunk & 7;
        long goff = (long)(q0 + r) * QKVW + h * COH + q4 * 8;
        *(uint4*)&sm[FQH + r * 36 + q4 * 4] = *(const uint4*)&qkvh[goff];
        *(uint4*)&sm[FQL + r * 36 + q4 * 4] = *(const uint4*)&qkvl[goff];
    }

    float m0 = -1e30f, m1 = -1e30f, l0s = 0.f, l1s = 0.f;
    float o[8][4];
#pragma unroll
    for (int nd = 0; nd < 8; nd++)
#pragma unroll
        for (int j = 0; j < 4; j++) o[nd][j] = 0.f;

    for (int kv0 = 0; kv0 < NN; kv0 += 64) {
        __syncthreads();
        // K tile copy (hi only)
#pragma unroll
        for (int i = 0; i < 4; i++) {
            int cchunk = tid + i * 128;
            int r = cchunk >> 3;
            int q4 = cchunk & 7;
            long goff = (long)(kv0 + r) * QKVW + CC + h * COH + q4 * 8;
            *(uint4*)&sm[FKH + r * 36 + q4 * 4] = *(const uint4*)&qkvh[goff];
        }
        // V tile transposed (hi only): V[d][kv]
        {
            unsigned short* Vhu = (unsigned short*)&sm[FVH];
            int r = tid >> 1;
            int dbase = (tid & 1) * 32;
            long goff = (long)(kv0 + r) * QKVW + 2 * CC + h * COH + dbase;
#pragma unroll
            for (int q4 = 0; q4 < 4; q4++) {
                uint4 vh = *(const uint4*)&qkvh[goff + q4 * 8];
                int d = dbase + q4 * 8;
                const unsigned hw[4] = {vh.x, vh.y, vh.z, vh.w};
#pragma unroll
                for (int e = 0; e < 4; e++) {
                    Vhu[(d + 2*e)     * 72 + r] = (unsigned short)(hw[e] & 0xFFFF);
                    Vhu[(d + 2*e + 1) * 72 + r] = (unsigned short)(hw[e] >> 16);
                }
            }
        }
        __syncthreads();

        // S = Q K^T (2-product, LDSM), then scale
        float s[8][4];
#pragma unroll
        for (int ni = 0; ni < 8; ni++)
#pragma unroll
            for (int j = 0; j < 4; j++) s[ni][j] = 0.f;

#pragma unroll
        for (int ks = 0; ks < 4; ks++) {
            unsigned ah[4], al[4];
            ldsm4(ah[0], ah[1], ah[2], ah[3], qFh + ks * 32);
            ldsm4(al[0], al[1], al[2], al[3], qFl + ks * 32);
#pragma unroll
            for (int p = 0; p < 4; p++) {
                unsigned bh[2][2];
                ldsm4(bh[0][0], bh[0][1], bh[1][0], bh[1][1], kF + p * 2304 + ks * 32);
                mma16816h(s[2*p],     al, bh[0]);
                mma16816h(s[2*p],     ah, bh[0]);
                mma16816h(s[2*p + 1], al, bh[1]);
                mma16816h(s[2*p + 1], ah, bh[1]);
            }
        }
#pragma unroll
        for (int ni = 0; ni < 8; ni++)
#pragma unroll
            for (int j = 0; j < 4; j++) s[ni][j] *= qs2;

        // online softmax (base-2)
        float mx0 = -1e30f, mx1 = -1e30f;
#pragma unroll
        for (int ni = 0; ni < 8; ni++) {
            mx0 = fmaxf(mx0, fmaxf(s[ni][0], s[ni][1]));
            mx1 = fmaxf(mx1, fmaxf(s[ni][2], s[ni][3]));
        }
        mx0 = fmaxf(mx0, __shfl_xor_sync(0xffffffffu, mx0, 1));
        mx0 = fmaxf(mx0, __shfl_xor_sync(0xffffffffu, mx0, 2));
        mx1 = fmaxf(mx1, __shfl_xor_sync(0xffffffffu, mx1, 1));
        mx1 = fmaxf(mx1, __shfl_xor_sync(0xffffffffu, mx1, 2));
        float mn0 = fmaxf(m0, mx0), mn1 = fmaxf(m1, mx1);
        float sc0 = exp2f(m0 - mn0), sc1 = exp2f(m1 - mn1);
        m0 = mn0; m1 = mn1;
        float sum0 = 0.f, sum1 = 0.f;
#pragma unroll
        for (int ni = 0; ni < 8; ni++) {
            s[ni][0] = exp2f(s[ni][0] - m0); sum0 += s[ni][0];
            s[ni][1] = exp2f(s[ni][1] - m0); sum0 += s[ni][1];
            s[ni][2] = exp2f(s[ni][2] - m1); sum1 += s[ni][2];
            s[ni][3] = exp2f(s[ni][3] - m1); sum1 += s[ni][3];
        }
        sum0 += __shfl_xor_sync(0xffffffffu, sum0, 1);
        sum0 += __shfl_xor_sync(0xffffffffu, sum0, 2);
        sum1 += __shfl_xor_sync(0xffffffffu, sum1, 1);
        sum1 += __shfl_xor_sync(0xffffffffu, sum1, 2);
        l0s = l0s * sc0 + sum0;
        l1s = l1s * sc1 + sum1;
#pragma unroll
        for (int nd = 0; nd < 8; nd++) {
            o[nd][0] *= sc0; o[nd][1] *= sc0;
            o[nd][2] *= sc1; o[nd][3] *= sc1;
        }

        // O += P V (P hi-only fp16, V hi-only; LDSM V)
#pragma unroll
        for (int ks = 0; ks < 4; ks++) {
            unsigned ph[4];
            ph[0] = pack2h(s[2*ks][0],   s[2*ks][1]);
            ph[1] = pack2h(s[2*ks][2],   s[2*ks][3]);
            ph[2] = pack2h(s[2*ks+1][0], s[2*ks+1][1]);
            ph[3] = pack2h(s[2*ks+1][2], s[2*ks+1][3]);
#pragma unroll
            for (int p = 0; p < 4; p++) {
                unsigned bh[2][2];
                ldsm4(bh[0][0], bh[0][1], bh[1][0], bh[1][1], vF + p * 2304 + ks * 32);
                mma16816h(o[2*p],     ph, bh[0]);
                mma16816h(o[2*p + 1], ph, bh[1]);
            }
        }
    }

    float inv0 = 1.f / l0s, inv1 = 1.f / l1s;
#pragma unroll
    for (int nd = 0; nd < 8; nd++) {
        int ccol = h * COH + nd * 8 + 2 * t;
        long r0 = q0 + mBase + g;
        unsigned hp, lp;
        split2h(o[nd][0] * inv0, o[nd][1] * inv0, hp, lp);
        *(unsigned*)&ath[r0 * CC + ccol] = hp;
        *(unsigned*)&atl[r0 * CC + ccol] = lp;
        split2h(o[nd][2] * inv1, o[nd][3] * inv1, hp, lp);
        *(unsigned*)&ath[(r0 + 8) * CC + ccol] = hp;
        *(unsigned*)&atl[(r0 + 8) * CC + ccol] = lp;
    }
}

// ---------------- launch ----------------
extern "C" void kernel_launch(void* const* d_in, const int* in_sizes, int n_in,
                              void* d_out, int out_size) {
    const float* x      = (const float*)d_in[0];
    const int*   ei     = (const int*)d_in[1];
    const float* gat_wl = (const float*)d_in[2];
    const float* gat_bl = (const float*)d_in[3];
    const float* gat_wr = (const float*)d_in[4];
    const float* gat_br = (const float*)d_in[5];
    const float* gat_at = (const float*)d_in[6];
    const float* gat_b  = (const float*)d_in[7];
    const float* in_w   = (const float*)d_in[8];
    const float* in_b   = (const float*)d_in[9];
    const float* out_w  = (const float*)d_in[10];
    const float* out_b  = (const float*)d_in[11];
    const float* ln1_g  = (const float*)d_in[12];
    const float* ln1_b  = (const float*)d_in[13];
    const float* ln2_g  = (const float*)d_in[14];
    const float* ln2_b  = (const float*)d_in[15];
    const float* ln3_g  = (const float*)d_in[16];
    const float* ln3_b  = (const float*)d_in[17];
    const float* w1     = (const float*)d_in[18];
    const float* b1     = (const float*)d_in[19];
    const float* w2     = (const float*)d_in[20];
    const float* b2     = (const float*)d_in[21];
    float* outp = (float*)d_out;

    float* gs = nullptr;
    cudaGetSymbolAddress((void**)&gs, g_scratch);
    __half* gh = nullptr;
    cudaGetSymbolAddress((void**)&gh, g_hf);

    cudaFuncSetAttribute(k_flash, cudaFuncAttributeMaxDynamicSharedMemorySize, FLASH_SMEM);

    __half *Xh = gh + ZX,    *Xl = Xh + (long)NN*CC;
    __half *X1h = gh + ZX1,  *X1l = X1h + (long)NN*CC;
    __half *Ath = gh + ZATT, *Atl = Ath + (long)NN*CC;
    __half *X2h = gh + ZX2,  *X2l = X2h + (long)NN*CC;
    __half *Qh = gh + ZQKV,  *Ql = Qh + (long)NN*3*CC;
    __half *Fh = gh + ZFFN,  *Fl = Fh + (long)NN*4*CC;
    __half *WLh = gh + ZWL;
    __half *WRh = gh + ZWR;
    __half *INh = gh + ZIN;
    __half *OWh = gh + ZOW;
    __half *W1h = gh + ZW1;
    __half *W2h = gh + ZW2;

    // CSR build
    k_zero_deg<<<16, 256>>>();
    k_count<<<EE / 256, 256>>>(ei);
    k_scan<<<1, 1024>>>();
    k_scatter<<<EE / 256, 256>>>(ei);

    // pre-split x (hi+lo) + convert weights (hi only)
    k_split<<<(NN*CC/4 + 255)/256, 256>>>(x, Xh, Xl, NN*CC/4);
    k_half<<<(CC*CC/4 + 255)/256, 256>>>(gat_wl, WLh, CC*CC/4);
    k_half<<<(CC*CC/4 + 255)/256, 256>>>(gat_wr, WRh, CC*CC/4);
    k_half<<<(3*CC*CC/4 + 255)/256, 256>>>(in_w, INh, 3*CC*CC/4);
    k_half<<<(CC*CC/4 + 255)/256, 256>>>(out_w, OWh, CC*CC/4);
    k_half<<<(4*CC*CC/4 + 255)/256, 256>>>(w1, W1h, 4*CC*CC/4);
    k_half<<<(4*CC*CC/4 + 255)/256, 256>>>(w2, W2h, 4*CC*CC/4);

    // GAT projections (fp32 out)
    dim3 g512(CC / 64, NN / 128);
    k_gemm<0><<<g512, 256>>>(Xh, Xl, WLh, gat_bl, gs + S_XL, 0, 0, CC, CC);
    k_gemm<0><<<g512, 256>>>(Xh, Xl, WRh, gat_br, gs + S_XR, 0, 0, CC, CC);

    // GAT aggregation
    k_gat<<<NN, 256>>>(gs + S_XL, gs + S_XR, gat_at, gat_b, gs + S_HB);

    // x1 = LN(x + h_local), + split
    k_add_ln<<<NN, 256>>>(x, gs + S_HB, ln1_g, ln1_b, gs + S_X1, X1h, X1l);

    // QKV (split fp16 out)
    dim3 gqkv(QKVW / 64, NN / 128);
    k_gemm<2><<<gqkv, 256>>>(X1h, X1l, INh, in_b, 0, Qh, Ql, QKVW, CC);

    // flash attention (split in, split out)
    dim3 gfl(NN / 64, HH);
    k_flash<<<gfl, 128, FLASH_SMEM>>>(Qh, Ql, Ath, Atl);

    // out proj (fp32 out)
    k_gemm<0><<<g512, 256>>>(Ath, Atl, OWh, out_b, gs + S_HB, 0, 0, CC, CC);

    // x2 = LN(x1 + h_global), + split
    k_add_ln<<<NN, 256>>>(gs + S_X1, gs + S_HB, ln2_g, ln2_b, gs + S_X2, X2h, X2l);

    // FFN1 (GELU, split fp16 out)
    dim3 gffn1(4 * CC / 64, NN / 128);
    k_gemm<1><<<gffn1, 256>>>(X2h, X2l, W1h, b1, 0, Fh, Fl, 4 * CC, CC);
    // FFN2 (fp32 out)
    k_gemm<0><<<g512, 256>>>(Fh, Fl, W2h, b2, gs + S_HB, 0, 0, CC, 4 * CC);

    // out = LN(x2 + ffn)
    k_add_ln<<<NN, 256>>>(gs + S_X2, gs + S_HB, ln3_g, ln3_b, outp, 0, 0);
}

// round 11
// speedup vs baseline: 1.9014x; 1.2452x over previous
#include <cuda_runtime.h>
#include <cuda_fp16.h>
#include <stdint.h>
#include <math.h>

#define NN    4096
#define CC    512
#define HH    8
#define COH   64
#define EE    131072
#define QKVW  1536

// ---------------- fp32 scratch ----------------
#define S_XL   0L
#define S_XR   (S_XL  + (long)NN*CC)
#define S_HB   (S_XR  + (long)NN*CC)
#define S_X1   (S_HB  + (long)NN*CC)
#define S_X2   (S_X1  + (long)NN*CC)
#define S_TOT  (S_X2  + (long)NN*CC)
__device__ float g_scratch[S_TOT];

// ---------------- fp16 scratch: activations hi+lo, weights hi only ----------------
#define ZX    0L
#define ZX1   (ZX   + 2L*NN*CC)
#define ZATT  (ZX1  + 2L*NN*CC)
#define ZX2   (ZATT + 2L*NN*CC)
#define ZQKV  (ZX2  + 2L*NN*CC)
#define ZFFN  (ZQKV + 2L*NN*3*CC)
#define ZWL   (ZFFN + 2L*NN*4*CC)
#define ZWR   (ZWL  + 1L*CC*CC)
#define ZIN   (ZWR  + 1L*CC*CC)
#define ZOW   (ZIN  + 3L*CC*CC)
#define ZW1   (ZOW  + 1L*CC*CC)
#define ZW2   (ZW1  + 4L*CC*CC)
#define ZTOT  (ZW2  + 4L*CC*CC)
__device__ __half g_hf[ZTOT];

// int scratch
#define I_DEG  0
#define I_OFF  4096
#define I_POS  (I_OFF + 4097)
#define I_ESRC (I_POS + 4096)
__device__ int g_ints[I_ESRC + EE];

// ---------------- helpers ----------------
__device__ __forceinline__ void split2h(float x0, float x1, unsigned &hi, unsigned &lo) {
    __half h0 = __float2half_rn(x0);
    __half h1 = __float2half_rn(x1);
    float r0 = x0 - __half2float(h0);
    float r1 = x1 - __half2float(h1);
    __half l0 = __float2half_rn(r0);
    __half l1 = __float2half_rn(r1);
    hi = ((unsigned)__half_as_ushort(h1) << 16) | (unsigned)__half_as_ushort(h0);
    lo = ((unsigned)__half_as_ushort(l1) << 16) | (unsigned)__half_as_ushort(l0);
}

__device__ __forceinline__ unsigned pack2h(float x0, float x1) {
    return ((unsigned)__half_as_ushort(__float2half_rn(x1)) << 16) |
           (unsigned)__half_as_ushort(__float2half_rn(x0));
}

__device__ __forceinline__ void mma16816h(float* c, const unsigned* a, const unsigned* b) {
    asm volatile(
        "mma.sync.aligned.m16n8k16.row.col.f32.f16.f16.f32 "
        "{%0,%1,%2,%3}, {%4,%5,%6,%7}, {%8,%9}, {%0,%1,%2,%3};\n"
        : "+f"(c[0]), "+f"(c[1]), "+f"(c[2]), "+f"(c[3])
        : "r"(a[0]), "r"(a[1]), "r"(a[2]), "r"(a[3]), "r"(b[0]), "r"(b[1]));
}

__device__ __forceinline__ void ldsm4(unsigned &r0, unsigned &r1, unsigned &r2, unsigned &r3,
                                      uint32_t addr) {
    asm volatile("ldmatrix.sync.aligned.m8n8.x4.shared.b16 {%0,%1,%2,%3}, [%4];"
                 : "=r"(r0), "=r"(r1), "=r"(r2), "=r"(r3) : "r"(addr));
}

__device__ __forceinline__ void ldsm4t(unsigned &r0, unsigned &r1, unsigned &r2, unsigned &r3,
                                       uint32_t addr) {
    asm volatile("ldmatrix.sync.aligned.m8n8.x4.trans.shared.b16 {%0,%1,%2,%3}, [%4];"
                 : "=r"(r0), "=r"(r1), "=r"(r2), "=r"(r3) : "r"(addr));
}

__device__ __forceinline__ uint32_t smem_u32(const void* p) {
    uint32_t a;
    asm("{ .reg .u64 t; cvta.to.shared.u64 t, %1; cvt.u32.u64 %0, t; }" : "=r"(a) : "l"(p));
    return a;
}

#define CP16(dst, src) asm volatile("cp.async.cg.shared.global [%0], [%1], 16;" :: "r"(dst), "l"(src) : "memory")
#define CP_COMMIT()    asm volatile("cp.async.commit_group;" ::: "memory")
#define CP_WAIT0()     asm volatile("cp.async.wait_group 0;" ::: "memory")
#define CP_WAIT1()     asm volatile("cp.async.wait_group 1;" ::: "memory")

__device__ __forceinline__ float geluf(float v) {
    return 0.5f * v * (1.f + erff(v * 0.70710678118654752f));
}

// ---------------- CSR build (edge_index int32 [2,E]) ----------------
__global__ void k_zero_deg() {
    int i = blockIdx.x * blockDim.x + threadIdx.x;
    if (i < NN) g_ints[I_DEG + i] = 0;
}
__global__ void k_count(const int* __restrict__ ei) {
    int e = blockIdx.x * blockDim.x + threadIdx.x;
    if (e < EE) atomicAdd(&g_ints[I_DEG + (ei[EE + e] & (NN - 1))], 1);
}
__global__ void k_scan() {
    __shared__ int ws[32];
    int t = threadIdx.x;
    int v[4]; int tot = 0;
#pragma unroll
    for (int j = 0; j < 4; j++) { v[j] = g_ints[I_DEG + t*4 + j]; tot += v[j]; }
    int lane = t & 31, wid = t >> 5;
    int sc = tot;
#pragma unroll
    for (int o = 1; o < 32; o <<= 1) {
        int y = __shfl_up_sync(0xffffffffu, sc, o);
        if (lane >= o) sc += y;
    }
    if (lane == 31) ws[wid] = sc;
    __syncthreads();
    if (wid == 0) {
        int z = ws[lane];
#pragma unroll
        for (int o = 1; o < 32; o <<= 1) {
            int y = __shfl_up_sync(0xffffffffu, z, o);
            if (lane >= o) z += y;
        }
        ws[lane] = z;
    }
    __syncthreads();
    int excl = sc - tot + (wid ? ws[wid - 1] : 0);
    int run = excl;
#pragma unroll
    for (int j = 0; j < 4; j++) {
        g_ints[I_OFF + t*4 + j] = run;
        g_ints[I_POS + t*4 + j] = run;
        run += v[j];
    }
    if (t == 1023) g_ints[I_OFF + 4096] = run;
}
__global__ void k_scatter(const int* __restrict__ ei) {
    int e = blockIdx.x * blockDim.x + threadIdx.x;
    if (e < EE) {
        int d = ei[EE + e] & (NN - 1);
        int s = ei[e] & (NN - 1);
        int p = atomicAdd(&g_ints[I_POS + d], 1);
        if (p >= 0 && p < EE) g_ints[I_ESRC + p] = s;
    }
}

// ---------------- fp32 -> fp16 hi/lo split (activations) ----------------
__global__ void k_split(const float* __restrict__ in, __half* __restrict__ hi,
                        __half* __restrict__ lo, int n4) {
    int i = blockIdx.x * blockDim.x + threadIdx.x;
    if (i >= n4) return;
    float4 v = ((const float4*)in)[i];
    unsigned h0, l0, h1, l1;
    split2h(v.x, v.y, h0, l0); split2h(v.z, v.w, h1, l1);
    ((uint2*)hi)[i] = make_uint2(h0, h1);
    ((uint2*)lo)[i] = make_uint2(l0, l1);
}

// ---------------- fp32 -> fp16 convert (weights, hi only) ----------------
__global__ void k_half(const float* __restrict__ in, __half* __restrict__ hi, int n4) {
    int i = blockIdx.x * blockDim.x + threadIdx.x;
    if (i >= n4) return;
    float4 v = ((const float4*)in)[i];
    ((uint2*)hi)[i] = make_uint2(pack2h(v.x, v.y), pack2h(v.z, v.w));
}

// ---------------- mma.sync NT GEMM, fp16 2-product, LDSM + cp.async pipeline ----------------
// BM=128 BN=64 BK=32, 256 thr, 8 warps (4Mx2N). Double-buffered dynamic smem.
// Buffer layout (bytes, per side 25600): Ah 0..10239, Al 10240..20479, Bh 20480..25599.
#define G_SMEM (2 * 25600)

template <int EPI>
__global__ void __launch_bounds__(256) k_gemm(
    const __half* __restrict__ Ah, const __half* __restrict__ Al,
    const __half* __restrict__ Bh,
    const float* __restrict__ bias, float* __restrict__ Cf,
    __half* __restrict__ Ch, __half* __restrict__ Cl,
    int Nd, int K) {
    extern __shared__ __align__(16) unsigned gsm[];
    int tid = threadIdx.x;
    int lane = tid & 31, wid = tid >> 5;
    int wm = wid & 3, wn = wid >> 2;
    int mBase = wm * 32, nBase = wn * 32;
    int g = lane >> 2, t = lane & 3;
    int bm = blockIdx.y * 128, bn = blockIdx.x * 64;
    uint32_t smB = smem_u32(gsm);

    // copy indices: 16B chunks; rows stride 80B, data in first 64B
    int rA0 = tid >> 2;
    int cA0 = (tid & 3) * 16;
    uint32_t dA0 = rA0 * 80 + cA0;
    uint32_t dA1 = dA0 + 64 * 80;
    const char* gA0h = (const char*)Ah + ((long)(bm + rA0) * K) * 2 + cA0;
    const char* gA1h = (const char*)Ah + ((long)(bm + rA0 + 64) * K) * 2 + cA0;
    const char* gA0l = (const char*)Al + ((long)(bm + rA0) * K) * 2 + cA0;
    const char* gA1l = (const char*)Al + ((long)(bm + rA0 + 64) * K) * 2 + cA0;
    const char* gB   = (const char*)Bh + ((long)(bn + rA0) * K) * 2 + cA0;

    // fragment offsets (relative to buffer base)
    uint32_t aFh = (mBase + (lane & 15)) * 80 + (lane >> 4) * 16;
    uint32_t aFl = 10240 + aFh;
    uint32_t bF  = 20480 + (nBase + 8 * (lane >> 4) + (lane & 7)) * 80 + ((lane >> 3) & 1) * 16;

    float c[2][4][4];
#pragma unroll
    for (int mi = 0; mi < 2; mi++)
#pragma unroll
        for (int ni = 0; ni < 4; ni++)
#pragma unroll
            for (int j = 0; j < 4; j++) c[mi][ni][j] = 0.f;

    int nch = K >> 5;
    // prefetch chunk 0
    {
        uint32_t bb = smB;
        CP16(bb + dA0, gA0h);
        CP16(bb + dA1, gA1h);
        CP16(bb + 10240 + dA0, gA0l);
        CP16(bb + 10240 + dA1, gA1l);
        CP16(bb + 20480 + dA0, gB);
    }
    CP_COMMIT();

    for (int cc = 0; cc < nch; cc++) {
        if (cc + 1 < nch) {
            long kb = (long)(cc + 1) * 64;      // 32 halves = 64 bytes
            uint32_t bb = smB + ((cc + 1) & 1) * 25600;
            CP16(bb + dA0, gA0h + kb);
            CP16(bb + dA1, gA1h + kb);
            CP16(bb + 10240 + dA0, gA0l + kb);
            CP16(bb + 10240 + dA1, gA1l + kb);
            CP16(bb + 20480 + dA0, gB + kb);
            CP_COMMIT();
            CP_WAIT1();
        } else {
            CP_WAIT0();
        }
        __syncthreads();
        uint32_t bb = smB + (cc & 1) * 25600;
#pragma unroll
        for (int ks = 0; ks < 2; ks++) {
            unsigned ah[2][4], al[2][4], bh[4][2];
#pragma unroll
            for (int mi = 0; mi < 2; mi++) {
                ldsm4(ah[mi][0], ah[mi][1], ah[mi][2], ah[mi][3], bb + aFh + mi * 1280 + ks * 32);
                ldsm4(al[mi][0], al[mi][1], al[mi][2], al[mi][3], bb + aFl + mi * 1280 + ks * 32);
            }
#pragma unroll
            for (int p = 0; p < 2; p++) {
                ldsm4(bh[2*p][0], bh[2*p][1], bh[2*p+1][0], bh[2*p+1][1], bb + bF + p * 1280 + ks * 32);
            }
#pragma unroll
            for (int mi = 0; mi < 2; mi++)
#pragma unroll
                for (int ni = 0; ni < 4; ni++) {
                    mma16816h(c[mi][ni], al[mi], bh[ni]);
                    mma16816h(c[mi][ni], ah[mi], bh[ni]);
                }
        }
        __syncthreads();
    }

    // epilogue
#pragma unroll
    for (int mi = 0; mi < 2; mi++)
#pragma unroll
        for (int ni = 0; ni < 4; ni++) {
            int n0 = bn + nBase + ni * 8 + 2 * t;
            long r0 = bm + mBase + mi * 16 + g;
            float v0 = c[mi][ni][0] + bias[n0];
            float v1 = c[mi][ni][1] + bias[n0 + 1];
            float v2 = c[mi][ni][2] + bias[n0];
            float v3 = c[mi][ni][3] + bias[n0 + 1];
            if (EPI == 0) {
                Cf[r0 * Nd + n0]           = v0;
                Cf[r0 * Nd + n0 + 1]       = v1;
                Cf[(r0 + 8) * Nd + n0]     = v2;
                Cf[(r0 + 8) * Nd + n0 + 1] = v3;
            } else {
                if (EPI == 1) { v0 = geluf(v0); v1 = geluf(v1); v2 = geluf(v2); v3 = geluf(v3); }
                unsigned hp, lp;
                split2h(v0, v1, hp, lp);
                *(unsigned*)&Ch[r0 * Nd + n0] = hp;
                *(unsigned*)&Cl[r0 * Nd + n0] = lp;
                split2h(v2, v3, hp, lp);
                *(unsigned*)&Ch[(r0 + 8) * Nd + n0] = hp;
                *(unsigned*)&Cl[(r0 + 8) * Nd + n0] = lp;
            }
        }
}

// ---------------- GAT per-node online softmax aggregation ----------------
__global__ void k_gat(const float* __restrict__ xl, const float* __restrict__ xr,
                      const float* __restrict__ att, const float* __restrict__ gbias,
                      float* __restrict__ outp) {
    int i = blockIdx.x;
    int w = threadIdx.x >> 5;
    int lane = threadIdx.x & 31;
    int c0 = lane, c1 = lane + 32;
    const float* xli = xl + (long)i * CC + w * COH;
    float xl0 = xli[c0], xl1 = xli[c1];
    float a0 = att[w * COH + c0], a1 = att[w * COH + c1];
    float m = -1e30f, l = 0.f, acc0 = 0.f, acc1 = 0.f;
    int beg = g_ints[I_OFF + i], end = g_ints[I_OFF + i + 1];
    for (int j = beg; j <= end; j++) {
        int s = (j < end) ? g_ints[I_ESRC + j] : i;
        const float* xrs = xr + (long)s * CC + w * COH;
        float xr0 = xrs[c0], xr1 = xrs[c1];
        float e0 = xl0 + xr0; e0 = (e0 > 0.f) ? e0 : 0.2f * e0;
        float e1 = xl1 + xr1; e1 = (e1 > 0.f) ? e1 : 0.2f * e1;
        float p = e0 * a0 + e1 * a1;
#pragma unroll
        for (int o = 16; o; o >>= 1) p += __shfl_xor_sync(0xffffffffu, p, o);
        float mn = fmaxf(m, p);
        float sc = __expf(m - mn);
        float wg = __expf(p - mn);
        l = l * sc + wg;
        acc0 = acc0 * sc + xr0 * wg;
        acc1 = acc1 * sc + xr1 * wg;
        m = mn;
    }
    float inv = 1.f / l;
    outp[(long)i * CC + w * COH + c0] = acc0 * inv + gbias[w * COH + c0];
    outp[(long)i * CC + w * COH + c1] = acc1 * inv + gbias[w * COH + c1];
}

// ---------------- residual add + layernorm (+ optional fp16 split out) ----------------
__global__ void k_add_ln(const float* __restrict__ x, const float* __restrict__ h,
                         const float* __restrict__ g, const float* __restrict__ b,
                         float* __restrict__ outp,
                         __half* __restrict__ oh, __half* __restrict__ ol) {
    int row = blockIdx.x;
    int t = threadIdx.x;
    __shared__ float sh[8];
    float v0 = x[(long)row * CC + t]       + h[(long)row * CC + t];
    float v1 = x[(long)row * CC + 256 + t] + h[(long)row * CC + 256 + t];
    float s = v0 + v1;
#pragma unroll
    for (int o = 16; o; o >>= 1) s += __shfl_xor_sync(0xffffffffu, s, o);
    if ((t & 31) == 0) sh[t >> 5] = s;
    __syncthreads();
    float tot = 0.f;
#pragma unroll
    for (int i = 0; i < 8; i++) tot += sh[i];
    float mu = tot * (1.f / 512.f);
    __syncthreads();
    float d0 = v0 - mu, d1 = v1 - mu;
    float q = d0 * d0 + d1 * d1;
#pragma unroll
    for (int o = 16; o; o >>= 1) q += __shfl_xor_sync(0xffffffffu, q, o);
    if ((t & 31) == 0) sh[t >> 5] = q;
    __syncthreads();
    float var = 0.f;
#pragma unroll
    for (int i = 0; i < 8; i++) var += sh[i];
    var *= (1.f / 512.f);
    float rstd = rsqrtf(var + 1e-5f);
    float y0 = d0 * rstd * g[t]       + b[t];
    float y1 = d1 * rstd * g[t + 256] + b[t + 256];
    outp[(long)row * CC + t]       = y0;
    outp[(long)row * CC + 256 + t] = y1;
    if (oh) {
        __half h0 = __float2half_rn(y0);
        __half h1 = __float2half_rn(y1);
        oh[(long)row * CC + t]       = h0;
        oh[(long)row * CC + 256 + t] = h1;
        ol[(long)row * CC + t]       = __float2half_rn(y0 - __half2float(h0));
        ol[(long)row * CC + 256 + t] = __float2half_rn(y1 - __half2float(h1));
    }
}

// ---------------- flash attention: cp.async double-buffered K/V, trans-ldmatrix V ----------------
// smem (uint units, row stride 36 = 144B): Qh 0, Ql 2304, K bufs 4608 + b*2304, V bufs 9216 + b*2304
#define FQH 0
#define FQL 2304
#define FKB 4608
#define FVB 9216
#define FLASH_SMEM (13824 * 4)

__global__ void __launch_bounds__(128) k_flash(const __half* __restrict__ qkvh,
                                               const __half* __restrict__ qkvl,
                                               __half* __restrict__ ath,
                                               __half* __restrict__ atl) {
    extern __shared__ __align__(16) unsigned sm[];
    int h = blockIdx.y;
    int q0 = blockIdx.x * 64;
    int tid = threadIdx.x;
    int lane = tid & 31, wid = tid >> 5;
    int g = lane >> 2, t = lane & 3;
    int mBase = wid * 16;
    const float qs2 = 0.125f * 1.44269504088896f;
    uint32_t smB = smem_u32(sm);

    // copy indices: 512 16B-chunks per tile, 128 threads, 4 each (rows r0+16i)
    int r0 = tid >> 3;
    int j0 = (tid & 7) * 16;
    uint32_t dKV = r0 * 144 + j0;
    const char* gK = (const char*)qkvh + ((long)r0 * QKVW + CC + h * COH) * 2 + j0;
    const char* gV = (const char*)qkvh + ((long)r0 * QKVW + 2 * CC + h * COH) * 2 + j0;

    // fragment offsets
    uint32_t qFh = smB + (mBase + (lane & 15)) * 144 + (lane >> 4) * 16;
    uint32_t qFl = qFh + FQL * 4;
    uint32_t kFo = (8 * (lane >> 4) + (lane & 7)) * 144 + ((lane >> 3) & 1) * 16;
    uint32_t vFo = (lane & 15) * 144 + (lane >> 4) * 16;

    // Q tile load (hi+lo), regular stores
#pragma unroll
    for (int i = 0; i < 4; i++) {
        int cchunk = tid + i * 128;
        int r = cchunk >> 3;
        int q4 = cchunk & 7;
        long goff = (long)(q0 + r) * QKVW + h * COH + q4 * 8;
        *(uint4*)&sm[FQH + r * 36 + q4 * 4] = *(const uint4*)&qkvh[goff];
        *(uint4*)&sm[FQL + r * 36 + q4 * 4] = *(const uint4*)&qkvl[goff];
    }

    float m0 = -1e30f, m1 = -1e30f, l0s = 0.f, l1s = 0.f;
    float o[8][4];
#pragma unroll
    for (int nd = 0; nd < 8; nd++)
#pragma unroll
        for (int j = 0; j < 4; j++) o[nd][j] = 0.f;

    // prefetch tile 0
    {
        uint32_t kb = smB + FKB * 4;
        uint32_t vb = smB + FVB * 4;
#pragma unroll
        for (int i = 0; i < 4; i++) {
            CP16(kb + dKV + i * 2304, gK + (long)i * 16 * QKVW * 2);
            CP16(vb + dKV + i * 2304, gV + (long)i * 16 * QKVW * 2);
        }
        CP_COMMIT();
    }

    for (int tt = 0; tt < 64; tt++) {
        if (tt + 1 < 64) {
            long go = (long)(tt + 1) * 64 * QKVW * 2;
            uint32_t kb = smB + (FKB + ((tt + 1) & 1) * 2304) * 4;
            uint32_t vb = smB + (FVB + ((tt + 1) & 1) * 2304) * 4;
#pragma unroll
            for (int i = 0; i < 4; i++) {
                CP16(kb + dKV + i * 2304, gK + go + (long)i * 16 * QKVW * 2);
                CP16(vb + dKV + i * 2304, gV + go + (long)i * 16 * QKVW * 2);
            }
            CP_COMMIT();
            CP_WAIT1();
        } else {
            CP_WAIT0();
        }
        __syncthreads();
        uint32_t kb = smB + (FKB + (tt & 1) * 2304) * 4;
        uint32_t vb = smB + (FVB + (tt & 1) * 2304) * 4;

        // S = Q K^T (2-product)
        float s[8][4];
#pragma unroll
        for (int ni = 0; ni < 8; ni++)
#pragma unroll
            for (int j = 0; j < 4; j++) s[ni][j] = 0.f;

#pragma unroll
        for (int ks = 0; ks < 4; ks++) {
            unsigned ah[4], al[4];
            ldsm4(ah[0], ah[1], ah[2], ah[3], qFh + ks * 32);
            ldsm4(al[0], al[1], al[2], al[3], qFl + ks * 32);
#pragma unroll
            for (int p = 0; p < 4; p++) {
                unsigned bh[2][2];
                ldsm4(bh[0][0], bh[0][1], bh[1][0], bh[1][1], kb + kFo + p * 2304 + ks * 32);
                mma16816h(s[2*p],     al, bh[0]);
                mma16816h(s[2*p],     ah, bh[0]);
                mma16816h(s[2*p + 1], al, bh[1]);
                mma16816h(s[2*p + 1], ah, bh[1]);
            }
        }
#pragma unroll
        for (int ni = 0; ni < 8; ni++)
#pragma unroll
            for (int j = 0; j < 4; j++) s[ni][j] *= qs2;

        // online softmax (base-2)
        float mx0 = -1e30f, mx1 = -1e30f;
#pragma unroll
        for (int ni = 0; ni < 8; ni++) {
            mx0 = fmaxf(mx0, fmaxf(s[ni][0], s[ni][1]));
            mx1 = fmaxf(mx1, fmaxf(s[ni][2], s[ni][3]));
        }
        mx0 = fmaxf(mx0, __shfl_xor_sync(0xffffffffu, mx0, 1));
        mx0 = fmaxf(mx0, __shfl_xor_sync(0xffffffffu, mx0, 2));
        mx1 = fmaxf(mx1, __shfl_xor_sync(0xffffffffu, mx1, 1));
        mx1 = fmaxf(mx1, __shfl_xor_sync(0xffffffffu, mx1, 2));
        float mn0 = fmaxf(m0, mx0), mn1 = fmaxf(m1, mx1);
        float sc0 = exp2f(m0 - mn0), sc1 = exp2f(m1 - mn1);
        m0 = mn0; m1 = mn1;
        float sum0 = 0.f, sum1 = 0.f;
#pragma unroll
        for (int ni = 0; ni < 8; ni++) {
            s[ni][0] = exp2f(s[ni][0] - m0); sum0 += s[ni][0];
            s[ni][1] = exp2f(s[ni][1] - m0); sum0 += s[ni][1];
            s[ni][2] = exp2f(s[ni][2] - m1); sum1 += s[ni][2];
            s[ni][3] = exp2f(s[ni][3] - m1); sum1 += s[ni][3];
        }
        sum0 += __shfl_xor_sync(0xffffffffu, sum0, 1);
        sum0 += __shfl_xor_sync(0xffffffffu, sum0, 2);
        sum1 += __shfl_xor_sync(0xffffffffu, sum1, 1);
        sum1 += __shfl_xor_sync(0xffffffffu, sum1, 2);
        l0s = l0s * sc0 + sum0;
        l1s = l1s * sc1 + sum1;
#pragma unroll
        for (int nd = 0; nd < 8; nd++) {
            o[nd][0] *= sc0; o[nd][1] *= sc0;
            o[nd][2] *= sc1; o[nd][3] *= sc1;
        }

        // O += P V (P hi-only; V via trans ldmatrix from row-major [kv][d])
#pragma unroll
        for (int ks = 0; ks < 4; ks++) {
            unsigned ph[4];
            ph[0] = pack2h(s[2*ks][0],   s[2*ks][1]);
            ph[1] = pack2h(s[2*ks][2],   s[2*ks][3]);
            ph[2] = pack2h(s[2*ks+1][0], s[2*ks+1][1]);
            ph[3] = pack2h(s[2*ks+1][2], s[2*ks+1][3]);
#pragma unroll
            for (int p = 0; p < 4; p++) {
                unsigned bh[2][2];
                ldsm4t(bh[0][0], bh[0][1], bh[1][0], bh[1][1], vb + vFo + ks * 2304 + p * 32);
                mma16816h(o[2*p],     ph, bh[0]);
                mma16816h(o[2*p + 1], ph, bh[1]);
            }
        }
        __syncthreads();
    }

    float inv0 = 1.f / l0s, inv1 = 1.f / l1s;
#pragma unroll
    for (int nd = 0; nd < 8; nd++) {
        int ccol = h * COH + nd * 8 + 2 * t;
        long r0q = q0 + mBase + g;
        unsigned hp, lp;
        split2h(o[nd][0] * inv0, o[nd][1] * inv0, hp, lp);
        *(unsigned*)&ath[r0q * CC + ccol] = hp;
        *(unsigned*)&atl[r0q * CC + ccol] = lp;
        split2h(o[nd][2] * inv1, o[nd][3] * inv1, hp, lp);
        *(unsigned*)&ath[(r0q + 8) * CC + ccol] = hp;
        *(unsigned*)&atl[(r0q + 8) * CC + ccol] = lp;
    }
}

// ---------------- launch ----------------
extern "C" void kernel_launch(void* const* d_in, const int* in_sizes, int n_in,
                              void* d_out, int out_size) {
    const float* x      = (const float*)d_in[0];
    const int*   ei     = (const int*)d_in[1];
    const float* gat_wl = (const float*)d_in[2];
    const float* gat_bl = (const float*)d_in[3];
    const float* gat_wr = (const float*)d_in[4];
    const float* gat_br = (const float*)d_in[5];
    const float* gat_at = (const float*)d_in[6];
    const float* gat_b  = (const float*)d_in[7];
    const float* in_w   = (const float*)d_in[8];
    const float* in_b   = (const float*)d_in[9];
    const float* out_w  = (const float*)d_in[10];
    const float* out_b  = (const float*)d_in[11];
    const float* ln1_g  = (const float*)d_in[12];
    const float* ln1_b  = (const float*)d_in[13];
    const float* ln2_g  = (const float*)d_in[14];
    const float* ln2_b  = (const float*)d_in[15];
    const float* ln3_g  = (const float*)d_in[16];
    const float* ln3_b  = (const float*)d_in[17];
    const float* w1     = (const float*)d_in[18];
    const float* b1     = (const float*)d_in[19];
    const float* w2     = (const float*)d_in[20];
    const float* b2     = (const float*)d_in[21];
    float* outp = (float*)d_out;

    float* gs = nullptr;
    cudaGetSymbolAddress((void**)&gs, g_scratch);
    __half* gh = nullptr;
    cudaGetSymbolAddress((void**)&gh, g_hf);

    cudaFuncSetAttribute(k_flash, cudaFuncAttributeMaxDynamicSharedMemorySize, FLASH_SMEM);
    cudaFuncSetAttribute(k_gemm<0>, cudaFuncAttributeMaxDynamicSharedMemorySize, G_SMEM);
    cudaFuncSetAttribute(k_gemm<1>, cudaFuncAttributeMaxDynamicSharedMemorySize, G_SMEM);
    cudaFuncSetAttribute(k_gemm<2>, cudaFuncAttributeMaxDynamicSharedMemorySize, G_SMEM);

    __half *Xh = gh + ZX,    *Xl = Xh + (long)NN*CC;
    __half *X1h = gh + ZX1,  *X1l = X1h + (long)NN*CC;
    __half *Ath = gh + ZATT, *Atl = Ath + (long)NN*CC;
    __half *X2h = gh + ZX2,  *X2l = X2h + (long)NN*CC;
    __half *Qh = gh + ZQKV,  *Ql = Qh + (long)NN*3*CC;
    __half *Fh = gh + ZFFN,  *Fl = Fh + (long)NN*4*CC;
    __half *WLh = gh + ZWL;
    __half *WRh = gh + ZWR;
    __half *INh = gh + ZIN;
    __half *OWh = gh + ZOW;
    __half *W1h = gh + ZW1;
    __half *W2h = gh + ZW2;

    // CSR build
    k_zero_deg<<<16, 256>>>();
    k_count<<<EE / 256, 256>>>(ei);
    k_scan<<<1, 1024>>>();
    k_scatter<<<EE / 256, 256>>>(ei);

    // pre-split x (hi+lo) + convert weights (hi only)
    k_split<<<(NN*CC/4 + 255)/256, 256>>>(x, Xh, Xl, NN*CC/4);
    k_half<<<(CC*CC/4 + 255)/256, 256>>>(gat_wl, WLh, CC*CC/4);
    k_half<<<(CC*CC/4 + 255)/256, 256>>>(gat_wr, WRh, CC*CC/4);
    k_half<<<(3*CC*CC/4 + 255)/256, 256>>>(in_w, INh, 3*CC*CC/4);
    k_half<<<(CC*CC/4 + 255)/256, 256>>>(out_w, OWh, CC*CC/4);
    k_half<<<(4*CC*CC/4 + 255)/256, 256>>>(w1, W1h, 4*CC*CC/4);
    k_half<<<(4*CC*CC/4 + 255)/256, 256>>>(w2, W2h, 4*CC*CC/4);

    // GAT projections (fp32 out)
    dim3 g512(CC / 64, NN / 128);
    k_gemm<0><<<g512, 256, G_SMEM>>>(Xh, Xl, WLh, gat_bl, gs + S_XL, 0, 0, CC, CC);
    k_gemm<0><<<g512, 256, G_SMEM>>>(Xh, Xl, WRh, gat_br, gs + S_XR, 0, 0, CC, CC);

    // GAT aggregation
    k_gat<<<NN, 256>>>(gs + S_XL, gs + S_XR, gat_at, gat_b, gs + S_HB);

    // x1 = LN(x + h_local), + split
    k_add_ln<<<NN, 256>>>(x, gs + S_HB, ln1_g, ln1_b, gs + S_X1, X1h, X1l);

    // QKV (split fp16 out)
    dim3 gqkv(QKVW / 64, NN / 128);
    k_gemm<2><<<gqkv, 256, G_SMEM>>>(X1h, X1l, INh, in_b, 0, Qh, Ql, QKVW, CC);

    // flash attention (split in, split out)
    dim3 gfl(NN / 64, HH);
    k_flash<<<gfl, 128, FLASH_SMEM>>>(Qh, Ql, Ath, Atl);

    // out proj (fp32 out)
    k_gemm<0><<<g512, 256, G_SMEM>>>(Ath, Atl, OWh, out_b, gs + S_HB, 0, 0, CC, CC);

    // x2 = LN(x1 + h_global), + split
    k_add_ln<<<NN, 256>>>(gs + S_X1, gs + S_HB, ln2_g, ln2_b, gs + S_X2, X2h, X2l);

    // FFN1 (GELU, split fp16 out)
    dim3 gffn1(4 * CC / 64, NN / 128);
    k_gemm<1><<<gffn1, 256, G_SMEM>>>(X2h, X2l, W1h, b1, 0, Fh, Fl, 4 * CC, CC);
    // FFN2 (fp32 out)
    k_gemm<0><<<g512, 256, G_SMEM>>>(Fh, Fl, W2h, b2, gs + S_HB, 0, 0, CC, 4 * CC);

    // out = LN(x2 + ffn)
    k_add_ln<<<NN, 256>>>(gs + S_X2, gs + S_HB, ln3_g, ln3_b, outp, 0, 0);
}

// round 13
// speedup vs baseline: 1.9545x; 1.0279x over previous
#include <cuda_runtime.h>
#include <cuda_fp16.h>
#include <stdint.h>
#include <math.h>

#define NN    4096
#define CC    512
#define HH    8
#define COH   64
#define EE    131072
#define QKVW  1536

// ---------------- fp32 scratch ----------------
#define S_XL   0L
#define S_XR   (S_XL  + (long)NN*CC)
#define S_HB   (S_XR  + (long)NN*CC)
#define S_X1   (S_HB  + (long)NN*CC)
#define S_X2   (S_X1  + (long)NN*CC)
#define S_TOT  (S_X2  + (long)NN*CC)
__device__ float g_scratch[S_TOT];

// ---------------- fp16 scratch: activations hi+lo, weights hi only ----------------
#define ZX    0L
#define ZX1   (ZX   + 2L*NN*CC)
#define ZATT  (ZX1  + 2L*NN*CC)
#define ZX2   (ZATT + 2L*NN*CC)
#define ZQKV  (ZX2  + 2L*NN*CC)
#define ZFFN  (ZQKV + 2L*NN*3*CC)
#define ZWL   (ZFFN + 2L*NN*4*CC)
#define ZWR   (ZWL  + 1L*CC*CC)
#define ZIN   (ZWR  + 1L*CC*CC)
#define ZOW   (ZIN  + 3L*CC*CC)
#define ZW1   (ZOW  + 1L*CC*CC)
#define ZW2   (ZW1  + 4L*CC*CC)
#define ZTOT  (ZW2  + 4L*CC*CC)
__device__ __half g_hf[ZTOT];

// int scratch
#define I_DEG  0
#define I_OFF  4096
#define I_POS  (I_OFF + 4097)
#define I_ESRC (I_POS + 4096)
__device__ int g_ints[I_ESRC + EE];

// ---------------- helpers ----------------
__device__ __forceinline__ void split2h(float x0, float x1, unsigned &hi, unsigned &lo) {
    __half h0 = __float2half_rn(x0);
    __half h1 = __float2half_rn(x1);
    float r0 = x0 - __half2float(h0);
    float r1 = x1 - __half2float(h1);
    __half l0 = __float2half_rn(r0);
    __half l1 = __float2half_rn(r1);
    hi = ((unsigned)__half_as_ushort(h1) << 16) | (unsigned)__half_as_ushort(h0);
    lo = ((unsigned)__half_as_ushort(l1) << 16) | (unsigned)__half_as_ushort(l0);
}

__device__ __forceinline__ unsigned pack2h(float x0, float x1) {
    return ((unsigned)__half_as_ushort(__float2half_rn(x1)) << 16) |
           (unsigned)__half_as_ushort(__float2half_rn(x0));
}

__device__ __forceinline__ void mma16816h(float* c, const unsigned* a, const unsigned* b) {
    asm volatile(
        "mma.sync.aligned.m16n8k16.row.col.f32.f16.f16.f32 "
        "{%0,%1,%2,%3}, {%4,%5,%6,%7}, {%8,%9}, {%0,%1,%2,%3};\n"
        : "+f"(c[0]), "+f"(c[1]), "+f"(c[2]), "+f"(c[3])
        : "r"(a[0]), "r"(a[1]), "r"(a[2]), "r"(a[3]), "r"(b[0]), "r"(b[1]));
}

__device__ __forceinline__ void ldsm4(unsigned &r0, unsigned &r1, unsigned &r2, unsigned &r3,
                                      uint32_t addr) {
    asm volatile("ldmatrix.sync.aligned.m8n8.x4.shared.b16 {%0,%1,%2,%3}, [%4];"
                 : "=r"(r0), "=r"(r1), "=r"(r2), "=r"(r3) : "r"(addr));
}

__device__ __forceinline__ void ldsm4t(unsigned &r0, unsigned &r1, unsigned &r2, unsigned &r3,
                                       uint32_t addr) {
    asm volatile("ldmatrix.sync.aligned.m8n8.x4.trans.shared.b16 {%0,%1,%2,%3}, [%4];"
                 : "=r"(r0), "=r"(r1), "=r"(r2), "=r"(r3) : "r"(addr));
}

__device__ __forceinline__ uint32_t smem_u32(const void* p) {
    uint32_t a;
    asm("{ .reg .u64 t; cvta.to.shared.u64 t, %1; cvt.u32.u64 %0, t; }" : "=r"(a) : "l"(p));
    return a;
}

#define CP16(dst, src) asm volatile("cp.async.cg.shared.global [%0], [%1], 16;" :: "r"(dst), "l"(src) : "memory")
#define CP_COMMIT()    asm volatile("cp.async.commit_group;" ::: "memory")
#define CP_WAIT0()     asm volatile("cp.async.wait_group 0;" ::: "memory")
#define CP_WAIT1()     asm volatile("cp.async.wait_group 1;" ::: "memory")

__device__ __forceinline__ float geluf(float v) {
    return 0.5f * v * (1.f + erff(v * 0.70710678118654752f));
}

// ---------------- CSR build (edge_index int32 [2,E]) ----------------
__global__ void k_zero_deg() {
    int i = blockIdx.x * blockDim.x + threadIdx.x;
    if (i < NN) g_ints[I_DEG + i] = 0;
}
__global__ void k_count(const int* __restrict__ ei) {
    int e = blockIdx.x * blockDim.x + threadIdx.x;
    if (e < EE) atomicAdd(&g_ints[I_DEG + (ei[EE + e] & (NN - 1))], 1);
}
__global__ void k_scan() {
    __shared__ int ws[32];
    int t = threadIdx.x;
    int v[4]; int tot = 0;
#pragma unroll
    for (int j = 0; j < 4; j++) { v[j] = g_ints[I_DEG + t*4 + j]; tot += v[j]; }
    int lane = t & 31, wid = t >> 5;
    int sc = tot;
#pragma unroll
    for (int o = 1; o < 32; o <<= 1) {
        int y = __shfl_up_sync(0xffffffffu, sc, o);
        if (lane >= o) sc += y;
    }
    if (lane == 31) ws[wid] = sc;
    __syncthreads();
    if (wid == 0) {
        int z = ws[lane];
#pragma unroll
        for (int o = 1; o < 32; o <<= 1) {
            int y = __shfl_up_sync(0xffffffffu, z, o);
            if (lane >= o) z += y;
        }
        ws[lane] = z;
    }
    __syncthreads();
    int excl = sc - tot + (wid ? ws[wid - 1] : 0);
    int run = excl;
#pragma unroll
    for (int j = 0; j < 4; j++) {
        g_ints[I_OFF + t*4 + j] = run;
        g_ints[I_POS + t*4 + j] = run;
        run += v[j];
    }
    if (t == 1023) g_ints[I_OFF + 4096] = run;
}
__global__ void k_scatter(const int* __restrict__ ei) {
    int e = blockIdx.x * blockDim.x + threadIdx.x;
    if (e < EE) {
        int d = ei[EE + e] & (NN - 1);
        int s = ei[e] & (NN - 1);
        int p = atomicAdd(&g_ints[I_POS + d], 1);
        if (p >= 0 && p < EE) g_ints[I_ESRC + p] = s;
    }
}

// ---------------- fp32 -> fp16 hi/lo split (activations) ----------------
__global__ void k_split(const float* __restrict__ in, __half* __restrict__ hi,
                        __half* __restrict__ lo, int n4) {
    int i = blockIdx.x * blockDim.x + threadIdx.x;
    if (i >= n4) return;
    float4 v = ((const float4*)in)[i];
    unsigned h0, l0, h1, l1;
    split2h(v.x, v.y, h0, l0); split2h(v.z, v.w, h1, l1);
    ((uint2*)hi)[i] = make_uint2(h0, h1);
    ((uint2*)lo)[i] = make_uint2(l0, l1);
}

// ---------------- fp32 -> fp16 convert (weights, hi only) ----------------
__global__ void k_half(const float* __restrict__ in, __half* __restrict__ hi, int n4) {
    int i = blockIdx.x * blockDim.x + threadIdx.x;
    if (i >= n4) return;
    float4 v = ((const float4*)in)[i];
    ((uint2*)hi)[i] = make_uint2(pack2h(v.x, v.y), pack2h(v.z, v.w));
}

// ---------------- mma.sync NT GEMM, fp16 2-product, LDSM + cp.async pipeline ----------------
// BM=128 BN=64 BK=32, 256 thr, 8 warps (4Mx2N). Double-buffered dynamic smem.
#define G_SMEM (2 * 25600)

template <int EPI>
__global__ void __launch_bounds__(256) k_gemm(
    const __half* __restrict__ Ah, const __half* __restrict__ Al,
    const __half* __restrict__ Bh,
    const float* __restrict__ bias, float* __restrict__ Cf,
    __half* __restrict__ Ch, __half* __restrict__ Cl,
    int Nd, int K) {
    extern __shared__ __align__(16) unsigned gsm[];
    int tid = threadIdx.x;
    int lane = tid & 31, wid = tid >> 5;
    int wm = wid & 3, wn = wid >> 2;
    int mBase = wm * 32, nBase = wn * 32;
    int g = lane >> 2, t = lane & 3;
    int bm = blockIdx.y * 128, bn = blockIdx.x * 64;
    uint32_t smB = smem_u32(gsm);

    int rA0 = tid >> 2;
    int cA0 = (tid & 3) * 16;
    uint32_t dA0 = rA0 * 80 + cA0;
    uint32_t dA1 = dA0 + 64 * 80;
    const char* gA0h = (const char*)Ah + ((long)(bm + rA0) * K) * 2 + cA0;
    const char* gA1h = (const char*)Ah + ((long)(bm + rA0 + 64) * K) * 2 + cA0;
    const char* gA0l = (const char*)Al + ((long)(bm + rA0) * K) * 2 + cA0;
    const char* gA1l = (const char*)Al + ((long)(bm + rA0 + 64) * K) * 2 + cA0;
    const char* gB   = (const char*)Bh + ((long)(bn + rA0) * K) * 2 + cA0;

    uint32_t aFh = (mBase + (lane & 15)) * 80 + (lane >> 4) * 16;
    uint32_t aFl = 10240 + aFh;
    uint32_t bF  = 20480 + (nBase + 8 * (lane >> 4) + (lane & 7)) * 80 + ((lane >> 3) & 1) * 16;

    float c[2][4][4];
#pragma unroll
    for (int mi = 0; mi < 2; mi++)
#pragma unroll
        for (int ni = 0; ni < 4; ni++)
#pragma unroll
            for (int j = 0; j < 4; j++) c[mi][ni][j] = 0.f;

    int nch = K >> 5;
    {
        uint32_t bb = smB;
        CP16(bb + dA0, gA0h);
        CP16(bb + dA1, gA1h);
        CP16(bb + 10240 + dA0, gA0l);
        CP16(bb + 10240 + dA1, gA1l);
        CP16(bb + 20480 + dA0, gB);
    }
    CP_COMMIT();

    for (int cc = 0; cc < nch; cc++) {
        if (cc + 1 < nch) {
            long kb = (long)(cc + 1) * 64;
            uint32_t bb = smB + ((cc + 1) & 1) * 25600;
            CP16(bb + dA0, gA0h + kb);
            CP16(bb + dA1, gA1h + kb);
            CP16(bb + 10240 + dA0, gA0l + kb);
            CP16(bb + 10240 + dA1, gA1l + kb);
            CP16(bb + 20480 + dA0, gB + kb);
            CP_COMMIT();
            CP_WAIT1();
        } else {
            CP_WAIT0();
        }
        __syncthreads();
        uint32_t bb = smB + (cc & 1) * 25600;
#pragma unroll
        for (int ks = 0; ks < 2; ks++) {
            unsigned ah[2][4], al[2][4], bh[4][2];
#pragma unroll
            for (int mi = 0; mi < 2; mi++) {
                ldsm4(ah[mi][0], ah[mi][1], ah[mi][2], ah[mi][3], bb + aFh + mi * 1280 + ks * 32);
                ldsm4(al[mi][0], al[mi][1], al[mi][2], al[mi][3], bb + aFl + mi * 1280 + ks * 32);
            }
#pragma unroll
            for (int p = 0; p < 2; p++) {
                ldsm4(bh[2*p][0], bh[2*p][1], bh[2*p+1][0], bh[2*p+1][1], bb + bF + p * 1280 + ks * 32);
            }
#pragma unroll
            for (int mi = 0; mi < 2; mi++)
#pragma unroll
                for (int ni = 0; ni < 4; ni++) {
                    mma16816h(c[mi][ni], al[mi], bh[ni]);
                    mma16816h(c[mi][ni], ah[mi], bh[ni]);
                }
        }
        __syncthreads();
    }

    // epilogue
#pragma unroll
    for (int mi = 0; mi < 2; mi++)
#pragma unroll
        for (int ni = 0; ni < 4; ni++) {
            int n0 = bn + nBase + ni * 8 + 2 * t;
            long r0 = bm + mBase + mi * 16 + g;
            float v0 = c[mi][ni][0] + bias[n0];
            float v1 = c[mi][ni][1] + bias[n0 + 1];
            float v2 = c[mi][ni][2] + bias[n0];
            float v3 = c[mi][ni][3] + bias[n0 + 1];
            if (EPI == 0) {
                Cf[r0 * Nd + n0]           = v0;
                Cf[r0 * Nd + n0 + 1]       = v1;
                Cf[(r0 + 8) * Nd + n0]     = v2;
                Cf[(r0 + 8) * Nd + n0 + 1] = v3;
            } else {
                if (EPI == 1) { v0 = geluf(v0); v1 = geluf(v1); v2 = geluf(v2); v3 = geluf(v3); }
                bool wlo = (EPI == 1) || (n0 < CC);   // QKV: only Q needs lo
                unsigned hp, lp;
                split2h(v0, v1, hp, lp);
                *(unsigned*)&Ch[r0 * Nd + n0] = hp;
                if (wlo) *(unsigned*)&Cl[r0 * Nd + n0] = lp;
                split2h(v2, v3, hp, lp);
                *(unsigned*)&Ch[(r0 + 8) * Nd + n0] = hp;
                if (wlo) *(unsigned*)&Cl[(r0 + 8) * Nd + n0] = lp;
            }
        }
}

// ---------------- GAT per-node online softmax aggregation (2-edge ILP) ----------------
__global__ void k_gat(const float* __restrict__ xl, const float* __restrict__ xr,
                      const float* __restrict__ att, const float* __restrict__ gbias,
                      float* __restrict__ outp) {
    int i = blockIdx.x;
    int w = threadIdx.x >> 5;
    int lane = threadIdx.x & 31;
    int c0 = lane, c1 = lane + 32;
    const float* xli = xl + (long)i * CC + w * COH;
    float xl0 = xli[c0], xl1 = xli[c1];
    float a0 = att[w * COH + c0], a1 = att[w * COH + c1];
    float m = -1e30f, l = 0.f, acc0 = 0.f, acc1 = 0.f;
    int beg = g_ints[I_OFF + i], end = g_ints[I_OFF + i + 1];
    int j = beg;
    for (; j + 2 <= end; j += 2) {
        int s1 = g_ints[I_ESRC + j];
        int s2 = g_ints[I_ESRC + j + 1];
        const float* x1p = xr + (long)s1 * CC + w * COH;
        const float* x2p = xr + (long)s2 * CC + w * COH;
        float x10 = x1p[c0], x11 = x1p[c1];
        float x20 = x2p[c0], x21 = x2p[c1];
        float e10 = xl0 + x10; e10 = (e10 > 0.f) ? e10 : 0.2f * e10;
        float e11 = xl1 + x11; e11 = (e11 > 0.f) ? e11 : 0.2f * e11;
        float e20 = xl0 + x20; e20 = (e20 > 0.f) ? e20 : 0.2f * e20;
        float e21 = xl1 + x21; e21 = (e21 > 0.f) ? e21 : 0.2f * e21;
        float p1 = e10 * a0 + e11 * a1;
        float p2 = e20 * a0 + e21 * a1;
#pragma unroll
        for (int o = 16; o; o >>= 1) {
            p1 += __shfl_xor_sync(0xffffffffu, p1, o);
            p2 += __shfl_xor_sync(0xffffffffu, p2, o);
        }
        float mn = fmaxf(m, fmaxf(p1, p2));
        float sc = __expf(m - mn);
        float w1 = __expf(p1 - mn);
        float w2 = __expf(p2 - mn);
        l = l * sc + w1 + w2;
        acc0 = acc0 * sc + x10 * w1 + x20 * w2;
        acc1 = acc1 * sc + x11 * w1 + x21 * w2;
        m = mn;
    }
    for (int jj = j; jj <= end; jj++) {
        int s = (jj < end) ? g_ints[I_ESRC + jj] : i;   // tail edge(s) + self loop
        const float* xrs = xr + (long)s * CC + w * COH;
        float xr0 = xrs[c0], xr1 = xrs[c1];
        float e0 = xl0 + xr0; e0 = (e0 > 0.f) ? e0 : 0.2f * e0;
        float e1 = xl1 + xr1; e1 = (e1 > 0.f) ? e1 : 0.2f * e1;
        float p = e0 * a0 + e1 * a1;
#pragma unroll
        for (int o = 16; o; o >>= 1) p += __shfl_xor_sync(0xffffffffu, p, o);
        float mn = fmaxf(m, p);
        float sc = __expf(m - mn);
        float wg = __expf(p - mn);
        l = l * sc + wg;
        acc0 = acc0 * sc + xr0 * wg;
        acc1 = acc1 * sc + xr1 * wg;
        m = mn;
    }
    float inv = 1.f / l;
    outp[(long)i * CC + w * COH + c0] = acc0 * inv + gbias[w * COH + c0];
    outp[(long)i * CC + w * COH + c1] = acc1 * inv + gbias[w * COH + c1];
}

// ---------------- residual add + layernorm (+ optional fp16 split out) ----------------
__global__ void k_add_ln(const float* __restrict__ x, const float* __restrict__ h,
                         const float* __restrict__ g, const float* __restrict__ b,
                         float* __restrict__ outp,
                         __half* __restrict__ oh, __half* __restrict__ ol) {
    int row = blockIdx.x;
    int t = threadIdx.x;
    __shared__ float sh[8];
    float v0 = x[(long)row * CC + t]       + h[(long)row * CC + t];
    float v1 = x[(long)row * CC + 256 + t] + h[(long)row * CC + 256 + t];
    float s = v0 + v1;
#pragma unroll
    for (int o = 16; o; o >>= 1) s += __shfl_xor_sync(0xffffffffu, s, o);
    if ((t & 31) == 0) sh[t >> 5] = s;
    __syncthreads();
    float tot = 0.f;
#pragma unroll
    for (int i = 0; i < 8; i++) tot += sh[i];
    float mu = tot * (1.f / 512.f);
    __syncthreads();
    float d0 = v0 - mu, d1 = v1 - mu;
    float q = d0 * d0 + d1 * d1;
#pragma unroll
    for (int o = 16; o; o >>= 1) q += __shfl_xor_sync(0xffffffffu, q, o);
    if ((t & 31) == 0) sh[t >> 5] = q;
    __syncthreads();
    float var = 0.f;
#pragma unroll
    for (int i = 0; i < 8; i++) var += sh[i];
    var *= (1.f / 512.f);
    float rstd = rsqrtf(var + 1e-5f);
    float y0 = d0 * rstd * g[t]       + b[t];
    float y1 = d1 * rstd * g[t + 256] + b[t + 256];
    outp[(long)row * CC + t]       = y0;
    outp[(long)row * CC + 256 + t] = y1;
    if (oh) {
        __half h0 = __float2half_rn(y0);
        __half h1 = __float2half_rn(y1);
        oh[(long)row * CC + t]       = h0;
        oh[(long)row * CC + 256 + t] = h1;
        ol[(long)row * CC + t]       = __float2half_rn(y0 - __half2float(h0));
        ol[(long)row * CC + 256 + t] = __float2half_rn(y1 - __half2float(h1));
    }
}

// ---------------- flash attention: BM=128, cp.async K/V, trans-ldmatrix V ----------------
// smem (uint units, row stride 36 = 144B): Qh 0, Ql 4608, K bufs 9216 + b*2304, V bufs 13824 + b*2304
#define FQH 0
#define FQL 4608
#define FKB 9216
#define FVB 13824
#define FLASH_SMEM (18432 * 4)

__global__ void __launch_bounds__(256) k_flash(const __half* __restrict__ qkvh,
                                               const __half* __restrict__ qkvl,
                                               __half* __restrict__ ath,
                                               __half* __restrict__ atl) {
    extern __shared__ __align__(16) unsigned sm[];
    int h = blockIdx.y;
    int q0 = blockIdx.x * 128;
    int tid = threadIdx.x;
    int lane = tid & 31, wid = tid >> 5;
    int g = lane >> 2, t = lane & 3;
    int mBase = wid * 16;
    const float qs2 = 0.125f * 1.44269504088896f;
    uint32_t smB = smem_u32(sm);

    // KV copy indices: 512 16B-chunks per tile, 256 threads, 2 each (rows r0 + 32i)
    int r0 = tid >> 3;
    int j0 = (tid & 7) * 16;
    uint32_t dKV = r0 * 144 + j0;
    const char* gK = (const char*)qkvh + ((long)r0 * QKVW + CC + h * COH) * 2 + j0;
    const char* gV = (const char*)qkvh + ((long)r0 * QKVW + 2 * CC + h * COH) * 2 + j0;

    uint32_t qFh = smB + (mBase + (lane & 15)) * 144 + (lane >> 4) * 16;
    uint32_t qFl = qFh + FQL * 4;
    uint32_t kFo = (8 * (lane >> 4) + (lane & 7)) * 144 + ((lane >> 3) & 1) * 16;
    uint32_t vFo = (lane & 15) * 144 + (lane >> 4) * 16;

    // Q tile load (128 rows, hi+lo)
#pragma unroll
    for (int i = 0; i < 4; i++) {
        int cchunk = tid + i * 256;
        int r = cchunk >> 3;
        int q4 = cchunk & 7;
        long goff = (long)(q0 + r) * QKVW + h * COH + q4 * 8;
        *(uint4*)&sm[FQH + r * 36 + q4 * 4] = *(const uint4*)&qkvh[goff];
        *(uint4*)&sm[FQL + r * 36 + q4 * 4] = *(const uint4*)&qkvl[goff];
    }

    float m0 = -1e30f, m1 = -1e30f, l0s = 0.f, l1s = 0.f;
    float o[8][4];
#pragma unroll
    for (int nd = 0; nd < 8; nd++)
#pragma unroll
        for (int j = 0; j < 4; j++) o[nd][j] = 0.f;

    // prefetch tile 0
    {
        uint32_t kb = smB + FKB * 4;
        uint32_t vb = smB + FVB * 4;
#pragma unroll
        for (int i = 0; i < 2; i++) {
            CP16(kb + dKV + i * (32 * 144), gK + (long)i * 32 * QKVW * 2);
            CP16(vb + dKV + i * (32 * 144), gV + (long)i * 32 * QKVW * 2);
        }
        CP_COMMIT();
    }

    for (int tt = 0; tt < 64; tt++) {
        if (tt + 1 < 64) {
            long go = (long)(tt + 1) * 64 * QKVW * 2;
            uint32_t kb = smB + (FKB + ((tt + 1) & 1) * 2304) * 4;
            uint32_t vb = smB + (FVB + ((tt + 1) & 1) * 2304) * 4;
#pragma unroll
            for (int i = 0; i < 2; i++) {
                CP16(kb + dKV + i * (32 * 144), gK + go + (long)i * 32 * QKVW * 2);
                CP16(vb + dKV + i * (32 * 144), gV + go + (long)i * 32 * QKVW * 2);
            }
            CP_COMMIT();
            CP_WAIT1();
        } else {
            CP_WAIT0();
        }
        __syncthreads();
        uint32_t kb = smB + (FKB + (tt & 1) * 2304) * 4;
        uint32_t vb = smB + (FVB + (tt & 1) * 2304) * 4;

        // S = Q K^T (2-product)
        float s[8][4];
#pragma unroll
        for (int ni = 0; ni < 8; ni++)
#pragma unroll
            for (int j = 0; j < 4; j++) s[ni][j] = 0.f;

#pragma unroll
        for (int ks = 0; ks < 4; ks++) {
            unsigned ah[4], al[4];
            ldsm4(ah[0], ah[1], ah[2], ah[3], qFh + ks * 32);
            ldsm4(al[0], al[1], al[2], al[3], qFl + ks * 32);
#pragma unroll
            for (int p = 0; p < 4; p++) {
                unsigned bh[2][2];
                ldsm4(bh[0][0], bh[0][1], bh[1][0], bh[1][1], kb + kFo + p * 2304 + ks * 32);
                mma16816h(s[2*p],     al, bh[0]);
                mma16816h(s[2*p],     ah, bh[0]);
                mma16816h(s[2*p + 1], al, bh[1]);
                mma16816h(s[2*p + 1], ah, bh[1]);
            }
        }
#pragma unroll
        for (int ni = 0; ni < 8; ni++)
#pragma unroll
            for (int j = 0; j < 4; j++) s[ni][j] *= qs2;

        // online softmax (base-2)
        float mx0 = -1e30f, mx1 = -1e30f;
#pragma unroll
        for (int ni = 0; ni < 8; ni++) {
            mx0 = fmaxf(mx0, fmaxf(s[ni][0], s[ni][1]));
            mx1 = fmaxf(mx1, fmaxf(s[ni][2], s[ni][3]));
        }
        mx0 = fmaxf(mx0, __shfl_xor_sync(0xffffffffu, mx0, 1));
        mx0 = fmaxf(mx0, __shfl_xor_sync(0xffffffffu, mx0, 2));
        mx1 = fmaxf(mx1, __shfl_xor_sync(0xffffffffu, mx1, 1));
        mx1 = fmaxf(mx1, __shfl_xor_sync(0xffffffffu, mx1, 2));
        float mn0 = fmaxf(m0, mx0), mn1 = fmaxf(m1, mx1);
        float sc0 = exp2f(m0 - mn0), sc1 = exp2f(m1 - mn1);
        m0 = mn0; m1 = mn1;
        float sum0 = 0.f, sum1 = 0.f;
#pragma unroll
        for (int ni = 0; ni < 8; ni++) {
            s[ni][0] = exp2f(s[ni][0] - m0); sum0 += s[ni][0];
            s[ni][1] = exp2f(s[ni][1] - m0); sum0 += s[ni][1];
            s[ni][2] = exp2f(s[ni][2] - m1); sum1 += s[ni][2];
            s[ni][3] = exp2f(s[ni][3] - m1); sum1 += s[ni][3];
        }
        sum0 += __shfl_xor_sync(0xffffffffu, sum0, 1);
        sum0 += __shfl_xor_sync(0xffffffffu, sum0, 2);
        sum1 += __shfl_xor_sync(0xffffffffu, sum1, 1);
        sum1 += __shfl_xor_sync(0xffffffffu, sum1, 2);
        l0s = l0s * sc0 + sum0;
        l1s = l1s * sc1 + sum1;
#pragma unroll
        for (int nd = 0; nd < 8; nd++) {
            o[nd][0] *= sc0; o[nd][1] *= sc0;
            o[nd][2] *= sc1; o[nd][3] *= sc1;
        }

        // O += P V (P hi-only; V via trans ldmatrix)
#pragma unroll
        for (int ks = 0; ks < 4; ks++) {
            unsigned ph[4];
            ph[0] = pack2h(s[2*ks][0],   s[2*ks][1]);
            ph[1] = pack2h(s[2*ks][2],   s[2*ks][3]);
            ph[2] = pack2h(s[2*ks+1][0], s[2*ks+1][1]);
            ph[3] = pack2h(s[2*ks+1][2], s[2*ks+1][3]);
#pragma unroll
            for (int p = 0; p < 4; p++) {
                unsigned bh[2][2];
                ldsm4t(bh[0][0], bh[0][1], bh[1][0], bh[1][1], vb + vFo + ks * 2304 + p * 32);
                mma16816h(o[2*p],     ph, bh[0]);
                mma16816h(o[2*p + 1], ph, bh[1]);
            }
        }
        __syncthreads();
    }

    float inv0 = 1.f / l0s, inv1 = 1.f / l1s;
#pragma unroll
    for (int nd = 0; nd < 8; nd++) {
        int ccol = h * COH + nd * 8 + 2 * t;
        long r0q = q0 + mBase + g;
        unsigned hp, lp;
        split2h(o[nd][0] * inv0, o[nd][1] * inv0, hp, lp);
        *(unsigned*)&ath[r0q * CC + ccol] = hp;
        *(unsigned*)&atl[r0q * CC + ccol] = lp;
        split2h(o[nd][2] * inv1, o[nd][3] * inv1, hp, lp);
        *(unsigned*)&ath[(r0q + 8) * CC + ccol] = hp;
        *(unsigned*)&atl[(r0q + 8) * CC + ccol] = lp;
    }
}

// ---------------- launch ----------------
extern "C" void kernel_launch(void* const* d_in, const int* in_sizes, int n_in,
                              void* d_out, int out_size) {
    const float* x      = (const float*)d_in[0];
    const int*   ei     = (const int*)d_in[1];
    const float* gat_wl = (const float*)d_in[2];
    const float* gat_bl = (const float*)d_in[3];
    const float* gat_wr = (const float*)d_in[4];
    const float* gat_br = (const float*)d_in[5];
    const float* gat_at = (const float*)d_in[6];
    const float* gat_b  = (const float*)d_in[7];
    const float* in_w   = (const float*)d_in[8];
    const float* in_b   = (const float*)d_in[9];
    const float* out_w  = (const float*)d_in[10];
    const float* out_b  = (const float*)d_in[11];
    const float* ln1_g  = (const float*)d_in[12];
    const float* ln1_b  = (const float*)d_in[13];
    const float* ln2_g  = (const float*)d_in[14];
    const float* ln2_b  = (const float*)d_in[15];
    const float* ln3_g  = (const float*)d_in[16];
    const float* ln3_b  = (const float*)d_in[17];
    const float* w1     = (const float*)d_in[18];
    const float* b1     = (const float*)d_in[19];
    const float* w2     = (const float*)d_in[20];
    const float* b2     = (const float*)d_in[21];
    float* outp = (float*)d_out;

    float* gs = nullptr;
    cudaGetSymbolAddress((void**)&gs, g_scratch);
    __half* gh = nullptr;
    cudaGetSymbolAddress((void**)&gh, g_hf);

    cudaFuncSetAttribute(k_flash, cudaFuncAttributeMaxDynamicSharedMemorySize, FLASH_SMEM);
    cudaFuncSetAttribute(k_gemm<0>, cudaFuncAttributeMaxDynamicSharedMemorySize, G_SMEM);
    cudaFuncSetAttribute(k_gemm<1>, cudaFuncAttributeMaxDynamicSharedMemorySize, G_SMEM);
    cudaFuncSetAttribute(k_gemm<2>, cudaFuncAttributeMaxDynamicSharedMemorySize, G_SMEM);

    __half *Xh = gh + ZX,    *Xl = Xh + (long)NN*CC;
    __half *X1h = gh + ZX1,  *X1l = X1h + (long)NN*CC;
    __half *Ath = gh + ZATT, *Atl = Ath + (long)NN*CC;
    __half *X2h = gh + ZX2,  *X2l = X2h + (long)NN*CC;
    __half *Qh = gh + ZQKV,  *Ql = Qh + (long)NN*3*CC;
    __half *Fh = gh + ZFFN,  *Fl = Fh + (long)NN*4*CC;
    __half *WLh = gh + ZWL;
    __half *WRh = gh + ZWR;
    __half *INh = gh + ZIN;
    __half *OWh = gh + ZOW;
    __half *W1h = gh + ZW1;
    __half *W2h = gh + ZW2;

    // CSR build
    k_zero_deg<<<16, 256>>>();
    k_count<<<EE / 256, 256>>>(ei);
    k_scan<<<1, 1024>>>();
    k_scatter<<<EE / 256, 256>>>(ei);

    // pre-split x (hi+lo) + convert weights (hi only)
    k_split<<<(NN*CC/4 + 255)/256, 256>>>(x, Xh, Xl, NN*CC/4);
    k_half<<<(CC*CC/4 + 255)/256, 256>>>(gat_wl, WLh, CC*CC/4);
    k_half<<<(CC*CC/4 + 255)/256, 256>>>(gat_wr, WRh, CC*CC/4);
    k_half<<<(3*CC*CC/4 + 255)/256, 256>>>(in_w, INh, 3*CC*CC/4);
    k_half<<<(CC*CC/4 + 255)/256, 256>>>(out_w, OWh, CC*CC/4);
    k_half<<<(4*CC*CC/4 + 255)/256, 256>>>(w1, W1h, 4*CC*CC/4);
    k_half<<<(4*CC*CC/4 + 255)/256, 256>>>(w2, W2h, 4*CC*CC/4);

    // GAT projections (fp32 out)
    dim3 g512(CC / 64, NN / 128);
    k_gemm<0><<<g512, 256, G_SMEM>>>(Xh, Xl, WLh, gat_bl, gs + S_XL, 0, 0, CC, CC);
    k_gemm<0><<<g512, 256, G_SMEM>>>(Xh, Xl, WRh, gat_br, gs + S_XR, 0, 0, CC, CC);

    // GAT aggregation
    k_gat<<<NN, 256>>>(gs + S_XL, gs + S_XR, gat_at, gat_b, gs + S_HB);

    // x1 = LN(x + h_local), + split
    k_add_ln<<<NN, 256>>>(x, gs + S_HB, ln1_g, ln1_b, gs + S_X1, X1h, X1l);

    // QKV (split fp16 out; lo only for Q columns)
    dim3 gqkv(QKVW / 64, NN / 128);
    k_gemm<2><<<gqkv, 256, G_SMEM>>>(X1h, X1l, INh, in_b, 0, Qh, Ql, QKVW, CC);

    // flash attention (BM=128)
    dim3 gfl(NN / 128, HH);
    k_flash<<<gfl, 256, FLASH_SMEM>>>(Qh, Ql, Ath, Atl);

    // out proj (fp32 out)
    k_gemm<0><<<g512, 256, G_SMEM>>>(Ath, Atl, OWh, out_b, gs + S_HB, 0, 0, CC, CC);

    // x2 = LN(x1 + h_global), + split
    k_add_ln<<<NN, 256>>>(gs + S_X1, gs + S_HB, ln2_g, ln2_b, gs + S_X2, X2h, X2l);

    // FFN1 (GELU, split fp16 out)
    dim3 gffn1(4 * CC / 64, NN / 128);
    k_gemm<1><<<gffn1, 256, G_SMEM>>>(X2h, X2l, W1h, b1, 0, Fh, Fl, 4 * CC, CC);
    // FFN2 (fp32 out)
    k_gemm<0><<<g512, 256, G_SMEM>>>(Fh, Fl, W2h, b2, gs + S_HB, 0, 0, CC, 4 * CC);

    // out = LN(x2 + ffn)
    k_add_ln<<<NN, 256>>>(gs + S_X2, gs + S_HB, ln3_g, ln3_b, outp, 0, 0);
}

// round 14
// speedup vs baseline: 2.2971x; 1.1753x over previous
#include <cuda_runtime.h>
#include <cuda_fp16.h>
#include <stdint.h>
#include <math.h>

#define NN    4096
#define CC    512
#define HH    8
#define COH   64
#define EE    131072
#define QKVW  1536

// ---------------- fp32 scratch ----------------
#define S_XL   0L
#define S_XR   (S_XL  + (long)NN*CC)
#define S_HB   (S_XR  + (long)NN*CC)
#define S_X1   (S_HB  + (long)NN*CC)
#define S_X2   (S_X1  + (long)NN*CC)
#define S_TOT  (S_X2  + (long)NN*CC)
__device__ float g_scratch[S_TOT];

// ---------------- fp16 scratch ----------------
#define ZX    0L
#define ZX1   (ZX   + 1L*NN*CC)
#define ZATT  (ZX1  + 2L*NN*CC)
#define ZX2   (ZATT + 1L*NN*CC)
#define ZQKV  (ZX2  + 1L*NN*CC)
#define ZFFN  (ZQKV + 2L*NN*3*CC)
#define ZWL   (ZFFN + 1L*NN*4*CC)
#define ZWR   (ZWL  + 1L*CC*CC)
#define ZIN   (ZWR  + 1L*CC*CC)
#define ZOW   (ZIN  + 3L*CC*CC)
#define ZW1   (ZOW  + 1L*CC*CC)
#define ZW2   (ZW1  + 4L*CC*CC)
#define ZTOT  (ZW2  + 4L*CC*CC)
__device__ __half g_hf[ZTOT];

// int scratch
#define I_DEG  0
#define I_OFF  4096
#define I_POS  (I_OFF + 4097)
#define I_ESRC (I_POS + 4096)
__device__ int g_ints[I_ESRC + EE];

// ---------------- helpers ----------------
__device__ __forceinline__ void split2h(float x0, float x1, unsigned &hi, unsigned &lo) {
    __half h0 = __float2half_rn(x0);
    __half h1 = __float2half_rn(x1);
    float r0 = x0 - __half2float(h0);
    float r1 = x1 - __half2float(h1);
    __half l0 = __float2half_rn(r0);
    __half l1 = __float2half_rn(r1);
    hi = ((unsigned)__half_as_ushort(h1) << 16) | (unsigned)__half_as_ushort(h0);
    lo = ((unsigned)__half_as_ushort(l1) << 16) | (unsigned)__half_as_ushort(l0);
}

__device__ __forceinline__ unsigned pack2h(float x0, float x1) {
    return ((unsigned)__half_as_ushort(__float2half_rn(x1)) << 16) |
           (unsigned)__half_as_ushort(__float2half_rn(x0));
}

__device__ __forceinline__ void mma16816h(float* c, const unsigned* a, const unsigned* b) {
    asm volatile(
        "mma.sync.aligned.m16n8k16.row.col.f32.f16.f16.f32 "
        "{%0,%1,%2,%3}, {%4,%5,%6,%7}, {%8,%9}, {%0,%1,%2,%3};\n"
        : "+f"(c[0]), "+f"(c[1]), "+f"(c[2]), "+f"(c[3])
        : "r"(a[0]), "r"(a[1]), "r"(a[2]), "r"(a[3]), "r"(b[0]), "r"(b[1]));
}

__device__ __forceinline__ void ldsm4(unsigned &r0, unsigned &r1, unsigned &r2, unsigned &r3,
                                      uint32_t addr) {
    asm volatile("ldmatrix.sync.aligned.m8n8.x4.shared.b16 {%0,%1,%2,%3}, [%4];"
                 : "=r"(r0), "=r"(r1), "=r"(r2), "=r"(r3) : "r"(addr));
}

__device__ __forceinline__ void ldsm4t(unsigned &r0, unsigned &r1, unsigned &r2, unsigned &r3,
                                       uint32_t addr) {
    asm volatile("ldmatrix.sync.aligned.m8n8.x4.trans.shared.b16 {%0,%1,%2,%3}, [%4];"
                 : "=r"(r0), "=r"(r1), "=r"(r2), "=r"(r3) : "r"(addr));
}

__device__ __forceinline__ uint32_t smem_u32(const void* p) {
    uint32_t a;
    asm("{ .reg .u64 t; cvta.to.shared.u64 t, %1; cvt.u32.u64 %0, t; }" : "=r"(a) : "l"(p));
    return a;
}

#define CP16(dst, src) asm volatile("cp.async.cg.shared.global [%0], [%1], 16;" :: "r"(dst), "l"(src) : "memory")
#define CP_COMMIT()    asm volatile("cp.async.commit_group;" ::: "memory")
#define CP_WAIT0()     asm volatile("cp.async.wait_group 0;" ::: "memory")
#define CP_WAIT1()     asm volatile("cp.async.wait_group 1;" ::: "memory")

__device__ __forceinline__ float geluf(float v) {
    return 0.5f * v * (1.f + erff(v * 0.70710678118654752f));
}

// ---------------- CSR build ----------------
__global__ void k_zero_deg() {
    int i = blockIdx.x * blockDim.x + threadIdx.x;
    if (i < NN) g_ints[I_DEG + i] = 0;
}
__global__ void k_count(const int* __restrict__ ei) {
    int e = blockIdx.x * blockDim.x + threadIdx.x;
    if (e < EE) atomicAdd(&g_ints[I_DEG + (ei[EE + e] & (NN - 1))], 1);
}
__global__ void k_scan() {
    __shared__ int ws[32];
    int t = threadIdx.x;
    int v[4]; int tot = 0;
#pragma unroll
    for (int j = 0; j < 4; j++) { v[j] = g_ints[I_DEG + t*4 + j]; tot += v[j]; }
    int lane = t & 31, wid = t >> 5;
    int sc = tot;
#pragma unroll
    for (int o = 1; o < 32; o <<= 1) {
        int y = __shfl_up_sync(0xffffffffu, sc, o);
        if (lane >= o) sc += y;
    }
    if (lane == 31) ws[wid] = sc;
    __syncthreads();
    if (wid == 0) {
        int z = ws[lane];
#pragma unroll
        for (int o = 1; o < 32; o <<= 1) {
            int y = __shfl_up_sync(0xffffffffu, z, o);
            if (lane >= o) z += y;
        }
        ws[lane] = z;
    }
    __syncthreads();
    int excl = sc - tot + (wid ? ws[wid - 1] : 0);
    int run = excl;
#pragma unroll
    for (int j = 0; j < 4; j++) {
        g_ints[I_OFF + t*4 + j] = run;
        g_ints[I_POS + t*4 + j] = run;
        run += v[j];
    }
    if (t == 1023) g_ints[I_OFF + 4096] = run;
}
__global__ void k_scatter(const int* __restrict__ ei) {
    int e = blockIdx.x * blockDim.x + threadIdx.x;
    if (e < EE) {
        int d = ei[EE + e] & (NN - 1);
        int s = ei[e] & (NN - 1);
        int p = atomicAdd(&g_ints[I_POS + d], 1);
        if (p >= 0 && p < EE) g_ints[I_ESRC + p] = s;
    }
}

// ---------------- fp32 -> fp16 convert (hi only) ----------------
__global__ void k_half(const float* __restrict__ in, __half* __restrict__ hi, int n4) {
    int i = blockIdx.x * blockDim.x + threadIdx.x;
    if (i >= n4) return;
    float4 v = ((const float4*)in)[i];
    ((uint2*)hi)[i] = make_uint2(pack2h(v.x, v.y), pack2h(v.z, v.w));
}

// ---------------- mma.sync NT GEMM, LDSM + cp.async pipeline ----------------
// BM=128 BN=64 BK=32, 256 thr, 8 warps (4Mx2N). Double-buffered dynamic smem.
// SPLITA=1: A hi+lo (2-product). SPLITA=0: A hi only (1-product).
// EPI: 0 fp32 out; 1 GELU -> hi fp16 out; 2 bias -> hi (+ lo for n<CC) fp16 out.
#define G_SMEM1 (2 * 25600)
#define G_SMEM0 (2 * 15360)

template <int EPI, int SPLITA>
__global__ void __launch_bounds__(256) k_gemm(
    const __half* __restrict__ Ah, const __half* __restrict__ Al,
    const __half* __restrict__ Bh,
    const float* __restrict__ bias, float* __restrict__ Cf,
    __half* __restrict__ Ch, __half* __restrict__ Cl,
    int Nd, int K) {
    extern __shared__ __align__(16) unsigned gsm[];
    const int SIDE = SPLITA ? 25600 : 15360;
    const int BOFF = SPLITA ? 20480 : 10240;
    int tid = threadIdx.x;
    int lane = tid & 31, wid = tid >> 5;
    int wm = wid & 3, wn = wid >> 2;
    int mBase = wm * 32, nBase = wn * 32;
    int g = lane >> 2, t = lane & 3;
    int bm = blockIdx.y * 128, bn = blockIdx.x * 64;
    uint32_t smB = smem_u32(gsm);

    int rA0 = tid >> 2;
    int cA0 = (tid & 3) * 16;
    uint32_t dA0 = rA0 * 80 + cA0;
    uint32_t dA1 = dA0 + 64 * 80;
    const char* gA0h = (const char*)Ah + ((long)(bm + rA0) * K) * 2 + cA0;
    const char* gA1h = (const char*)Ah + ((long)(bm + rA0 + 64) * K) * 2 + cA0;
    const char* gA0l = SPLITA ? (const char*)Al + ((long)(bm + rA0) * K) * 2 + cA0 : 0;
    const char* gA1l = SPLITA ? (const char*)Al + ((long)(bm + rA0 + 64) * K) * 2 + cA0 : 0;
    const char* gB   = (const char*)Bh + ((long)(bn + rA0) * K) * 2 + cA0;

    uint32_t aFh = (mBase + (lane & 15)) * 80 + (lane >> 4) * 16;
    uint32_t aFl = 10240 + aFh;
    uint32_t bF  = BOFF + (nBase + 8 * (lane >> 4) + (lane & 7)) * 80 + ((lane >> 3) & 1) * 16;

    float c[2][4][4];
#pragma unroll
    for (int mi = 0; mi < 2; mi++)
#pragma unroll
        for (int ni = 0; ni < 4; ni++)
#pragma unroll
            for (int j = 0; j < 4; j++) c[mi][ni][j] = 0.f;

    int nch = K >> 5;
    {
        uint32_t bb = smB;
        CP16(bb + dA0, gA0h);
        CP16(bb + dA1, gA1h);
        if (SPLITA) {
            CP16(bb + 10240 + dA0, gA0l);
            CP16(bb + 10240 + dA1, gA1l);
        }
        CP16(bb + BOFF + dA0, gB);
    }
    CP_COMMIT();

    for (int cc = 0; cc < nch; cc++) {
        if (cc + 1 < nch) {
            long kb = (long)(cc + 1) * 64;
            uint32_t bb = smB + ((cc + 1) & 1) * SIDE;
            CP16(bb + dA0, gA0h + kb);
            CP16(bb + dA1, gA1h + kb);
            if (SPLITA) {
                CP16(bb + 10240 + dA0, gA0l + kb);
                CP16(bb + 10240 + dA1, gA1l + kb);
            }
            CP16(bb + BOFF + dA0, gB + kb);
            CP_COMMIT();
            CP_WAIT1();
        } else {
            CP_WAIT0();
        }
        __syncthreads();
        uint32_t bb = smB + (cc & 1) * SIDE;
#pragma unroll
        for (int ks = 0; ks < 2; ks++) {
            unsigned ah[2][4], al[2][4], bh[4][2];
#pragma unroll
            for (int mi = 0; mi < 2; mi++) {
                ldsm4(ah[mi][0], ah[mi][1], ah[mi][2], ah[mi][3], bb + aFh + mi * 1280 + ks * 32);
                if (SPLITA)
                    ldsm4(al[mi][0], al[mi][1], al[mi][2], al[mi][3], bb + aFl + mi * 1280 + ks * 32);
            }
#pragma unroll
            for (int p = 0; p < 2; p++) {
                ldsm4(bh[2*p][0], bh[2*p][1], bh[2*p+1][0], bh[2*p+1][1], bb + bF + p * 1280 + ks * 32);
            }
#pragma unroll
            for (int mi = 0; mi < 2; mi++)
#pragma unroll
                for (int ni = 0; ni < 4; ni++) {
                    if (SPLITA) mma16816h(c[mi][ni], al[mi], bh[ni]);
                    mma16816h(c[mi][ni], ah[mi], bh[ni]);
                }
        }
        __syncthreads();
    }

    // epilogue
#pragma unroll
    for (int mi = 0; mi < 2; mi++)
#pragma unroll
        for (int ni = 0; ni < 4; ni++) {
            int n0 = bn + nBase + ni * 8 + 2 * t;
            long r0 = bm + mBase + mi * 16 + g;
            float v0 = c[mi][ni][0] + bias[n0];
            float v1 = c[mi][ni][1] + bias[n0 + 1];
            float v2 = c[mi][ni][2] + bias[n0];
            float v3 = c[mi][ni][3] + bias[n0 + 1];
            if (EPI == 0) {
                Cf[r0 * Nd + n0]           = v0;
                Cf[r0 * Nd + n0 + 1]       = v1;
                Cf[(r0 + 8) * Nd + n0]     = v2;
                Cf[(r0 + 8) * Nd + n0 + 1] = v3;
            } else if (EPI == 1) {
                *(unsigned*)&Ch[r0 * Nd + n0]       = pack2h(geluf(v0), geluf(v1));
                *(unsigned*)&Ch[(r0 + 8) * Nd + n0] = pack2h(geluf(v2), geluf(v3));
            } else {
                bool wlo = (n0 < CC);   // QKV: only Q needs lo
                unsigned hp, lp;
                split2h(v0, v1, hp, lp);
                *(unsigned*)&Ch[r0 * Nd + n0] = hp;
                if (wlo) *(unsigned*)&Cl[r0 * Nd + n0] = lp;
                split2h(v2, v3, hp, lp);
                *(unsigned*)&Ch[(r0 + 8) * Nd + n0] = hp;
                if (wlo) *(unsigned*)&Cl[(r0 + 8) * Nd + n0] = lp;
            }
        }
}

// ---------------- GAT per-node online softmax aggregation (2-edge ILP) ----------------
__global__ void k_gat(const float* __restrict__ xl, const float* __restrict__ xr,
                      const float* __restrict__ att, const float* __restrict__ gbias,
                      float* __restrict__ outp) {
    int i = blockIdx.x;
    int w = threadIdx.x >> 5;
    int lane = threadIdx.x & 31;
    int c0 = lane, c1 = lane + 32;
    const float* xli = xl + (long)i * CC + w * COH;
    float xl0 = xli[c0], xl1 = xli[c1];
    float a0 = att[w * COH + c0], a1 = att[w * COH + c1];
    float m = -1e30f, l = 0.f, acc0 = 0.f, acc1 = 0.f;
    int beg = g_ints[I_OFF + i], end = g_ints[I_OFF + i + 1];
    int j = beg;
    for (; j + 2 <= end; j += 2) {
        int s1 = g_ints[I_ESRC + j];
        int s2 = g_ints[I_ESRC + j + 1];
        const float* x1p = xr + (long)s1 * CC + w * COH;
        const float* x2p = xr + (long)s2 * CC + w * COH;
        float x10 = x1p[c0], x11 = x1p[c1];
        float x20 = x2p[c0], x21 = x2p[c1];
        float e10 = xl0 + x10; e10 = (e10 > 0.f) ? e10 : 0.2f * e10;
        float e11 = xl1 + x11; e11 = (e11 > 0.f) ? e11 : 0.2f * e11;
        float e20 = xl0 + x20; e20 = (e20 > 0.f) ? e20 : 0.2f * e20;
        float e21 = xl1 + x21; e21 = (e21 > 0.f) ? e21 : 0.2f * e21;
        float p1 = e10 * a0 + e11 * a1;
        float p2 = e20 * a0 + e21 * a1;
#pragma unroll
        for (int o = 16; o; o >>= 1) {
            p1 += __shfl_xor_sync(0xffffffffu, p1, o);
            p2 += __shfl_xor_sync(0xffffffffu, p2, o);
        }
        float mn = fmaxf(m, fmaxf(p1, p2));
        float sc = __expf(m - mn);
        float w1 = __expf(p1 - mn);
        float w2 = __expf(p2 - mn);
        l = l * sc + w1 + w2;
        acc0 = acc0 * sc + x10 * w1 + x20 * w2;
        acc1 = acc1 * sc + x11 * w1 + x21 * w2;
        m = mn;
    }
    for (int jj = j; jj <= end; jj++) {
        int s = (jj < end) ? g_ints[I_ESRC + jj] : i;
        const float* xrs = xr + (long)s * CC + w * COH;
        float xr0 = xrs[c0], xr1 = xrs[c1];
        float e0 = xl0 + xr0; e0 = (e0 > 0.f) ? e0 : 0.2f * e0;
        float e1 = xl1 + xr1; e1 = (e1 > 0.f) ? e1 : 0.2f * e1;
        float p = e0 * a0 + e1 * a1;
#pragma unroll
        for (int o = 16; o; o >>= 1) p += __shfl_xor_sync(0xffffffffu, p, o);
        float mn = fmaxf(m, p);
        float sc = __expf(m - mn);
        float wg = __expf(p - mn);
        l = l * sc + wg;
        acc0 = acc0 * sc + xr0 * wg;
        acc1 = acc1 * sc + xr1 * wg;
        m = mn;
    }
    float inv = 1.f / l;
    outp[(long)i * CC + w * COH + c0] = acc0 * inv + gbias[w * COH + c0];
    outp[(long)i * CC + w * COH + c1] = acc1 * inv + gbias[w * COH + c1];
}

// ---------------- residual add + layernorm (+ optional fp16 hi / hi+lo out) ----------------
__global__ void k_add_ln(const float* __restrict__ x, const float* __restrict__ h,
                         const float* __restrict__ g, const float* __restrict__ b,
                         float* __restrict__ outp,
                         __half* __restrict__ oh, __half* __restrict__ ol) {
    int row = blockIdx.x;
    int t = threadIdx.x;
    __shared__ float sh[8];
    float v0 = x[(long)row * CC + t]       + h[(long)row * CC + t];
    float v1 = x[(long)row * CC + 256 + t] + h[(long)row * CC + 256 + t];
    float s = v0 + v1;
#pragma unroll
    for (int o = 16; o; o >>= 1) s += __shfl_xor_sync(0xffffffffu, s, o);
    if ((t & 31) == 0) sh[t >> 5] = s;
    __syncthreads();
    float tot = 0.f;
#pragma unroll
    for (int i = 0; i < 8; i++) tot += sh[i];
    float mu = tot * (1.f / 512.f);
    __syncthreads();
    float d0 = v0 - mu, d1 = v1 - mu;
    float q = d0 * d0 + d1 * d1;
#pragma unroll
    for (int o = 16; o; o >>= 1) q += __shfl_xor_sync(0xffffffffu, q, o);
    if ((t & 31) == 0) sh[t >> 5] = q;
    __syncthreads();
    float var = 0.f;
#pragma unroll
    for (int i = 0; i < 8; i++) var += sh[i];
    var *= (1.f / 512.f);
    float rstd = rsqrtf(var + 1e-5f);
    float y0 = d0 * rstd * g[t]       + b[t];
    float y1 = d1 * rstd * g[t + 256] + b[t + 256];
    outp[(long)row * CC + t]       = y0;
    outp[(long)row * CC + 256 + t] = y1;
    if (oh) {
        __half h0 = __float2half_rn(y0);
        __half h1 = __float2half_rn(y1);
        oh[(long)row * CC + t]       = h0;
        oh[(long)row * CC + 256 + t] = h1;
        if (ol) {
            ol[(long)row * CC + t]       = __float2half_rn(y0 - __half2float(h0));
            ol[(long)row * CC + 256 + t] = __float2half_rn(y1 - __half2float(h1));
        }
    }
}

// ---------------- flash attention: BM=128, cp.async K/V, trans-ldmatrix V, hi-only out ----------------
#define FQH 0
#define FQL 4608
#define FKB 9216
#define FVB 13824
#define FLASH_SMEM (18432 * 4)

__global__ void __launch_bounds__(256) k_flash(const __half* __restrict__ qkvh,
                                               const __half* __restrict__ qkvl,
                                               __half* __restrict__ ath) {
    extern __shared__ __align__(16) unsigned sm[];
    int h = blockIdx.y;
    int q0 = blockIdx.x * 128;
    int tid = threadIdx.x;
    int lane = tid & 31, wid = tid >> 5;
    int g = lane >> 2, t = lane & 3;
    int mBase = wid * 16;
    const float qs2 = 0.125f * 1.44269504088896f;
    uint32_t smB = smem_u32(sm);

    int r0 = tid >> 3;
    int j0 = (tid & 7) * 16;
    uint32_t dKV = r0 * 144 + j0;
    const char* gK = (const char*)qkvh + ((long)r0 * QKVW + CC + h * COH) * 2 + j0;
    const char* gV = (const char*)qkvh + ((long)r0 * QKVW + 2 * CC + h * COH) * 2 + j0;

    uint32_t qFh = smB + (mBase + (lane & 15)) * 144 + (lane >> 4) * 16;
    uint32_t qFl = qFh + FQL * 4;
    uint32_t kFo = (8 * (lane >> 4) + (lane & 7)) * 144 + ((lane >> 3) & 1) * 16;
    uint32_t vFo = (lane & 15) * 144 + (lane >> 4) * 16;

#pragma unroll
    for (int i = 0; i < 4; i++) {
        int cchunk = tid + i * 256;
        int r = cchunk >> 3;
        int q4 = cchunk & 7;
        long goff = (long)(q0 + r) * QKVW + h * COH + q4 * 8;
        *(uint4*)&sm[FQH + r * 36 + q4 * 4] = *(const uint4*)&qkvh[goff];
        *(uint4*)&sm[FQL + r * 36 + q4 * 4] = *(const uint4*)&qkvl[goff];
    }

    float m0 = -1e30f, m1 = -1e30f, l0s = 0.f, l1s = 0.f;
    float o[8][4];
#pragma unroll
    for (int nd = 0; nd < 8; nd++)
#pragma unroll
        for (int j = 0; j < 4; j++) o[nd][j] = 0.f;

    {
        uint32_t kb = smB + FKB * 4;
        uint32_t vb = smB + FVB * 4;
#pragma unroll
        for (int i = 0; i < 2; i++) {
            CP16(kb + dKV + i * (32 * 144), gK + (long)i * 32 * QKVW * 2);
            CP16(vb + dKV + i * (32 * 144), gV + (long)i * 32 * QKVW * 2);
        }
        CP_COMMIT();
    }

    for (int tt = 0; tt < 64; tt++) {
        if (tt + 1 < 64) {
            long go = (long)(tt + 1) * 64 * QKVW * 2;
            uint32_t kb = smB + (FKB + ((tt + 1) & 1) * 2304) * 4;
            uint32_t vb = smB + (FVB + ((tt + 1) & 1) * 2304) * 4;
#pragma unroll
            for (int i = 0; i < 2; i++) {
                CP16(kb + dKV + i * (32 * 144), gK + go + (long)i * 32 * QKVW * 2);
                CP16(vb + dKV + i * (32 * 144), gV + go + (long)i * 32 * QKVW * 2);
            }
            CP_COMMIT();
            CP_WAIT1();
        } else {
            CP_WAIT0();
        }
        __syncthreads();
        uint32_t kb = smB + (FKB + (tt & 1) * 2304) * 4;
        uint32_t vb = smB + (FVB + (tt & 1) * 2304) * 4;

        float s[8][4];
#pragma unroll
        for (int ni = 0; ni < 8; ni++)
#pragma unroll
            for (int j = 0; j < 4; j++) s[ni][j] = 0.f;

#pragma unroll
        for (int ks = 0; ks < 4; ks++) {
            unsigned ah[4], al[4];
            ldsm4(ah[0], ah[1], ah[2], ah[3], qFh + ks * 32);
            ldsm4(al[0], al[1], al[2], al[3], qFl + ks * 32);
#pragma unroll
            for (int p = 0; p < 4; p++) {
                unsigned bh[2][2];
                ldsm4(bh[0][0], bh[0][1], bh[1][0], bh[1][1], kb + kFo + p * 2304 + ks * 32);
                mma16816h(s[2*p],     al, bh[0]);
                mma16816h(s[2*p],     ah, bh[0]);
                mma16816h(s[2*p + 1], al, bh[1]);
                mma16816h(s[2*p + 1], ah, bh[1]);
            }
        }
#pragma unroll
        for (int ni = 0; ni < 8; ni++)
#pragma unroll
            for (int j = 0; j < 4; j++) s[ni][j] *= qs2;

        float mx0 = -1e30f, mx1 = -1e30f;
#pragma unroll
        for (int ni = 0; ni < 8; ni++) {
            mx0 = fmaxf(mx0, fmaxf(s[ni][0], s[ni][1]));
            mx1 = fmaxf(mx1, fmaxf(s[ni][2], s[ni][3]));
        }
        mx0 = fmaxf(mx0, __shfl_xor_sync(0xffffffffu, mx0, 1));
        mx0 = fmaxf(mx0, __shfl_xor_sync(0xffffffffu, mx0, 2));
        mx1 = fmaxf(mx1, __shfl_xor_sync(0xffffffffu, mx1, 1));
        mx1 = fmaxf(mx1, __shfl_xor_sync(0xffffffffu, mx1, 2));
        float mn0 = fmaxf(m0, mx0), mn1 = fmaxf(m1, mx1);
        float sc0 = exp2f(m0 - mn0), sc1 = exp2f(m1 - mn1);
        m0 = mn0; m1 = mn1;
        float sum0 = 0.f, sum1 = 0.f;
#pragma unroll
        for (int ni = 0; ni < 8; ni++) {
            s[ni][0] = exp2f(s[ni][0] - m0); sum0 += s[ni][0];
            s[ni][1] = exp2f(s[ni][1] - m0); sum0 += s[ni][1];
            s[ni][2] = exp2f(s[ni][2] - m1); sum1 += s[ni][2];
            s[ni][3] = exp2f(s[ni][3] - m1); sum1 += s[ni][3];
        }
        sum0 += __shfl_xor_sync(0xffffffffu, sum0, 1);
        sum0 += __shfl_xor_sync(0xffffffffu, sum0, 2);
        sum1 += __shfl_xor_sync(0xffffffffu, sum1, 1);
        sum1 += __shfl_xor_sync(0xffffffffu, sum1, 2);
        l0s = l0s * sc0 + sum0;
        l1s = l1s * sc1 + sum1;
#pragma unroll
        for (int nd = 0; nd < 8; nd++) {
            o[nd][0] *= sc0; o[nd][1] *= sc0;
            o[nd][2] *= sc1; o[nd][3] *= sc1;
        }

#pragma unroll
        for (int ks = 0; ks < 4; ks++) {
            unsigned ph[4];
            ph[0] = pack2h(s[2*ks][0],   s[2*ks][1]);
            ph[1] = pack2h(s[2*ks][2],   s[2*ks][3]);
            ph[2] = pack2h(s[2*ks+1][0], s[2*ks+1][1]);
            ph[3] = pack2h(s[2*ks+1][2], s[2*ks+1][3]);
#pragma unroll
            for (int p = 0; p < 4; p++) {
                unsigned bh[2][2];
                ldsm4t(bh[0][0], bh[0][1], bh[1][0], bh[1][1], vb + vFo + ks * 2304 + p * 32);
                mma16816h(o[2*p],     ph, bh[0]);
                mma16816h(o[2*p + 1], ph, bh[1]);
            }
        }
        __syncthreads();
    }

    float inv0 = 1.f / l0s, inv1 = 1.f / l1s;
#pragma unroll
    for (int nd = 0; nd < 8; nd++) {
        int ccol = h * COH + nd * 8 + 2 * t;
        long r0q = q0 + mBase + g;
        *(unsigned*)&ath[r0q * CC + ccol]       = pack2h(o[nd][0] * inv0, o[nd][1] * inv0);
        *(unsigned*)&ath[(r0q + 8) * CC + ccol] = pack2h(o[nd][2] * inv1, o[nd][3] * inv1);
    }
}

// ---------------- launch ----------------
extern "C" void kernel_launch(void* const* d_in, const int* in_sizes, int n_in,
                              void* d_out, int out_size) {
    const float* x      = (const float*)d_in[0];
    const int*   ei     = (const int*)d_in[1];
    const float* gat_wl = (const float*)d_in[2];
    const float* gat_bl = (const float*)d_in[3];
    const float* gat_wr = (const float*)d_in[4];
    const float* gat_br = (const float*)d_in[5];
    const float* gat_at = (const float*)d_in[6];
    const float* gat_b  = (const float*)d_in[7];
    const float* in_w   = (const float*)d_in[8];
    const float* in_b   = (const float*)d_in[9];
    const float* out_w  = (const float*)d_in[10];
    const float* out_b  = (const float*)d_in[11];
    const float* ln1_g  = (const float*)d_in[12];
    const float* ln1_b  = (const float*)d_in[13];
    const float* ln2_g  = (const float*)d_in[14];
    const float* ln2_b  = (const float*)d_in[15];
    const float* ln3_g  = (const float*)d_in[16];
    const float* ln3_b  = (const float*)d_in[17];
    const float* w1     = (const float*)d_in[18];
    const float* b1     = (const float*)d_in[19];
    const float* w2     = (const float*)d_in[20];
    const float* b2     = (const float*)d_in[21];
    float* outp = (float*)d_out;

    float* gs = nullptr;
    cudaGetSymbolAddress((void**)&gs, g_scratch);
    __half* gh = nullptr;
    cudaGetSymbolAddress((void**)&gh, g_hf);

    cudaFuncSetAttribute(k_flash, cudaFuncAttributeMaxDynamicSharedMemorySize, FLASH_SMEM);
    cudaFuncSetAttribute((k_gemm<0,0>), cudaFuncAttributeMaxDynamicSharedMemorySize, G_SMEM0);
    cudaFuncSetAttribute((k_gemm<1,0>), cudaFuncAttributeMaxDynamicSharedMemorySize, G_SMEM0);
    cudaFuncSetAttribute((k_gemm<2,1>), cudaFuncAttributeMaxDynamicSharedMemorySize, G_SMEM1);

    __half *Xh = gh + ZX;
    __half *X1h = gh + ZX1,  *X1l = X1h + (long)NN*CC;
    __half *Ath = gh + ZATT;
    __half *X2h = gh + ZX2;
    __half *Qh = gh + ZQKV,  *Ql = Qh + (long)NN*3*CC;
    __half *Fh = gh + ZFFN;
    __half *WLh = gh + ZWL;
    __half *WRh = gh + ZWR;
    __half *INh = gh + ZIN;
    __half *OWh = gh + ZOW;
    __half *W1h = gh + ZW1;
    __half *W2h = gh + ZW2;

    // CSR build
    k_zero_deg<<<16, 256>>>();
    k_count<<<EE / 256, 256>>>(ei);
    k_scan<<<1, 1024>>>();
    k_scatter<<<EE / 256, 256>>>(ei);

    // convert x + weights (hi only)
    k_half<<<(NN*CC/4 + 255)/256, 256>>>(x, Xh, NN*CC/4);
    k_half<<<(CC*CC/4 + 255)/256, 256>>>(gat_wl, WLh, CC*CC/4);
    k_half<<<(CC*CC/4 + 255)/256, 256>>>(gat_wr, WRh, CC*CC/4);
    k_half<<<(3*CC*CC/4 + 255)/256, 256>>>(in_w, INh, 3*CC*CC/4);
    k_half<<<(CC*CC/4 + 255)/256, 256>>>(out_w, OWh, CC*CC/4);
    k_half<<<(4*CC*CC/4 + 255)/256, 256>>>(w1, W1h, 4*CC*CC/4);
    k_half<<<(4*CC*CC/4 + 255)/256, 256>>>(w2, W2h, 4*CC*CC/4);

    // GAT projections (1-product, fp32 out)
    dim3 g512(CC / 64, NN / 128);
    k_gemm<0,0><<<g512, 256, G_SMEM0>>>(Xh, 0, WLh, gat_bl, gs + S_XL, 0, 0, CC, CC);
    k_gemm<0,0><<<g512, 256, G_SMEM0>>>(Xh, 0, WRh, gat_br, gs + S_XR, 0, 0, CC, CC);

    // GAT aggregation
    k_gat<<<NN, 256>>>(gs + S_XL, gs + S_XR, gat_at, gat_b, gs + S_HB);

    // x1 = LN(x + h_local), + hi/lo split (QKV input needs 2-product)
    k_add_ln<<<NN, 256>>>(x, gs + S_HB, ln1_g, ln1_b, gs + S_X1, X1h, X1l);

    // QKV (2-product; hi out + lo for Q cols)
    dim3 gqkv(QKVW / 64, NN / 128);
    k_gemm<2,1><<<gqkv, 256, G_SMEM1>>>(X1h, X1l, INh, in_b, 0, Qh, Ql, QKVW, CC);

    // flash attention (BM=128, hi-only out)
    dim3 gfl(NN / 128, HH);
    k_flash<<<gfl, 256, FLASH_SMEM>>>(Qh, Ql, Ath);

    // out proj (1-product, fp32 out)
    k_gemm<0,0><<<g512, 256, G_SMEM0>>>(Ath, 0, OWh, out_b, gs + S_HB, 0, 0, CC, CC);

    // x2 = LN(x1 + h_global), hi only
    k_add_ln<<<NN, 256>>>(gs + S_X1, gs + S_HB, ln2_g, ln2_b, gs + S_X2, X2h, 0);

    // FFN1 (1-product, GELU, hi out)
    dim3 gffn1(4 * CC / 64, NN / 128);
    k_gemm<1,0><<<gffn1, 256, G_SMEM0>>>(X2h, 0, W1h, b1, 0, Fh, 0, 4 * CC, CC);
    // FFN2 (1-product, fp32 out)
    k_gemm<0,0><<<g512, 256, G_SMEM0>>>(Fh, 0, W2h, b2, gs + S_HB, 0, 0, CC, 4 * CC);

    // out = LN(x2 + ffn)
    k_add_ln<<<NN, 256>>>(gs + S_X2, gs + S_HB, ln3_g, ln3_b, outp, 0, 0);
}

// round 15
// speedup vs baseline: 2.5656x; 1.1169x over previous
#include <cuda_runtime.h>
#include <cuda_fp16.h>
#include <stdint.h>
#include <math.h>

#define NN    4096
#define CC    512
#define HH    8
#define COH   64
#define EE    131072
#define QKVW  1536

// ---------------- fp32 scratch ----------------
#define S_XL   0L
#define S_XR   (S_XL  + (long)NN*CC)
#define S_HB   (S_XR  + (long)NN*CC)
#define S_X1   (S_HB  + (long)NN*CC)
#define S_X2   (S_X1  + (long)NN*CC)
#define S_TOT  (S_X2  + (long)NN*CC)
__device__ float g_scratch[S_TOT];

// ---------------- fp16 scratch (all hi-only now) ----------------
#define ZX    0L
#define ZX1   (ZX   + 1L*NN*CC)
#define ZATT  (ZX1  + 1L*NN*CC)
#define ZX2   (ZATT + 1L*NN*CC)
#define ZQKV  (ZX2  + 1L*NN*CC)
#define ZFFN  (ZQKV + 1L*NN*3*CC)
#define ZWL   (ZFFN + 1L*NN*4*CC)
#define ZWR   (ZWL  + 1L*CC*CC)
#define ZIN   (ZWR  + 1L*CC*CC)
#define ZOW   (ZIN  + 3L*CC*CC)
#define ZW1   (ZOW  + 1L*CC*CC)
#define ZW2   (ZW1  + 4L*CC*CC)
#define ZTOT  (ZW2  + 4L*CC*CC)
__device__ __half g_hf[ZTOT];

// int scratch
#define I_DEG  0
#define I_OFF  4096
#define I_POS  (I_OFF + 4097)
#define I_ESRC (I_POS + 4096)
__device__ int g_ints[I_ESRC + EE];

// ---------------- helpers ----------------
__device__ __forceinline__ unsigned pack2h(float x0, float x1) {
    return ((unsigned)__half_as_ushort(__float2half_rn(x1)) << 16) |
           (unsigned)__half_as_ushort(__float2half_rn(x0));
}

__device__ __forceinline__ void mma16816h(float* c, const unsigned* a, const unsigned* b) {
    asm volatile(
        "mma.sync.aligned.m16n8k16.row.col.f32.f16.f16.f32 "
        "{%0,%1,%2,%3}, {%4,%5,%6,%7}, {%8,%9}, {%0,%1,%2,%3};\n"
        : "+f"(c[0]), "+f"(c[1]), "+f"(c[2]), "+f"(c[3])
        : "r"(a[0]), "r"(a[1]), "r"(a[2]), "r"(a[3]), "r"(b[0]), "r"(b[1]));
}

__device__ __forceinline__ void ldsm4(unsigned &r0, unsigned &r1, unsigned &r2, unsigned &r3,
                                      uint32_t addr) {
    asm volatile("ldmatrix.sync.aligned.m8n8.x4.shared.b16 {%0,%1,%2,%3}, [%4];"
                 : "=r"(r0), "=r"(r1), "=r"(r2), "=r"(r3) : "r"(addr));
}

__device__ __forceinline__ void ldsm4t(unsigned &r0, unsigned &r1, unsigned &r2, unsigned &r3,
                                       uint32_t addr) {
    asm volatile("ldmatrix.sync.aligned.m8n8.x4.trans.shared.b16 {%0,%1,%2,%3}, [%4];"
                 : "=r"(r0), "=r"(r1), "=r"(r2), "=r"(r3) : "r"(addr));
}

__device__ __forceinline__ uint32_t smem_u32(const void* p) {
    uint32_t a;
    asm("{ .reg .u64 t; cvta.to.shared.u64 t, %1; cvt.u32.u64 %0, t; }" : "=r"(a) : "l"(p));
    return a;
}

#define CP16(dst, src) asm volatile("cp.async.cg.shared.global [%0], [%1], 16;" :: "r"(dst), "l"(src) : "memory")
#define CP_COMMIT()    asm volatile("cp.async.commit_group;" ::: "memory")
#define CP_WAIT0()     asm volatile("cp.async.wait_group 0;" ::: "memory")
#define CP_WAIT1()     asm volatile("cp.async.wait_group 1;" ::: "memory")

__device__ __forceinline__ float geluf(float v) {
    return 0.5f * v * (1.f + erff(v * 0.70710678118654752f));
}

// ---------------- CSR build ----------------
__global__ void k_zero_deg() {
    int i = blockIdx.x * blockDim.x + threadIdx.x;
    if (i < NN) g_ints[I_DEG + i] = 0;
}
__global__ void k_count(const int* __restrict__ ei) {
    int e = blockIdx.x * blockDim.x + threadIdx.x;
    if (e < EE) atomicAdd(&g_ints[I_DEG + (ei[EE + e] & (NN - 1))], 1);
}
__global__ void k_scan() {
    __shared__ int ws[32];
    int t = threadIdx.x;
    int v[4]; int tot = 0;
#pragma unroll
    for (int j = 0; j < 4; j++) { v[j] = g_ints[I_DEG + t*4 + j]; tot += v[j]; }
    int lane = t & 31, wid = t >> 5;
    int sc = tot;
#pragma unroll
    for (int o = 1; o < 32; o <<= 1) {
        int y = __shfl_up_sync(0xffffffffu, sc, o);
        if (lane >= o) sc += y;
    }
    if (lane == 31) ws[wid] = sc;
    __syncthreads();
    if (wid == 0) {
        int z = ws[lane];
#pragma unroll
        for (int o = 1; o < 32; o <<= 1) {
            int y = __shfl_up_sync(0xffffffffu, z, o);
            if (lane >= o) z += y;
        }
        ws[lane] = z;
    }
    __syncthreads();
    int excl = sc - tot + (wid ? ws[wid - 1] : 0);
    int run = excl;
#pragma unroll
    for (int j = 0; j < 4; j++) {
        g_ints[I_OFF + t*4 + j] = run;
        g_ints[I_POS + t*4 + j] = run;
        run += v[j];
    }
    if (t == 1023) g_ints[I_OFF + 4096] = run;
}
__global__ void k_scatter(const int* __restrict__ ei) {
    int e = blockIdx.x * blockDim.x + threadIdx.x;
    if (e < EE) {
        int d = ei[EE + e] & (NN - 1);
        int s = ei[e] & (NN - 1);
        int p = atomicAdd(&g_ints[I_POS + d], 1);
        if (p >= 0 && p < EE) g_ints[I_ESRC + p] = s;
    }
}

// ---------------- fp32 -> fp16 convert ----------------
__global__ void k_half(const float* __restrict__ in, __half* __restrict__ hi, int n4) {
    int i = blockIdx.x * blockDim.x + threadIdx.x;
    if (i >= n4) return;
    float4 v = ((const float4*)in)[i];
    ((uint2*)hi)[i] = make_uint2(pack2h(v.x, v.y), pack2h(v.z, v.w));
}

// ---------------- mma.sync NT GEMM (1-product fp16), LDSM + cp.async pipeline ----------------
// BM=128 BN=64 BK=32, 256 thr, 8 warps (4Mx2N). Double-buffered dynamic smem.
// EPI: 0 fp32 out; 1 GELU -> hi fp16 out; 3 bias -> hi fp16 out.
#define G_SMEM0 (2 * 15360)

template <int EPI>
__global__ void __launch_bounds__(256) k_gemm(
    const __half* __restrict__ Ah, const __half* __restrict__ Bh,
    const float* __restrict__ bias, float* __restrict__ Cf,
    __half* __restrict__ Ch, int Nd, int K) {
    extern __shared__ __align__(16) unsigned gsm[];
    const int SIDE = 15360;
    const int BOFF = 10240;
    int tid = threadIdx.x;
    int lane = tid & 31, wid = tid >> 5;
    int wm = wid & 3, wn = wid >> 2;
    int mBase = wm * 32, nBase = wn * 32;
    int g = lane >> 2, t = lane & 3;
    int bm = blockIdx.y * 128, bn = blockIdx.x * 64;
    uint32_t smB = smem_u32(gsm);

    int rA0 = tid >> 2;
    int cA0 = (tid & 3) * 16;
    uint32_t dA0 = rA0 * 80 + cA0;
    uint32_t dA1 = dA0 + 64 * 80;
    const char* gA0h = (const char*)Ah + ((long)(bm + rA0) * K) * 2 + cA0;
    const char* gA1h = (const char*)Ah + ((long)(bm + rA0 + 64) * K) * 2 + cA0;
    const char* gB   = (const char*)Bh + ((long)(bn + rA0) * K) * 2 + cA0;

    uint32_t aFh = (mBase + (lane & 15)) * 80 + (lane >> 4) * 16;
    uint32_t bF  = BOFF + (nBase + 8 * (lane >> 4) + (lane & 7)) * 80 + ((lane >> 3) & 1) * 16;

    float c[2][4][4];
#pragma unroll
    for (int mi = 0; mi < 2; mi++)
#pragma unroll
        for (int ni = 0; ni < 4; ni++)
#pragma unroll
            for (int j = 0; j < 4; j++) c[mi][ni][j] = 0.f;

    int nch = K >> 5;
    {
        uint32_t bb = smB;
        CP16(bb + dA0, gA0h);
        CP16(bb + dA1, gA1h);
        CP16(bb + BOFF + dA0, gB);
    }
    CP_COMMIT();

    for (int cc = 0; cc < nch; cc++) {
        if (cc + 1 < nch) {
            long kb = (long)(cc + 1) * 64;
            uint32_t bb = smB + ((cc + 1) & 1) * SIDE;
            CP16(bb + dA0, gA0h + kb);
            CP16(bb + dA1, gA1h + kb);
            CP16(bb + BOFF + dA0, gB + kb);
            CP_COMMIT();
            CP_WAIT1();
        } else {
            CP_WAIT0();
        }
        __syncthreads();
        uint32_t bb = smB + (cc & 1) * SIDE;
#pragma unroll
        for (int ks = 0; ks < 2; ks++) {
            unsigned ah[2][4], bh[4][2];
#pragma unroll
            for (int mi = 0; mi < 2; mi++)
                ldsm4(ah[mi][0], ah[mi][1], ah[mi][2], ah[mi][3], bb + aFh + mi * 1280 + ks * 32);
#pragma unroll
            for (int p = 0; p < 2; p++)
                ldsm4(bh[2*p][0], bh[2*p][1], bh[2*p+1][0], bh[2*p+1][1], bb + bF + p * 1280 + ks * 32);
#pragma unroll
            for (int mi = 0; mi < 2; mi++)
#pragma unroll
                for (int ni = 0; ni < 4; ni++)
                    mma16816h(c[mi][ni], ah[mi], bh[ni]);
        }
        __syncthreads();
    }

    // epilogue
#pragma unroll
    for (int mi = 0; mi < 2; mi++)
#pragma unroll
        for (int ni = 0; ni < 4; ni++) {
            int n0 = bn + nBase + ni * 8 + 2 * t;
            long r0 = bm + mBase + mi * 16 + g;
            float v0 = c[mi][ni][0] + bias[n0];
            float v1 = c[mi][ni][1] + bias[n0 + 1];
            float v2 = c[mi][ni][2] + bias[n0];
            float v3 = c[mi][ni][3] + bias[n0 + 1];
            if (EPI == 0) {
                Cf[r0 * Nd + n0]           = v0;
                Cf[r0 * Nd + n0 + 1]       = v1;
                Cf[(r0 + 8) * Nd + n0]     = v2;
                Cf[(r0 + 8) * Nd + n0 + 1] = v3;
            } else if (EPI == 1) {
                *(unsigned*)&Ch[r0 * Nd + n0]       = pack2h(geluf(v0), geluf(v1));
                *(unsigned*)&Ch[(r0 + 8) * Nd + n0] = pack2h(geluf(v2), geluf(v3));
            } else {
                *(unsigned*)&Ch[r0 * Nd + n0]       = pack2h(v0, v1);
                *(unsigned*)&Ch[(r0 + 8) * Nd + n0] = pack2h(v2, v3);
            }
        }
}

// ---------------- GAT per-node online softmax aggregation (2-edge ILP) ----------------
__global__ void k_gat(const float* __restrict__ xl, const float* __restrict__ xr,
                      const float* __restrict__ att, const float* __restrict__ gbias,
                      float* __restrict__ outp) {
    int i = blockIdx.x;
    int w = threadIdx.x >> 5;
    int lane = threadIdx.x & 31;
    int c0 = lane, c1 = lane + 32;
    const float* xli = xl + (long)i * CC + w * COH;
    float xl0 = xli[c0], xl1 = xli[c1];
    float a0 = att[w * COH + c0], a1 = att[w * COH + c1];
    float m = -1e30f, l = 0.f, acc0 = 0.f, acc1 = 0.f;
    int beg = g_ints[I_OFF + i], end = g_ints[I_OFF + i + 1];
    int j = beg;
    for (; j + 2 <= end; j += 2) {
        int s1 = g_ints[I_ESRC + j];
        int s2 = g_ints[I_ESRC + j + 1];
        const float* x1p = xr + (long)s1 * CC + w * COH;
        const float* x2p = xr + (long)s2 * CC + w * COH;
        float x10 = x1p[c0], x11 = x1p[c1];
        float x20 = x2p[c0], x21 = x2p[c1];
        float e10 = xl0 + x10; e10 = (e10 > 0.f) ? e10 : 0.2f * e10;
        float e11 = xl1 + x11; e11 = (e11 > 0.f) ? e11 : 0.2f * e11;
        float e20 = xl0 + x20; e20 = (e20 > 0.f) ? e20 : 0.2f * e20;
        float e21 = xl1 + x21; e21 = (e21 > 0.f) ? e21 : 0.2f * e21;
        float p1 = e10 * a0 + e11 * a1;
        float p2 = e20 * a0 + e21 * a1;
#pragma unroll
        for (int o = 16; o; o >>= 1) {
            p1 += __shfl_xor_sync(0xffffffffu, p1, o);
            p2 += __shfl_xor_sync(0xffffffffu, p2, o);
        }
        float mn = fmaxf(m, fmaxf(p1, p2));
        float sc = __expf(m - mn);
        float w1 = __expf(p1 - mn);
        float w2 = __expf(p2 - mn);
        l = l * sc + w1 + w2;
        acc0 = acc0 * sc + x10 * w1 + x20 * w2;
        acc1 = acc1 * sc + x11 * w1 + x21 * w2;
        m = mn;
    }
    for (int jj = j; jj <= end; jj++) {
        int s = (jj < end) ? g_ints[I_ESRC + jj] : i;
        const float* xrs = xr + (long)s * CC + w * COH;
        float xr0 = xrs[c0], xr1 = xrs[c1];
        float e0 = xl0 + xr0; e0 = (e0 > 0.f) ? e0 : 0.2f * e0;
        float e1 = xl1 + xr1; e1 = (e1 > 0.f) ? e1 : 0.2f * e1;
        float p = e0 * a0 + e1 * a1;
#pragma unroll
        for (int o = 16; o; o >>= 1) p += __shfl_xor_sync(0xffffffffu, p, o);
        float mn = fmaxf(m, p);
        float sc = __expf(m - mn);
        float wg = __expf(p - mn);
        l = l * sc + wg;
        acc0 = acc0 * sc + xr0 * wg;
        acc1 = acc1 * sc + xr1 * wg;
        m = mn;
    }
    float inv = 1.f / l;
    outp[(long)i * CC + w * COH + c0] = acc0 * inv + gbias[w * COH + c0];
    outp[(long)i * CC + w * COH + c1] = acc1 * inv + gbias[w * COH + c1];
}

// ---------------- residual add + layernorm (+ optional fp16 hi out) ----------------
__global__ void k_add_ln(const float* __restrict__ x, const float* __restrict__ h,
                         const float* __restrict__ g, const float* __restrict__ b,
                         float* __restrict__ outp, __half* __restrict__ oh) {
    int row = blockIdx.x;
    int t = threadIdx.x;
    __shared__ float sh[8];
    float v0 = x[(long)row * CC + t]       + h[(long)row * CC + t];
    float v1 = x[(long)row * CC + 256 + t] + h[(long)row * CC + 256 + t];
    float s = v0 + v1;
#pragma unroll
    for (int o = 16; o; o >>= 1) s += __shfl_xor_sync(0xffffffffu, s, o);
    if ((t & 31) == 0) sh[t >> 5] = s;
    __syncthreads();
    float tot = 0.f;
#pragma unroll
    for (int i = 0; i < 8; i++) tot += sh[i];
    float mu = tot * (1.f / 512.f);
    __syncthreads();
    float d0 = v0 - mu, d1 = v1 - mu;
    float q = d0 * d0 + d1 * d1;
#pragma unroll
    for (int o = 16; o; o >>= 1) q += __shfl_xor_sync(0xffffffffu, q, o);
    if ((t & 31) == 0) sh[t >> 5] = q;
    __syncthreads();
    float var = 0.f;
#pragma unroll
    for (int i = 0; i < 8; i++) var += sh[i];
    var *= (1.f / 512.f);
    float rstd = rsqrtf(var + 1e-5f);
    float y0 = d0 * rstd * g[t]       + b[t];
    float y1 = d1 * rstd * g[t + 256] + b[t + 256];
    outp[(long)row * CC + t]       = y0;
    outp[(long)row * CC + 256 + t] = y1;
    if (oh) {
        oh[(long)row * CC + t]       = __float2half_rn(y0);
        oh[(long)row * CC + 256 + t] = __float2half_rn(y1);
    }
}

// ---------------- flash attention: BM=128, hi-only everything ----------------
// smem (uint units, row stride 36 = 144B): Qh 0, K bufs 4608 + b*2304, V bufs 9216 + b*2304
#define FQH 0
#define FKB 4608
#define FVB 9216
#define FLASH_SMEM (13824 * 4)

__global__ void __launch_bounds__(256) k_flash(const __half* __restrict__ qkvh,
                                               __half* __restrict__ ath) {
    extern __shared__ __align__(16) unsigned sm[];
    int h = blockIdx.y;
    int q0 = blockIdx.x * 128;
    int tid = threadIdx.x;
    int lane = tid & 31, wid = tid >> 5;
    int g = lane >> 2, t = lane & 3;
    int mBase = wid * 16;
    const float qs2 = 0.125f * 1.44269504088896f;
    uint32_t smB = smem_u32(sm);

    int r0 = tid >> 3;
    int j0 = (tid & 7) * 16;
    uint32_t dKV = r0 * 144 + j0;
    const char* gK = (const char*)qkvh + ((long)r0 * QKVW + CC + h * COH) * 2 + j0;
    const char* gV = (const char*)qkvh + ((long)r0 * QKVW + 2 * CC + h * COH) * 2 + j0;

    uint32_t qFh = smB + (mBase + (lane & 15)) * 144 + (lane >> 4) * 16;
    uint32_t kFo = (8 * (lane >> 4) + (lane & 7)) * 144 + ((lane >> 3) & 1) * 16;
    uint32_t vFo = (lane & 15) * 144 + (lane >> 4) * 16;

    // Q tile load (128 rows, hi)
#pragma unroll
    for (int i = 0; i < 2; i++) {
        int cchunk = tid + i * 256;
        int r = cchunk >> 2;
        int q8 = (cchunk & 3) * 8;     // 8 halves = 16B; 2 chunks of 16B per 64-half... careful
        // 128 rows x 64 halves = 8192 halves = 1024 x uint4; 256 thr x 4 iters of 1... use 4 iters
    }
    // simpler: 1024 uint4 chunks, 256 threads, 4 each
#pragma unroll
    for (int i = 0; i < 4; i++) {
        int cchunk = tid + i * 256;
        int r = cchunk >> 3;
        int q4 = cchunk & 7;
        if (q4 < 8) {
            long goff = (long)(q0 + r) * QKVW + h * COH + q4 * 8;
            *(uint4*)&sm[FQH + r * 36 + q4 * 4] = *(const uint4*)&qkvh[goff];
        }
    }

    float m0 = -1e30f, m1 = -1e30f, l0s = 0.f, l1s = 0.f;
    float o[8][4];
#pragma unroll
    for (int nd = 0; nd < 8; nd++)
#pragma unroll
        for (int j = 0; j < 4; j++) o[nd][j] = 0.f;

    {
        uint32_t kb = smB + FKB * 4;
        uint32_t vb = smB + FVB * 4;
#pragma unroll
        for (int i = 0; i < 2; i++) {
            CP16(kb + dKV + i * (32 * 144), gK + (long)i * 32 * QKVW * 2);
            CP16(vb + dKV + i * (32 * 144), gV + (long)i * 32 * QKVW * 2);
        }
        CP_COMMIT();
    }

    for (int tt = 0; tt < 64; tt++) {
        if (tt + 1 < 64) {
            long go = (long)(tt + 1) * 64 * QKVW * 2;
            uint32_t kb = smB + (FKB + ((tt + 1) & 1) * 2304) * 4;
            uint32_t vb = smB + (FVB + ((tt + 1) & 1) * 2304) * 4;
#pragma unroll
            for (int i = 0; i < 2; i++) {
                CP16(kb + dKV + i * (32 * 144), gK + go + (long)i * 32 * QKVW * 2);
                CP16(vb + dKV + i * (32 * 144), gV + go + (long)i * 32 * QKVW * 2);
            }
            CP_COMMIT();
            CP_WAIT1();
        } else {
            CP_WAIT0();
        }
        __syncthreads();
        uint32_t kb = smB + (FKB + (tt & 1) * 2304) * 4;
        uint32_t vb = smB + (FVB + (tt & 1) * 2304) * 4;

        // S = Q K^T (1-product)
        float s[8][4];
#pragma unroll
        for (int ni = 0; ni < 8; ni++)
#pragma unroll
            for (int j = 0; j < 4; j++) s[ni][j] = 0.f;

#pragma unroll
        for (int ks = 0; ks < 4; ks++) {
            unsigned ah[4];
            ldsm4(ah[0], ah[1], ah[2], ah[3], qFh + ks * 32);
#pragma unroll
            for (int p = 0; p < 4; p++) {
                unsigned bh[2][2];
                ldsm4(bh[0][0], bh[0][1], bh[1][0], bh[1][1], kb + kFo + p * 2304 + ks * 32);
                mma16816h(s[2*p],     ah, bh[0]);
                mma16816h(s[2*p + 1], ah, bh[1]);
            }
        }
#pragma unroll
        for (int ni = 0; ni < 8; ni++)
#pragma unroll
            for (int j = 0; j < 4; j++) s[ni][j] *= qs2;

        // online softmax (base-2)
        float mx0 = -1e30f, mx1 = -1e30f;
#pragma unroll
        for (int ni = 0; ni < 8; ni++) {
            mx0 = fmaxf(mx0, fmaxf(s[ni][0], s[ni][1]));
            mx1 = fmaxf(mx1, fmaxf(s[ni][2], s[ni][3]));
        }
        mx0 = fmaxf(mx0, __shfl_xor_sync(0xffffffffu, mx0, 1));
        mx0 = fmaxf(mx0, __shfl_xor_sync(0xffffffffu, mx0, 2));
        mx1 = fmaxf(mx1, __shfl_xor_sync(0xffffffffu, mx1, 1));
        mx1 = fmaxf(mx1, __shfl_xor_sync(0xffffffffu, mx1, 2));
        float mn0 = fmaxf(m0, mx0), mn1 = fmaxf(m1, mx1);
        float sc0 = exp2f(m0 - mn0), sc1 = exp2f(m1 - mn1);
        m0 = mn0; m1 = mn1;
        float sum0 = 0.f, sum1 = 0.f;
#pragma unroll
        for (int ni = 0; ni < 8; ni++) {
            s[ni][0] = exp2f(s[ni][0] - m0); sum0 += s[ni][0];
            s[ni][1] = exp2f(s[ni][1] - m0); sum0 += s[ni][1];
            s[ni][2] = exp2f(s[ni][2] - m1); sum1 += s[ni][2];
            s[ni][3] = exp2f(s[ni][3] - m1); sum1 += s[ni][3];
        }
        sum0 += __shfl_xor_sync(0xffffffffu, sum0, 1);
        sum0 += __shfl_xor_sync(0xffffffffu, sum0, 2);
        sum1 += __shfl_xor_sync(0xffffffffu, sum1, 1);
        sum1 += __shfl_xor_sync(0xffffffffu, sum1, 2);
        l0s = l0s * sc0 + sum0;
        l1s = l1s * sc1 + sum1;
#pragma unroll
        for (int nd = 0; nd < 8; nd++) {
            o[nd][0] *= sc0; o[nd][1] *= sc0;
            o[nd][2] *= sc1; o[nd][3] *= sc1;
        }

        // O += P V (trans ldmatrix V)
#pragma unroll
        for (int ks = 0; ks < 4; ks++) {
            unsigned ph[4];
            ph[0] = pack2h(s[2*ks][0],   s[2*ks][1]);
            ph[1] = pack2h(s[2*ks][2],   s[2*ks][3]);
            ph[2] = pack2h(s[2*ks+1][0], s[2*ks+1][1]);
            ph[3] = pack2h(s[2*ks+1][2], s[2*ks+1][3]);
#pragma unroll
            for (int p = 0; p < 4; p++) {
                unsigned bh[2][2];
                ldsm4t(bh[0][0], bh[0][1], bh[1][0], bh[1][1], vb + vFo + ks * 2304 + p * 32);
                mma16816h(o[2*p],     ph, bh[0]);
                mma16816h(o[2*p + 1], ph, bh[1]);
            }
        }
        __syncthreads();
    }

    float inv0 = 1.f / l0s, inv1 = 1.f / l1s;
#pragma unroll
    for (int nd = 0; nd < 8; nd++) {
        int ccol = h * COH + nd * 8 + 2 * t;
        long r0q = q0 + mBase + g;
        *(unsigned*)&ath[r0q * CC + ccol]       = pack2h(o[nd][0] * inv0, o[nd][1] * inv0);
        *(unsigned*)&ath[(r0q + 8) * CC + ccol] = pack2h(o[nd][2] * inv1, o[nd][3] * inv1);
    }
}

// ---------------- launch ----------------
extern "C" void kernel_launch(void* const* d_in, const int* in_sizes, int n_in,
                              void* d_out, int out_size) {
    const float* x      = (const float*)d_in[0];
    const int*   ei     = (const int*)d_in[1];
    const float* gat_wl = (const float*)d_in[2];
    const float* gat_bl = (const float*)d_in[3];
    const float* gat_wr = (const float*)d_in[4];
    const float* gat_br = (const float*)d_in[5];
    const float* gat_at = (const float*)d_in[6];
    const float* gat_b  = (const float*)d_in[7];
    const float* in_w   = (const float*)d_in[8];
    const float* in_b   = (const float*)d_in[9];
    const float* out_w  = (const float*)d_in[10];
    const float* out_b  = (const float*)d_in[11];
    const float* ln1_g  = (const float*)d_in[12];
    const float* ln1_b  = (const float*)d_in[13];
    const float* ln2_g  = (const float*)d_in[14];
    const float* ln2_b  = (const float*)d_in[15];
    const float* ln3_g  = (const float*)d_in[16];
    const float* ln3_b  = (const float*)d_in[17];
    const float* w1     = (const float*)d_in[18];
    const float* b1     = (const float*)d_in[19];
    const float* w2     = (const float*)d_in[20];
    const float* b2     = (const float*)d_in[21];
    float* outp = (float*)d_out;

    float* gs = nullptr;
    cudaGetSymbolAddress((void**)&gs, g_scratch);
    __half* gh = nullptr;
    cudaGetSymbolAddress((void**)&gh, g_hf);

    cudaFuncSetAttribute(k_flash, cudaFuncAttributeMaxDynamicSharedMemorySize, FLASH_SMEM);
    cudaFuncSetAttribute(k_gemm<0>, cudaFuncAttributeMaxDynamicSharedMemorySize, G_SMEM0);
    cudaFuncSetAttribute(k_gemm<1>, cudaFuncAttributeMaxDynamicSharedMemorySize, G_SMEM0);
    cudaFuncSetAttribute(k_gemm<3>, cudaFuncAttributeMaxDynamicSharedMemorySize, G_SMEM0);

    __half *Xh = gh + ZX;
    __half *X1h = gh + ZX1;
    __half *Ath = gh + ZATT;
    __half *X2h = gh + ZX2;
    __half *Qh = gh + ZQKV;
    __half *Fh = gh + ZFFN;
    __half *WLh = gh + ZWL;
    __half *WRh = gh + ZWR;
    __half *INh = gh + ZIN;
    __half *OWh = gh + ZOW;
    __half *W1h = gh + ZW1;
    __half *W2h = gh + ZW2;

    // CSR build
    k_zero_deg<<<16, 256>>>();
    k_count<<<EE / 256, 256>>>(ei);
    k_scan<<<1, 1024>>>();
    k_scatter<<<EE / 256, 256>>>(ei);

    // convert x + weights
    k_half<<<(NN*CC/4 + 255)/256, 256>>>(x, Xh, NN*CC/4);
    k_half<<<(CC*CC/4 + 255)/256, 256>>>(gat_wl, WLh, CC*CC/4);
    k_half<<<(CC*CC/4 + 255)/256, 256>>>(gat_wr, WRh, CC*CC/4);
    k_half<<<(3*CC*CC/4 + 255)/256, 256>>>(in_w, INh, 3*CC*CC/4);
    k_half<<<(CC*CC/4 + 255)/256, 256>>>(out_w, OWh, CC*CC/4);
    k_half<<<(4*CC*CC/4 + 255)/256, 256>>>(w1, W1h, 4*CC*CC/4);
    k_half<<<(4*CC*CC/4 + 255)/256, 256>>>(w2, W2h, 4*CC*CC/4);

    // GAT projections (fp32 out)
    dim3 g512(CC / 64, NN / 128);
    k_gemm<0><<<g512, 256, G_SMEM0>>>(Xh, WLh, gat_bl, gs + S_XL, 0, CC, CC);
    k_gemm<0><<<g512, 256, G_SMEM0>>>(Xh, WRh, gat_br, gs + S_XR, 0, CC, CC);

    // GAT aggregation
    k_gat<<<NN, 256>>>(gs + S_XL, gs + S_XR, gat_at, gat_b, gs + S_HB);

    // x1 = LN(x + h_local), hi out
    k_add_ln<<<NN, 256>>>(x, gs + S_HB, ln1_g, ln1_b, gs + S_X1, X1h);

    // QKV (hi fp16 out)
    dim3 gqkv(QKVW / 64, NN / 128);
    k_gemm<3><<<gqkv, 256, G_SMEM0>>>(X1h, INh, in_b, 0, Qh, QKVW, CC);

    // flash attention (BM=128, hi-only)
    dim3 gfl(NN / 128, HH);
    k_flash<<<gfl, 256, FLASH_SMEM>>>(Qh, Ath);

    // out proj (fp32 out)
    k_gemm<0><<<g512, 256, G_SMEM0>>>(Ath, OWh, out_b, gs + S_HB, 0, CC, CC);

    // x2 = LN(x1 + h_global), hi out
    k_add_ln<<<NN, 256>>>(gs + S_X1, gs + S_HB, ln2_g, ln2_b, gs + S_X2, X2h);

    // FFN1 (GELU, hi out)
    dim3 gffn1(4 * CC / 64, NN / 128);
    k_gemm<1><<<gffn1, 256, G_SMEM0>>>(X2h, W1h, b1, 0, Fh, 4 * CC, CC);
    // FFN2 (fp32 out)
    k_gemm<0><<<g512, 256, G_SMEM0>>>(Fh, W2h, b2, gs + S_HB, 0, CC, 4 * CC);

    // out = LN(x2 + ffn)
    k_add_ln<<<NN, 256>>>(gs + S_X2, gs + S_HB, ln3_g, ln3_b, outp, 0);
}

// round 16
// speedup vs baseline: 2.6659x; 1.0391x over previous
#include <cuda_runtime.h>
#include <cuda_fp16.h>
#include <stdint.h>
#include <math.h>

#define NN    4096
#define CC    512
#define HH    8
#define COH   64
#define EE    131072
#define QKVW  1536

// ---------------- fp32 scratch ----------------
#define S_XLR  0L
#define S_HB   (S_XLR + 2L*NN*CC)
#define S_X1   (S_HB  + (long)NN*CC)
#define S_X2   (S_X1  + (long)NN*CC)
#define S_BIAS (S_X2  + (long)NN*CC)
#define S_TOT  (S_BIAS + 1024)
__device__ float g_scratch[S_TOT];

// ---------------- fp16 scratch (hi-only) ----------------
#define ZX    0L
#define ZX1   (ZX   + 1L*NN*CC)
#define ZATT  (ZX1  + 1L*NN*CC)
#define ZX2   (ZATT + 1L*NN*CC)
#define ZQKV  (ZX2  + 1L*NN*CC)
#define ZFFN  (ZQKV + 1L*NN*3*CC)
#define ZWLR  (ZFFN + 1L*NN*4*CC)
#define ZIN   (ZWLR + 2L*CC*CC)
#define ZOW   (ZIN  + 3L*CC*CC)
#define ZW1   (ZOW  + 1L*CC*CC)
#define ZW2   (ZW1  + 4L*CC*CC)
#define ZTOT  (ZW2  + 4L*CC*CC)
__device__ __half g_hf[ZTOT];

// int scratch
#define I_DEG  0
#define I_OFF  4096
#define I_POS  (I_OFF + 4097)
#define I_ESRC (I_POS + 4096)
__device__ int g_ints[I_ESRC + EE];

// ---------------- helpers ----------------
__device__ __forceinline__ unsigned pack2h(float x0, float x1) {
    return ((unsigned)__half_as_ushort(__float2half_rn(x1)) << 16) |
           (unsigned)__half_as_ushort(__float2half_rn(x0));
}

__device__ __forceinline__ void mma16816h(float* c, const unsigned* a, const unsigned* b) {
    asm volatile(
        "mma.sync.aligned.m16n8k16.row.col.f32.f16.f16.f32 "
        "{%0,%1,%2,%3}, {%4,%5,%6,%7}, {%8,%9}, {%0,%1,%2,%3};\n"
        : "+f"(c[0]), "+f"(c[1]), "+f"(c[2]), "+f"(c[3])
        : "r"(a[0]), "r"(a[1]), "r"(a[2]), "r"(a[3]), "r"(b[0]), "r"(b[1]));
}

__device__ __forceinline__ void ldsm4(unsigned &r0, unsigned &r1, unsigned &r2, unsigned &r3,
                                      uint32_t addr) {
    asm volatile("ldmatrix.sync.aligned.m8n8.x4.shared.b16 {%0,%1,%2,%3}, [%4];"
                 : "=r"(r0), "=r"(r1), "=r"(r2), "=r"(r3) : "r"(addr));
}

__device__ __forceinline__ void ldsm4t(unsigned &r0, unsigned &r1, unsigned &r2, unsigned &r3,
                                       uint32_t addr) {
    asm volatile("ldmatrix.sync.aligned.m8n8.x4.trans.shared.b16 {%0,%1,%2,%3}, [%4];"
                 : "=r"(r0), "=r"(r1), "=r"(r2), "=r"(r3) : "r"(addr));
}

__device__ __forceinline__ uint32_t smem_u32(const void* p) {
    uint32_t a;
    asm("{ .reg .u64 t; cvta.to.shared.u64 t, %1; cvt.u32.u64 %0, t; }" : "=r"(a) : "l"(p));
    return a;
}

#define CP16(dst, src) asm volatile("cp.async.cg.shared.global [%0], [%1], 16;" :: "r"(dst), "l"(src) : "memory")
#define CP_COMMIT()    asm volatile("cp.async.commit_group;" ::: "memory")
#define CP_WAIT0()     asm volatile("cp.async.wait_group 0;" ::: "memory")
#define CP_WAIT1()     asm volatile("cp.async.wait_group 1;" ::: "memory")

__device__ __forceinline__ float geluf(float v) {
    return 0.5f * v * (1.f + erff(v * 0.70710678118654752f));
}

// ---------------- CSR build ----------------
__global__ void k_setup(const float* __restrict__ bl, const float* __restrict__ br,
                        float* __restrict__ bias_cat) {
    int i = blockIdx.x * blockDim.x + threadIdx.x;
    if (i < NN) g_ints[I_DEG + i] = 0;
    if (i < CC) { bias_cat[i] = bl[i]; bias_cat[CC + i] = br[i]; }
}
__global__ void k_count(const int* __restrict__ ei) {
    int e = blockIdx.x * blockDim.x + threadIdx.x;
    if (e < EE) atomicAdd(&g_ints[I_DEG + (ei[EE + e] & (NN - 1))], 1);
}
__global__ void k_scan() {
    __shared__ int ws[32];
    int t = threadIdx.x;
    int v[4]; int tot = 0;
#pragma unroll
    for (int j = 0; j < 4; j++) { v[j] = g_ints[I_DEG + t*4 + j]; tot += v[j]; }
    int lane = t & 31, wid = t >> 5;
    int sc = tot;
#pragma unroll
    for (int o = 1; o < 32; o <<= 1) {
        int y = __shfl_up_sync(0xffffffffu, sc, o);
        if (lane >= o) sc += y;
    }
    if (lane == 31) ws[wid] = sc;
    __syncthreads();
    if (wid == 0) {
        int z = ws[lane];
#pragma unroll
        for (int o = 1; o < 32; o <<= 1) {
            int y = __shfl_up_sync(0xffffffffu, z, o);
            if (lane >= o) z += y;
        }
        ws[lane] = z;
    }
    __syncthreads();
    int excl = sc - tot + (wid ? ws[wid - 1] : 0);
    int run = excl;
#pragma unroll
    for (int j = 0; j < 4; j++) {
        g_ints[I_OFF + t*4 + j] = run;
        g_ints[I_POS + t*4 + j] = run;
        run += v[j];
    }
    if (t == 1023) g_ints[I_OFF + 4096] = run;
}
__global__ void k_scatter(const int* __restrict__ ei) {
    int e = blockIdx.x * blockDim.x + threadIdx.x;
    if (e < EE) {
        int d = ei[EE + e] & (NN - 1);
        int s = ei[e] & (NN - 1);
        int p = atomicAdd(&g_ints[I_POS + d], 1);
        if (p >= 0 && p < EE) g_ints[I_ESRC + p] = s;
    }
}

// ---------------- one-shot fp32 -> fp16 convert of x + all weights ----------------
// segments (float4 units): x 524288 | wl 65536 | wr 65536 | in 196608 | ow 65536 | w1 262144 | w2 262144
#define C_B0 524288L
#define C_B1 (C_B0 + 65536L)
#define C_B2 (C_B1 + 65536L)
#define C_B3 (C_B2 + 196608L)
#define C_B4 (C_B3 + 65536L)
#define C_B5 (C_B4 + 262144L)
#define C_B6 (C_B5 + 262144L)
__global__ void k_convert(const float* __restrict__ x, const float* __restrict__ wl,
                          const float* __restrict__ wr, const float* __restrict__ inw,
                          const float* __restrict__ ow, const float* __restrict__ w1,
                          const float* __restrict__ w2) {
    long i = (long)blockIdx.x * blockDim.x + threadIdx.x;
    if (i >= C_B6) return;
    const float* src; uint2* dst; long li;
    if (i < C_B0)      { src = x;   dst = (uint2*)(g_hf + ZX);                li = i; }
    else if (i < C_B1) { src = wl;  dst = (uint2*)(g_hf + ZWLR);              li = i - C_B0; }
    else if (i < C_B2) { src = wr;  dst = (uint2*)(g_hf + ZWLR + (long)CC*CC); li = i - C_B1; }
    else if (i < C_B3) { src = inw; dst = (uint2*)(g_hf + ZIN);               li = i - C_B2; }
    else if (i < C_B4) { src = ow;  dst = (uint2*)(g_hf + ZOW);               li = i - C_B3; }
    else if (i < C_B5) { src = w1;  dst = (uint2*)(g_hf + ZW1);               li = i - C_B4; }
    else               { src = w2;  dst = (uint2*)(g_hf + ZW2);               li = i - C_B5; }
    float4 v = ((const float4*)src)[li];
    dst[li] = make_uint2(pack2h(v.x, v.y), pack2h(v.z, v.w));
}

// ---------------- mma.sync NT GEMM (1-product fp16), LDSM + cp.async pipeline ----------------
// BM=128 BN=64 BK=32, 256 thr, 8 warps (4Mx2N). Double-buffered dynamic smem.
// EPI: 0 fp32 out; 1 GELU -> hi fp16 out; 3 bias -> hi fp16 out.
#define G_SMEM0 (2 * 15360)

template <int EPI>
__global__ void __launch_bounds__(256) k_gemm(
    const __half* __restrict__ Ah, const __half* __restrict__ Bh,
    const float* __restrict__ bias, float* __restrict__ Cf,
    __half* __restrict__ Ch, int Nd, int K) {
    extern __shared__ __align__(16) unsigned gsm[];
    const int SIDE = 15360;
    const int BOFF = 10240;
    int tid = threadIdx.x;
    int lane = tid & 31, wid = tid >> 5;
    int wm = wid & 3, wn = wid >> 2;
    int mBase = wm * 32, nBase = wn * 32;
    int g = lane >> 2, t = lane & 3;
    int bm = blockIdx.y * 128, bn = blockIdx.x * 64;
    uint32_t smB = smem_u32(gsm);

    int rA0 = tid >> 2;
    int cA0 = (tid & 3) * 16;
    uint32_t dA0 = rA0 * 80 + cA0;
    uint32_t dA1 = dA0 + 64 * 80;
    const char* gA0h = (const char*)Ah + ((long)(bm + rA0) * K) * 2 + cA0;
    const char* gA1h = (const char*)Ah + ((long)(bm + rA0 + 64) * K) * 2 + cA0;
    const char* gB   = (const char*)Bh + ((long)(bn + rA0) * K) * 2 + cA0;

    uint32_t aFh = (mBase + (lane & 15)) * 80 + (lane >> 4) * 16;
    uint32_t bF  = BOFF + (nBase + 8 * (lane >> 4) + (lane & 7)) * 80 + ((lane >> 3) & 1) * 16;

    float c[2][4][4];
#pragma unroll
    for (int mi = 0; mi < 2; mi++)
#pragma unroll
        for (int ni = 0; ni < 4; ni++)
#pragma unroll
            for (int j = 0; j < 4; j++) c[mi][ni][j] = 0.f;

    int nch = K >> 5;
    {
        uint32_t bb = smB;
        CP16(bb + dA0, gA0h);
        CP16(bb + dA1, gA1h);
        CP16(bb + BOFF + dA0, gB);
    }
    CP_COMMIT();

    for (int cc = 0; cc < nch; cc++) {
        if (cc + 1 < nch) {
            long kb = (long)(cc + 1) * 64;
            uint32_t bb = smB + ((cc + 1) & 1) * SIDE;
            CP16(bb + dA0, gA0h + kb);
            CP16(bb + dA1, gA1h + kb);
            CP16(bb + BOFF + dA0, gB + kb);
            CP_COMMIT();
            CP_WAIT1();
        } else {
            CP_WAIT0();
        }
        __syncthreads();
        uint32_t bb = smB + (cc & 1) * SIDE;
#pragma unroll
        for (int ks = 0; ks < 2; ks++) {
            unsigned ah[2][4], bh[4][2];
#pragma unroll
            for (int mi = 0; mi < 2; mi++)
                ldsm4(ah[mi][0], ah[mi][1], ah[mi][2], ah[mi][3], bb + aFh + mi * 1280 + ks * 32);
#pragma unroll
            for (int p = 0; p < 2; p++)
                ldsm4(bh[2*p][0], bh[2*p][1], bh[2*p+1][0], bh[2*p+1][1], bb + bF + p * 1280 + ks * 32);
#pragma unroll
            for (int mi = 0; mi < 2; mi++)
#pragma unroll
                for (int ni = 0; ni < 4; ni++)
                    mma16816h(c[mi][ni], ah[mi], bh[ni]);
        }
        __syncthreads();
    }

    // epilogue
#pragma unroll
    for (int mi = 0; mi < 2; mi++)
#pragma unroll
        for (int ni = 0; ni < 4; ni++) {
            int n0 = bn + nBase + ni * 8 + 2 * t;
            long r0 = bm + mBase + mi * 16 + g;
            float v0 = c[mi][ni][0] + bias[n0];
            float v1 = c[mi][ni][1] + bias[n0 + 1];
            float v2 = c[mi][ni][2] + bias[n0];
            float v3 = c[mi][ni][3] + bias[n0 + 1];
            if (EPI == 0) {
                Cf[r0 * Nd + n0]           = v0;
                Cf[r0 * Nd + n0 + 1]       = v1;
                Cf[(r0 + 8) * Nd + n0]     = v2;
                Cf[(r0 + 8) * Nd + n0 + 1] = v3;
            } else if (EPI == 1) {
                *(unsigned*)&Ch[r0 * Nd + n0]       = pack2h(geluf(v0), geluf(v1));
                *(unsigned*)&Ch[(r0 + 8) * Nd + n0] = pack2h(geluf(v2), geluf(v3));
            } else {
                *(unsigned*)&Ch[r0 * Nd + n0]       = pack2h(v0, v1);
                *(unsigned*)&Ch[(r0 + 8) * Nd + n0] = pack2h(v2, v3);
            }
        }
}

// ---------------- fused GAT aggregation + residual + LN1 (+ fp16 out) ----------------
// xlr: [NN][1024], cols 0-511 = xl, 512-1023 = xr. One block per node, 8 warps = 8 heads.
__global__ void k_gat_ln(const float* __restrict__ xlr,
                         const float* __restrict__ att, const float* __restrict__ gbias,
                         const float* __restrict__ x,
                         const float* __restrict__ g, const float* __restrict__ b,
                         float* __restrict__ x1f, __half* __restrict__ x1h) {
    int i = blockIdx.x;
    int tid = threadIdx.x;
    int w = tid >> 5;
    int lane = tid & 31;
    int c0 = lane, c1 = lane + 32;
    const float* xli = xlr + (long)i * 1024 + w * COH;
    float xl0 = xli[c0], xl1 = xli[c1];
    float a0 = att[w * COH + c0], a1 = att[w * COH + c1];
    float m = -1e30f, l = 0.f, acc0 = 0.f, acc1 = 0.f;
    int beg = g_ints[I_OFF + i], end = g_ints[I_OFF + i + 1];
    int j = beg;
    for (; j + 2 <= end; j += 2) {
        int s1 = g_ints[I_ESRC + j];
        int s2 = g_ints[I_ESRC + j + 1];
        const float* x1p = xlr + (long)s1 * 1024 + 512 + w * COH;
        const float* x2p = xlr + (long)s2 * 1024 + 512 + w * COH;
        float x10 = x1p[c0], x11 = x1p[c1];
        float x20 = x2p[c0], x21 = x2p[c1];
        float e10 = xl0 + x10; e10 = (e10 > 0.f) ? e10 : 0.2f * e10;
        float e11 = xl1 + x11; e11 = (e11 > 0.f) ? e11 : 0.2f * e11;
        float e20 = xl0 + x20; e20 = (e20 > 0.f) ? e20 : 0.2f * e20;
        float e21 = xl1 + x21; e21 = (e21 > 0.f) ? e21 : 0.2f * e21;
        float p1 = e10 * a0 + e11 * a1;
        float p2 = e20 * a0 + e21 * a1;
#pragma unroll
        for (int o = 16; o; o >>= 1) {
            p1 += __shfl_xor_sync(0xffffffffu, p1, o);
            p2 += __shfl_xor_sync(0xffffffffu, p2, o);
        }
        float mn = fmaxf(m, fmaxf(p1, p2));
        float sc = __expf(m - mn);
        float w1 = __expf(p1 - mn);
        float w2 = __expf(p2 - mn);
        l = l * sc + w1 + w2;
        acc0 = acc0 * sc + x10 * w1 + x20 * w2;
        acc1 = acc1 * sc + x11 * w1 + x21 * w2;
        m = mn;
    }
    for (int jj = j; jj <= end; jj++) {
        int s = (jj < end) ? g_ints[I_ESRC + jj] : i;
        const float* xrs = xlr + (long)s * 1024 + 512 + w * COH;
        float xr0 = xrs[c0], xr1 = xrs[c1];
        float e0 = xl0 + xr0; e0 = (e0 > 0.f) ? e0 : 0.2f * e0;
        float e1 = xl1 + xr1; e1 = (e1 > 0.f) ? e1 : 0.2f * e1;
        float p = e0 * a0 + e1 * a1;
#pragma unroll
        for (int o = 16; o; o >>= 1) p += __shfl_xor_sync(0xffffffffu, p, o);
        float mn = fmaxf(m, p);
        float sc = __expf(m - mn);
        float wg = __expf(p - mn);
        l = l * sc + wg;
        acc0 = acc0 * sc + xr0 * wg;
        acc1 = acc1 * sc + xr1 * wg;
        m = mn;
    }
    float inv = 1.f / l;
    int col0 = w * COH + c0, col1 = w * COH + c1;
    float v0 = x[(long)i * CC + col0] + acc0 * inv + gbias[col0];
    float v1 = x[(long)i * CC + col1] + acc1 * inv + gbias[col1];

    // block LN over the 512 values (2 per thread)
    __shared__ float sh[8];
    float s = v0 + v1;
#pragma unroll
    for (int o = 16; o; o >>= 1) s += __shfl_xor_sync(0xffffffffu, s, o);
    if (lane == 0) sh[w] = s;
    __syncthreads();
    float tot = 0.f;
#pragma unroll
    for (int k = 0; k < 8; k++) tot += sh[k];
    float mu = tot * (1.f / 512.f);
    __syncthreads();
    float d0 = v0 - mu, d1 = v1 - mu;
    float q = d0 * d0 + d1 * d1;
#pragma unroll
    for (int o = 16; o; o >>= 1) q += __shfl_xor_sync(0xffffffffu, q, o);
    if (lane == 0) sh[w] = q;
    __syncthreads();
    float var = 0.f;
#pragma unroll
    for (int k = 0; k < 8; k++) var += sh[k];
    var *= (1.f / 512.f);
    float rstd = rsqrtf(var + 1e-5f);
    float y0 = d0 * rstd * g[col0] + b[col0];
    float y1 = d1 * rstd * g[col1] + b[col1];
    x1f[(long)i * CC + col0] = y0;
    x1f[(long)i * CC + col1] = y1;
    x1h[(long)i * CC + col0] = __float2half_rn(y0);
    x1h[(long)i * CC + col1] = __float2half_rn(y1);
}

// ---------------- residual add + layernorm (+ optional fp16 hi out) ----------------
__global__ void k_add_ln(const float* __restrict__ x, const float* __restrict__ h,
                         const float* __restrict__ g, const float* __restrict__ b,
                         float* __restrict__ outp, __half* __restrict__ oh) {
    int row = blockIdx.x;
    int t = threadIdx.x;
    __shared__ float sh[8];
    float v0 = x[(long)row * CC + t]       + h[(long)row * CC + t];
    float v1 = x[(long)row * CC + 256 + t] + h[(long)row * CC + 256 + t];
    float s = v0 + v1;
#pragma unroll
    for (int o = 16; o; o >>= 1) s += __shfl_xor_sync(0xffffffffu, s, o);
    if ((t & 31) == 0) sh[t >> 5] = s;
    __syncthreads();
    float tot = 0.f;
#pragma unroll
    for (int i = 0; i < 8; i++) tot += sh[i];
    float mu = tot * (1.f / 512.f);
    __syncthreads();
    float d0 = v0 - mu, d1 = v1 - mu;
    float q = d0 * d0 + d1 * d1;
#pragma unroll
    for (int o = 16; o; o >>= 1) q += __shfl_xor_sync(0xffffffffu, q, o);
    if ((t & 31) == 0) sh[t >> 5] = q;
    __syncthreads();
    float var = 0.f;
#pragma unroll
    for (int i = 0; i < 8; i++) var += sh[i];
    var *= (1.f / 512.f);
    float rstd = rsqrtf(var + 1e-5f);
    float y0 = d0 * rstd * g[t]       + b[t];
    float y1 = d1 * rstd * g[t + 256] + b[t + 256];
    outp[(long)row * CC + t]       = y0;
    outp[(long)row * CC + 256 + t] = y1;
    if (oh) {
        oh[(long)row * CC + t]       = __float2half_rn(y0);
        oh[(long)row * CC + 256 + t] = __float2half_rn(y1);
    }
}

// ---------------- flash attention: BM=128, hi-only everything ----------------
// smem (uint units, row stride 36 = 144B): Qh 0, K bufs 4608 + b*2304, V bufs 9216 + b*2304
#define FQH 0
#define FKB 4608
#define FVB 9216
#define FLASH_SMEM (13824 * 4)

__global__ void __launch_bounds__(256) k_flash(const __half* __restrict__ qkvh,
                                               __half* __restrict__ ath) {
    extern __shared__ __align__(16) unsigned sm[];
    int h = blockIdx.y;
    int q0 = blockIdx.x * 128;
    int tid = threadIdx.x;
    int lane = tid & 31, wid = tid >> 5;
    int g = lane >> 2, t = lane & 3;
    int mBase = wid * 16;
    const float qs2 = 0.125f * 1.44269504088896f;
    uint32_t smB = smem_u32(sm);

    int r0 = tid >> 3;
    int j0 = (tid & 7) * 16;
    uint32_t dKV = r0 * 144 + j0;
    const char* gK = (const char*)qkvh + ((long)r0 * QKVW + CC + h * COH) * 2 + j0;
    const char* gV = (const char*)qkvh + ((long)r0 * QKVW + 2 * CC + h * COH) * 2 + j0;

    uint32_t qFh = smB + (mBase + (lane & 15)) * 144 + (lane >> 4) * 16;
    uint32_t kFo = (8 * (lane >> 4) + (lane & 7)) * 144 + ((lane >> 3) & 1) * 16;
    uint32_t vFo = (lane & 15) * 144 + (lane >> 4) * 16;

    // Q tile load (128 rows x 64 halves = 1024 uint4; 256 threads x 4)
#pragma unroll
    for (int i = 0; i < 4; i++) {
        int cchunk = tid + i * 256;
        int r = cchunk >> 3;
        int q4 = cchunk & 7;
        long goff = (long)(q0 + r) * QKVW + h * COH + q4 * 8;
        *(uint4*)&sm[FQH + r * 36 + q4 * 4] = *(const uint4*)&qkvh[goff];
    }

    float m0 = -1e30f, m1 = -1e30f, l0s = 0.f, l1s = 0.f;
    float o[8][4];
#pragma unroll
    for (int nd = 0; nd < 8; nd++)
#pragma unroll
        for (int j = 0; j < 4; j++) o[nd][j] = 0.f;

    {
        uint32_t kb = smB + FKB * 4;
        uint32_t vb = smB + FVB * 4;
#pragma unroll
        for (int i = 0; i < 2; i++) {
            CP16(kb + dKV + i * (32 * 144), gK + (long)i * 32 * QKVW * 2);
            CP16(vb + dKV + i * (32 * 144), gV + (long)i * 32 * QKVW * 2);
        }
        CP_COMMIT();
    }

    for (int tt = 0; tt < 64; tt++) {
        if (tt + 1 < 64) {
            long go = (long)(tt + 1) * 64 * QKVW * 2;
            uint32_t kb = smB + (FKB + ((tt + 1) & 1) * 2304) * 4;
            uint32_t vb = smB + (FVB + ((tt + 1) & 1) * 2304) * 4;
#pragma unroll
            for (int i = 0; i < 2; i++) {
                CP16(kb + dKV + i * (32 * 144), gK + go + (long)i * 32 * QKVW * 2);
                CP16(vb + dKV + i * (32 * 144), gV + go + (long)i * 32 * QKVW * 2);
            }
            CP_COMMIT();
            CP_WAIT1();
        } else {
            CP_WAIT0();
        }
        __syncthreads();
        uint32_t kb = smB + (FKB + (tt & 1) * 2304) * 4;
        uint32_t vb = smB + (FVB + (tt & 1) * 2304) * 4;

        // S = Q K^T (1-product)
        float s[8][4];
#pragma unroll
        for (int ni = 0; ni < 8; ni++)
#pragma unroll
            for (int j = 0; j < 4; j++) s[ni][j] = 0.f;

#pragma unroll
        for (int ks = 0; ks < 4; ks++) {
            unsigned ah[4];
            ldsm4(ah[0], ah[1], ah[2], ah[3], qFh + ks * 32);
#pragma unroll
            for (int p = 0; p < 4; p++) {
                unsigned bh[2][2];
                ldsm4(bh[0][0], bh[0][1], bh[1][0], bh[1][1], kb + kFo + p * 2304 + ks * 32);
                mma16816h(s[2*p],     ah, bh[0]);
                mma16816h(s[2*p + 1], ah, bh[1]);
            }
        }
#pragma unroll
        for (int ni = 0; ni < 8; ni++)
#pragma unroll
            for (int j = 0; j < 4; j++) s[ni][j] *= qs2;

        // online softmax (base-2)
        float mx0 = -1e30f, mx1 = -1e30f;
#pragma unroll
        for (int ni = 0; ni < 8; ni++) {
            mx0 = fmaxf(mx0, fmaxf(s[ni][0], s[ni][1]));
            mx1 = fmaxf(mx1, fmaxf(s[ni][2], s[ni][3]));
        }
        mx0 = fmaxf(mx0, __shfl_xor_sync(0xffffffffu, mx0, 1));
        mx0 = fmaxf(mx0, __shfl_xor_sync(0xffffffffu, mx0, 2));
        mx1 = fmaxf(mx1, __shfl_xor_sync(0xffffffffu, mx1, 1));
        mx1 = fmaxf(mx1, __shfl_xor_sync(0xffffffffu, mx1, 2));
        float mn0 = fmaxf(m0, mx0), mn1 = fmaxf(m1, mx1);
        float sc0 = exp2f(m0 - mn0), sc1 = exp2f(m1 - mn1);
        m0 = mn0; m1 = mn1;
        float sum0 = 0.f, sum1 = 0.f;
#pragma unroll
        for (int ni = 0; ni < 8; ni++) {
            s[ni][0] = exp2f(s[ni][0] - m0); sum0 += s[ni][0];
            s[ni][1] = exp2f(s[ni][1] - m0); sum0 += s[ni][1];
            s[ni][2] = exp2f(s[ni][2] - m1); sum1 += s[ni][2];
            s[ni][3] = exp2f(s[ni][3] - m1); sum1 += s[ni][3];
        }
        sum0 += __shfl_xor_sync(0xffffffffu, sum0, 1);
        sum0 += __shfl_xor_sync(0xffffffffu, sum0, 2);
        sum1 += __shfl_xor_sync(0xffffffffu, sum1, 1);
        sum1 += __shfl_xor_sync(0xffffffffu, sum1, 2);
        l0s = l0s * sc0 + sum0;
        l1s = l1s * sc1 + sum1;
#pragma unroll
        for (int nd = 0; nd < 8; nd++) {
            o[nd][0] *= sc0; o[nd][1] *= sc0;
            o[nd][2] *= sc1; o[nd][3] *= sc1;
        }

        // O += P V (trans ldmatrix V)
#pragma unroll
        for (int ks = 0; ks < 4; ks++) {
            unsigned ph[4];
            ph[0] = pack2h(s[2*ks][0],   s[2*ks][1]);
            ph[1] = pack2h(s[2*ks][2],   s[2*ks][3]);
            ph[2] = pack2h(s[2*ks+1][0], s[2*ks+1][1]);
            ph[3] = pack2h(s[2*ks+1][2], s[2*ks+1][3]);
#pragma unroll
            for (int p = 0; p < 4; p++) {
                unsigned bh[2][2];
                ldsm4t(bh[0][0], bh[0][1], bh[1][0], bh[1][1], vb + vFo + ks * 2304 + p * 32);
                mma16816h(o[2*p],     ph, bh[0]);
                mma16816h(o[2*p + 1], ph, bh[1]);
            }
        }
        __syncthreads();
    }

    float inv0 = 1.f / l0s, inv1 = 1.f / l1s;
#pragma unroll
    for (int nd = 0; nd < 8; nd++) {
        int ccol = h * COH + nd * 8 + 2 * t;
        long r0q = q0 + mBase + g;
        *(unsigned*)&ath[r0q * CC + ccol]       = pack2h(o[nd][0] * inv0, o[nd][1] * inv0);
        *(unsigned*)&ath[(r0q + 8) * CC + ccol] = pack2h(o[nd][2] * inv1, o[nd][3] * inv1);
    }
}

// ---------------- launch ----------------
extern "C" void kernel_launch(void* const* d_in, const int* in_sizes, int n_in,
                              void* d_out, int out_size) {
    const float* x      = (const float*)d_in[0];
    const int*   ei     = (const int*)d_in[1];
    const float* gat_wl = (const float*)d_in[2];
    const float* gat_bl = (const float*)d_in[3];
    const float* gat_wr = (const float*)d_in[4];
    const float* gat_br = (const float*)d_in[5];
    const float* gat_at = (const float*)d_in[6];
    const float* gat_b  = (const float*)d_in[7];
    const float* in_w   = (const float*)d_in[8];
    const float* in_b   = (const float*)d_in[9];
    const float* out_w  = (const float*)d_in[10];
    const float* out_b  = (const float*)d_in[11];
    const float* ln1_g  = (const float*)d_in[12];
    const float* ln1_b  = (const float*)d_in[13];
    const float* ln2_g  = (const float*)d_in[14];
    const float* ln2_b  = (const float*)d_in[15];
    const float* ln3_g  = (const float*)d_in[16];
    const float* ln3_b  = (const float*)d_in[17];
    const float* w1     = (const float*)d_in[18];
    const float* b1     = (const float*)d_in[19];
    const float* w2     = (const float*)d_in[20];
    const float* b2     = (const float*)d_in[21];
    float* outp = (float*)d_out;

    float* gs = nullptr;
    cudaGetSymbolAddress((void**)&gs, g_scratch);
    __half* gh = nullptr;
    cudaGetSymbolAddress((void**)&gh, g_hf);

    cudaFuncSetAttribute(k_flash, cudaFuncAttributeMaxDynamicSharedMemorySize, FLASH_SMEM);
    cudaFuncSetAttribute(k_gemm<0>, cudaFuncAttributeMaxDynamicSharedMemorySize, G_SMEM0);
    cudaFuncSetAttribute(k_gemm<1>, cudaFuncAttributeMaxDynamicSharedMemorySize, G_SMEM0);
    cudaFuncSetAttribute(k_gemm<3>, cudaFuncAttributeMaxDynamicSharedMemorySize, G_SMEM0);

    __half *Xh = gh + ZX;
    __half *X1h = gh + ZX1;
    __half *Ath = gh + ZATT;
    __half *X2h = gh + ZX2;
    __half *Qh = gh + ZQKV;
    __half *Fh = gh + ZFFN;
    __half *WLRh = gh + ZWLR;
    __half *INh = gh + ZIN;
    __half *OWh = gh + ZOW;
    __half *W1h = gh + ZW1;
    __half *W2h = gh + ZW2;

    // CSR build + bias concat
    k_setup<<<16, 256>>>(gat_bl, gat_br, gs + S_BIAS);
    k_count<<<EE / 256, 256>>>(ei);
    k_scan<<<1, 1024>>>();
    k_scatter<<<EE / 256, 256>>>(ei);

    // one-shot convert: x + all weights
    k_convert<<<(int)((C_B6 + 255) / 256), 256>>>(x, gat_wl, gat_wr, in_w, out_w, w1, w2);

    // merged GAT projections: XLR[NN][1024] = X @ [WL;WR]^T + [bl;br]
    dim3 glr(1024 / 64, NN / 128);
    k_gemm<0><<<glr, 256, G_SMEM0>>>(Xh, WLRh, gs + S_BIAS, gs + S_XLR, 0, 1024, CC);

    // fused GAT aggregation + residual + LN1
    k_gat_ln<<<NN, 256>>>(gs + S_XLR, gat_at, gat_b, x, ln1_g, ln1_b, gs + S_X1, X1h);

    // QKV (hi fp16 out)
    dim3 gqkv(QKVW / 64, NN / 128);
    k_gemm<3><<<gqkv, 256, G_SMEM0>>>(X1h, INh, in_b, 0, Qh, QKVW, CC);

    // flash attention (BM=128, hi-only)
    dim3 gfl(NN / 128, HH);
    k_flash<<<gfl, 256, FLASH_SMEM>>>(Qh, Ath);

    // out proj (fp32 out)
    dim3 g512(CC / 64, NN / 128);
    k_gemm<0><<<g512, 256, G_SMEM0>>>(Ath, OWh, out_b, gs + S_HB, 0, CC, CC);

    // x2 = LN(x1 + h_global), hi out
    k_add_ln<<<NN, 256>>>(gs + S_X1, gs + S_HB, ln2_g, ln2_b, gs + S_X2, X2h);

    // FFN1 (GELU, hi out)
    dim3 gffn1(4 * CC / 64, NN / 128);
    k_gemm<1><<<gffn1, 256, G_SMEM0>>>(X2h, W1h, b1, 0, Fh, 4 * CC, CC);
    // FFN2 (fp32 out)
    k_gemm<0><<<g512, 256, G_SMEM0>>>(Fh, W2h, b2, gs + S_HB, 0, CC, 4 * CC);

    // out = LN(x2 + ffn)
    k_add_ln<<<NN, 256>>>(gs + S_X2, gs + S_HB, ln3_g, ln3_b, outp, 0);
}

// round 17
// speedup vs baseline: 2.8521x; 1.0698x over previous
#include <cuda_runtime.h>
#include <cuda_fp16.h>
#include <stdint.h>
#include <math.h>

#define NN    4096
#define CC    512
#define HH    8
#define COH   64
#define EE    131072
#define QKVW  1536
#define QS2   0.1803368801111204f   // (1/8) * log2(e)

// ---------------- fp32 scratch ----------------
#define S_XLR  0L
#define S_HB   (S_XLR + 2L*NN*CC)
#define S_X1   (S_HB  + (long)NN*CC)
#define S_X2   (S_X1  + (long)NN*CC)
#define S_BIAS (S_X2  + (long)NN*CC)
#define S_TOT  (S_BIAS + 1024)
__device__ float g_scratch[S_TOT];

// ---------------- fp16 scratch (hi-only) ----------------
#define ZX    0L
#define ZX1   (ZX   + 1L*NN*CC)
#define ZATT  (ZX1  + 1L*NN*CC)
#define ZX2   (ZATT + 1L*NN*CC)
#define ZQKV  (ZX2  + 1L*NN*CC)
#define ZFFN  (ZQKV + 1L*NN*3*CC)
#define ZWLR  (ZFFN + 1L*NN*4*CC)
#define ZIN   (ZWLR + 2L*CC*CC)
#define ZOW   (ZIN  + 3L*CC*CC)
#define ZW1   (ZOW  + 1L*CC*CC)
#define ZW2   (ZW1  + 4L*CC*CC)
#define ZTOT  (ZW2  + 4L*CC*CC)
__device__ __half g_hf[ZTOT];

// int scratch
#define I_DEG  0
#define I_OFF  4096
#define I_POS  (I_OFF + 4097)
#define I_ESRC (I_POS + 4096)
__device__ int g_ints[I_ESRC + EE];

// ---------------- helpers ----------------
__device__ __forceinline__ unsigned pack2h(float x0, float x1) {
    return ((unsigned)__half_as_ushort(__float2half_rn(x1)) << 16) |
           (unsigned)__half_as_ushort(__float2half_rn(x0));
}

// packed exp2: returns half2 {lo=exp2(lo), hi=exp2(hi)} as one MUFU op
__device__ __forceinline__ unsigned h2e(float lo, float hi) {
    unsigned r;
    asm("{\n\t.reg .b32 t;\n\tcvt.rn.f16x2.f32 t, %1, %2;\n\tex2.approx.f16x2 %0, t;\n\t}"
        : "=r"(r) : "f"(hi), "f"(lo));
    return r;
}

__device__ __forceinline__ void mma16816h(float* c, const unsigned* a, const unsigned* b) {
    asm volatile(
        "mma.sync.aligned.m16n8k16.row.col.f32.f16.f16.f32 "
        "{%0,%1,%2,%3}, {%4,%5,%6,%7}, {%8,%9}, {%0,%1,%2,%3};\n"
        : "+f"(c[0]), "+f"(c[1]), "+f"(c[2]), "+f"(c[3])
        : "r"(a[0]), "r"(a[1]), "r"(a[2]), "r"(a[3]), "r"(b[0]), "r"(b[1]));
}

__device__ __forceinline__ void ldsm4(unsigned &r0, unsigned &r1, unsigned &r2, unsigned &r3,
                                      uint32_t addr) {
    asm volatile("ldmatrix.sync.aligned.m8n8.x4.shared.b16 {%0,%1,%2,%3}, [%4];"
                 : "=r"(r0), "=r"(r1), "=r"(r2), "=r"(r3) : "r"(addr));
}

__device__ __forceinline__ void ldsm4t(unsigned &r0, unsigned &r1, unsigned &r2, unsigned &r3,
                                       uint32_t addr) {
    asm volatile("ldmatrix.sync.aligned.m8n8.x4.trans.shared.b16 {%0,%1,%2,%3}, [%4];"
                 : "=r"(r0), "=r"(r1), "=r"(r2), "=r"(r3) : "r"(addr));
}

__device__ __forceinline__ uint32_t smem_u32(const void* p) {
    uint32_t a;
    asm("{ .reg .u64 t; cvta.to.shared.u64 t, %1; cvt.u32.u64 %0, t; }" : "=r"(a) : "l"(p));
    return a;
}

#define CP16(dst, src) asm volatile("cp.async.cg.shared.global [%0], [%1], 16;" :: "r"(dst), "l"(src) : "memory")
#define CP_COMMIT()    asm volatile("cp.async.commit_group;" ::: "memory")
#define CP_WAIT0()     asm volatile("cp.async.wait_group 0;" ::: "memory")
#define CP_WAIT1()     asm volatile("cp.async.wait_group 1;" ::: "memory")

__device__ __forceinline__ float geluf(float v) {
    return 0.5f * v * (1.f + erff(v * 0.70710678118654752f));
}

// ---------------- CSR build ----------------
__global__ void k_setup(const float* __restrict__ bl, const float* __restrict__ br,
                        float* __restrict__ bias_cat) {
    int i = blockIdx.x * blockDim.x + threadIdx.x;
    if (i < NN) g_ints[I_DEG + i] = 0;
    if (i < CC) { bias_cat[i] = bl[i]; bias_cat[CC + i] = br[i]; }
}
__global__ void k_count(const int* __restrict__ ei) {
    int e = blockIdx.x * blockDim.x + threadIdx.x;
    if (e < EE) atomicAdd(&g_ints[I_DEG + (ei[EE + e] & (NN - 1))], 1);
}
__global__ void k_scan() {
    __shared__ int ws[32];
    int t = threadIdx.x;
    int v[4]; int tot = 0;
#pragma unroll
    for (int j = 0; j < 4; j++) { v[j] = g_ints[I_DEG + t*4 + j]; tot += v[j]; }
    int lane = t & 31, wid = t >> 5;
    int sc = tot;
#pragma unroll
    for (int o = 1; o < 32; o <<= 1) {
        int y = __shfl_up_sync(0xffffffffu, sc, o);
        if (lane >= o) sc += y;
    }
    if (lane == 31) ws[wid] = sc;
    __syncthreads();
    if (wid == 0) {
        int z = ws[lane];
#pragma unroll
        for (int o = 1; o < 32; o <<= 1) {
            int y = __shfl_up_sync(0xffffffffu, z, o);
            if (lane >= o) z += y;
        }
        ws[lane] = z;
    }
    __syncthreads();
    int excl = sc - tot + (wid ? ws[wid - 1] : 0);
    int run = excl;
#pragma unroll
    for (int j = 0; j < 4; j++) {
        g_ints[I_OFF + t*4 + j] = run;
        g_ints[I_POS + t*4 + j] = run;
        run += v[j];
    }
    if (t == 1023) g_ints[I_OFF + 4096] = run;
}
__global__ void k_scatter(const int* __restrict__ ei) {
    int e = blockIdx.x * blockDim.x + threadIdx.x;
    if (e < EE) {
        int d = ei[EE + e] & (NN - 1);
        int s = ei[e] & (NN - 1);
        int p = atomicAdd(&g_ints[I_POS + d], 1);
        if (p >= 0 && p < EE) g_ints[I_ESRC + p] = s;
    }
}

// ---------------- one-shot fp32 -> fp16 convert of x + all weights ----------------
#define C_B0 524288L
#define C_B1 (C_B0 + 65536L)
#define C_B2 (C_B1 + 65536L)
#define C_B3 (C_B2 + 196608L)
#define C_B4 (C_B3 + 65536L)
#define C_B5 (C_B4 + 262144L)
#define C_B6 (C_B5 + 262144L)
__global__ void k_convert(const float* __restrict__ x, const float* __restrict__ wl,
                          const float* __restrict__ wr, const float* __restrict__ inw,
                          const float* __restrict__ ow, const float* __restrict__ w1,
                          const float* __restrict__ w2) {
    long i = (long)blockIdx.x * blockDim.x + threadIdx.x;
    if (i >= C_B6) return;
    const float* src; uint2* dst; long li;
    if (i < C_B0)      { src = x;   dst = (uint2*)(g_hf + ZX);                li = i; }
    else if (i < C_B1) { src = wl;  dst = (uint2*)(g_hf + ZWLR);              li = i - C_B0; }
    else if (i < C_B2) { src = wr;  dst = (uint2*)(g_hf + ZWLR + (long)CC*CC); li = i - C_B1; }
    else if (i < C_B3) { src = inw; dst = (uint2*)(g_hf + ZIN);               li = i - C_B2; }
    else if (i < C_B4) { src = ow;  dst = (uint2*)(g_hf + ZOW);               li = i - C_B3; }
    else if (i < C_B5) { src = w1;  dst = (uint2*)(g_hf + ZW1);               li = i - C_B4; }
    else               { src = w2;  dst = (uint2*)(g_hf + ZW2);               li = i - C_B5; }
    float4 v = ((const float4*)src)[li];
    dst[li] = make_uint2(pack2h(v.x, v.y), pack2h(v.z, v.w));
}

// ---------------- mma.sync NT GEMM (1-product fp16), LDSM + cp.async pipeline ----------------
// EPI: 0 fp32 out; 1 GELU -> hi fp16 out; 3 bias -> hi fp16 out (Q cols pre-scaled by QS2).
#define G_SMEM0 (2 * 15360)

template <int EPI>
__global__ void __launch_bounds__(256) k_gemm(
    const __half* __restrict__ Ah, const __half* __restrict__ Bh,
    const float* __restrict__ bias, float* __restrict__ Cf,
    __half* __restrict__ Ch, int Nd, int K) {
    extern __shared__ __align__(16) unsigned gsm[];
    const int SIDE = 15360;
    const int BOFF = 10240;
    int tid = threadIdx.x;
    int lane = tid & 31, wid = tid >> 5;
    int wm = wid & 3, wn = wid >> 2;
    int mBase = wm * 32, nBase = wn * 32;
    int g = lane >> 2, t = lane & 3;
    int bm = blockIdx.y * 128, bn = blockIdx.x * 64;
    uint32_t smB = smem_u32(gsm);

    int rA0 = tid >> 2;
    int cA0 = (tid & 3) * 16;
    uint32_t dA0 = rA0 * 80 + cA0;
    uint32_t dA1 = dA0 + 64 * 80;
    const char* gA0h = (const char*)Ah + ((long)(bm + rA0) * K) * 2 + cA0;
    const char* gA1h = (const char*)Ah + ((long)(bm + rA0 + 64) * K) * 2 + cA0;
    const char* gB   = (const char*)Bh + ((long)(bn + rA0) * K) * 2 + cA0;

    uint32_t aFh = (mBase + (lane & 15)) * 80 + (lane >> 4) * 16;
    uint32_t bF  = BOFF + (nBase + 8 * (lane >> 4) + (lane & 7)) * 80 + ((lane >> 3) & 1) * 16;

    float c[2][4][4];
#pragma unroll
    for (int mi = 0; mi < 2; mi++)
#pragma unroll
        for (int ni = 0; ni < 4; ni++)
#pragma unroll
            for (int j = 0; j < 4; j++) c[mi][ni][j] = 0.f;

    int nch = K >> 5;
    {
        uint32_t bb = smB;
        CP16(bb + dA0, gA0h);
        CP16(bb + dA1, gA1h);
        CP16(bb + BOFF + dA0, gB);
    }
    CP_COMMIT();

    for (int cc = 0; cc < nch; cc++) {
        if (cc + 1 < nch) {
            long kb = (long)(cc + 1) * 64;
            uint32_t bb = smB + ((cc + 1) & 1) * SIDE;
            CP16(bb + dA0, gA0h + kb);
            CP16(bb + dA1, gA1h + kb);
            CP16(bb + BOFF + dA0, gB + kb);
            CP_COMMIT();
            CP_WAIT1();
        } else {
            CP_WAIT0();
        }
        __syncthreads();
        uint32_t bb = smB + (cc & 1) * SIDE;
#pragma unroll
        for (int ks = 0; ks < 2; ks++) {
            unsigned ah[2][4], bh[4][2];
#pragma unroll
            for (int mi = 0; mi < 2; mi++)
                ldsm4(ah[mi][0], ah[mi][1], ah[mi][2], ah[mi][3], bb + aFh + mi * 1280 + ks * 32);
#pragma unroll
            for (int p = 0; p < 2; p++)
                ldsm4(bh[2*p][0], bh[2*p][1], bh[2*p+1][0], bh[2*p+1][1], bb + bF + p * 1280 + ks * 32);
#pragma unroll
            for (int mi = 0; mi < 2; mi++)
#pragma unroll
                for (int ni = 0; ni < 4; ni++)
                    mma16816h(c[mi][ni], ah[mi], bh[ni]);
        }
        __syncthreads();
    }

    // epilogue
#pragma unroll
    for (int mi = 0; mi < 2; mi++)
#pragma unroll
        for (int ni = 0; ni < 4; ni++) {
            int n0 = bn + nBase + ni * 8 + 2 * t;
            long r0 = bm + mBase + mi * 16 + g;
            float v0 = c[mi][ni][0] + bias[n0];
            float v1 = c[mi][ni][1] + bias[n0 + 1];
            float v2 = c[mi][ni][2] + bias[n0];
            float v3 = c[mi][ni][3] + bias[n0 + 1];
            if (EPI == 0) {
                Cf[r0 * Nd + n0]           = v0;
                Cf[r0 * Nd + n0 + 1]       = v1;
                Cf[(r0 + 8) * Nd + n0]     = v2;
                Cf[(r0 + 8) * Nd + n0 + 1] = v3;
            } else if (EPI == 1) {
                *(unsigned*)&Ch[r0 * Nd + n0]       = pack2h(geluf(v0), geluf(v1));
                *(unsigned*)&Ch[(r0 + 8) * Nd + n0] = pack2h(geluf(v2), geluf(v3));
            } else {
                if (n0 < CC) { v0 *= QS2; v1 *= QS2; v2 *= QS2; v3 *= QS2; }  // pre-scale Q
                *(unsigned*)&Ch[r0 * Nd + n0]       = pack2h(v0, v1);
                *(unsigned*)&Ch[(r0 + 8) * Nd + n0] = pack2h(v2, v3);
            }
        }
}

// ---------------- fused GAT aggregation + residual + LN1 (+ fp16 out) ----------------
__global__ void k_gat_ln(const float* __restrict__ xlr,
                         const float* __restrict__ att, const float* __restrict__ gbias,
                         const float* __restrict__ x,
                         const float* __restrict__ g, const float* __restrict__ b,
                         float* __restrict__ x1f, __half* __restrict__ x1h) {
    int i = blockIdx.x;
    int tid = threadIdx.x;
    int w = tid >> 5;
    int lane = tid & 31;
    int c0 = lane, c1 = lane + 32;
    const float* xli = xlr + (long)i * 1024 + w * COH;
    float xl0 = xli[c0], xl1 = xli[c1];
    float a0 = att[w * COH + c0], a1 = att[w * COH + c1];
    float m = -1e30f, l = 0.f, acc0 = 0.f, acc1 = 0.f;
    int beg = g_ints[I_OFF + i], end = g_ints[I_OFF + i + 1];
    int j = beg;
    for (; j + 2 <= end; j += 2) {
        int s1 = g_ints[I_ESRC + j];
        int s2 = g_ints[I_ESRC + j + 1];
        const float* x1p = xlr + (long)s1 * 1024 + 512 + w * COH;
        const float* x2p = xlr + (long)s2 * 1024 + 512 + w * COH;
        float x10 = x1p[c0], x11 = x1p[c1];
        float x20 = x2p[c0], x21 = x2p[c1];
        float e10 = xl0 + x10; e10 = (e10 > 0.f) ? e10 : 0.2f * e10;
        float e11 = xl1 + x11; e11 = (e11 > 0.f) ? e11 : 0.2f * e11;
        float e20 = xl0 + x20; e20 = (e20 > 0.f) ? e20 : 0.2f * e20;
        float e21 = xl1 + x21; e21 = (e21 > 0.f) ? e21 : 0.2f * e21;
        float p1 = e10 * a0 + e11 * a1;
        float p2 = e20 * a0 + e21 * a1;
#pragma unroll
        for (int o = 16; o; o >>= 1) {
            p1 += __shfl_xor_sync(0xffffffffu, p1, o);
            p2 += __shfl_xor_sync(0xffffffffu, p2, o);
        }
        float mn = fmaxf(m, fmaxf(p1, p2));
        float sc = __expf(m - mn);
        float w1 = __expf(p1 - mn);
        float w2 = __expf(p2 - mn);
        l = l * sc + w1 + w2;
        acc0 = acc0 * sc + x10 * w1 + x20 * w2;
        acc1 = acc1 * sc + x11 * w1 + x21 * w2;
        m = mn;
    }
    for (int jj = j; jj <= end; jj++) {
        int s = (jj < end) ? g_ints[I_ESRC + jj] : i;
        const float* xrs = xlr + (long)s * 1024 + 512 + w * COH;
        float xr0 = xrs[c0], xr1 = xrs[c1];
        float e0 = xl0 + xr0; e0 = (e0 > 0.f) ? e0 : 0.2f * e0;
        float e1 = xl1 + xr1; e1 = (e1 > 0.f) ? e1 : 0.2f * e1;
        float p = e0 * a0 + e1 * a1;
#pragma unroll
        for (int o = 16; o; o >>= 1) p += __shfl_xor_sync(0xffffffffu, p, o);
        float mn = fmaxf(m, p);
        float sc = __expf(m - mn);
        float wg = __expf(p - mn);
        l = l * sc + wg;
        acc0 = acc0 * sc + xr0 * wg;
        acc1 = acc1 * sc + xr1 * wg;
        m = mn;
    }
    float inv = 1.f / l;
    int col0 = w * COH + c0, col1 = w * COH + c1;
    float v0 = x[(long)i * CC + col0] + acc0 * inv + gbias[col0];
    float v1 = x[(long)i * CC + col1] + acc1 * inv + gbias[col1];

    __shared__ float sh[8];
    float s = v0 + v1;
#pragma unroll
    for (int o = 16; o; o >>= 1) s += __shfl_xor_sync(0xffffffffu, s, o);
    if (lane == 0) sh[w] = s;
    __syncthreads();
    float tot = 0.f;
#pragma unroll
    for (int k = 0; k < 8; k++) tot += sh[k];
    float mu = tot * (1.f / 512.f);
    __syncthreads();
    float d0 = v0 - mu, d1 = v1 - mu;
    float q = d0 * d0 + d1 * d1;
#pragma unroll
    for (int o = 16; o; o >>= 1) q += __shfl_xor_sync(0xffffffffu, q, o);
    if (lane == 0) sh[w] = q;
    __syncthreads();
    float var = 0.f;
#pragma unroll
    for (int k = 0; k < 8; k++) var += sh[k];
    var *= (1.f / 512.f);
    float rstd = rsqrtf(var + 1e-5f);
    float y0 = d0 * rstd * g[col0] + b[col0];
    float y1 = d1 * rstd * g[col1] + b[col1];
    x1f[(long)i * CC + col0] = y0;
    x1f[(long)i * CC + col1] = y1;
    x1h[(long)i * CC + col0] = __float2half_rn(y0);
    x1h[(long)i * CC + col1] = __float2half_rn(y1);
}

// ---------------- residual add + layernorm (+ optional fp16 hi out) ----------------
__global__ void k_add_ln(const float* __restrict__ x, const float* __restrict__ h,
                         const float* __restrict__ g, const float* __restrict__ b,
                         float* __restrict__ outp, __half* __restrict__ oh) {
    int row = blockIdx.x;
    int t = threadIdx.x;
    __shared__ float sh[8];
    float v0 = x[(long)row * CC + t]       + h[(long)row * CC + t];
    float v1 = x[(long)row * CC + 256 + t] + h[(long)row * CC + 256 + t];
    float s = v0 + v1;
#pragma unroll
    for (int o = 16; o; o >>= 1) s += __shfl_xor_sync(0xffffffffu, s, o);
    if ((t & 31) == 0) sh[t >> 5] = s;
    __syncthreads();
    float tot = 0.f;
#pragma unroll
    for (int i = 0; i < 8; i++) tot += sh[i];
    float mu = tot * (1.f / 512.f);
    __syncthreads();
    float d0 = v0 - mu, d1 = v1 - mu;
    float q = d0 * d0 + d1 * d1;
#pragma unroll
    for (int o = 16; o; o >>= 1) q += __shfl_xor_sync(0xffffffffu, q, o);
    if ((t & 31) == 0) sh[t >> 5] = q;
    __syncthreads();
    float var = 0.f;
#pragma unroll
    for (int i = 0; i < 8; i++) var += sh[i];
    var *= (1.f / 512.f);
    float rstd = rsqrtf(var + 1e-5f);
    float y0 = d0 * rstd * g[t]       + b[t];
    float y1 = d1 * rstd * g[t + 256] + b[t + 256];
    outp[(long)row * CC + t]       = y0;
    outp[(long)row * CC + 256 + t] = y1;
    if (oh) {
        oh[(long)row * CC + t]       = __float2half_rn(y0);
        oh[(long)row * CC + 256 + t] = __float2half_rn(y1);
    }
}

// ---------------- flash attention: BM=128, fp16x2 exp + ones-mma row sums ----------------
#define FQH 0
#define FKB 4608
#define FVB 9216
#define FLASH_SMEM (13824 * 4)

__global__ void __launch_bounds__(256) k_flash(const __half* __restrict__ qkvh,
                                               __half* __restrict__ ath) {
    extern __shared__ __align__(16) unsigned sm[];
    int h = blockIdx.y;
    int q0 = blockIdx.x * 128;
    int tid = threadIdx.x;
    int lane = tid & 31, wid = tid >> 5;
    int g = lane >> 2, t = lane & 3;
    int mBase = wid * 16;
    uint32_t smB = smem_u32(sm);

    int r0 = tid >> 3;
    int j0 = (tid & 7) * 16;
    uint32_t dKV = r0 * 144 + j0;
    const char* gK = (const char*)qkvh + ((long)r0 * QKVW + CC + h * COH) * 2 + j0;
    const char* gV = (const char*)qkvh + ((long)r0 * QKVW + 2 * CC + h * COH) * 2 + j0;

    uint32_t qFh = smB + (mBase + (lane & 15)) * 144 + (lane >> 4) * 16;
    uint32_t kFo = (8 * (lane >> 4) + (lane & 7)) * 144 + ((lane >> 3) & 1) * 16;
    uint32_t vFo = (lane & 15) * 144 + (lane >> 4) * 16;

    // Q tile load (128 rows x 64 halves = 1024 uint4; 256 threads x 4)
#pragma unroll
    for (int i = 0; i < 4; i++) {
        int cchunk = tid + i * 256;
        int r = cchunk >> 3;
        int q4 = cchunk & 7;
        long goff = (long)(q0 + r) * QKVW + h * COH + q4 * 8;
        *(uint4*)&sm[FQH + r * 36 + q4 * 4] = *(const uint4*)&qkvh[goff];
    }

    float m0 = -1e30f, m1 = -1e30f;
    float o[8][4];
#pragma unroll
    for (int nd = 0; nd < 8; nd++)
#pragma unroll
        for (int j = 0; j < 4; j++) o[nd][j] = 0.f;
    float sAcc[4] = {0.f, 0.f, 0.f, 0.f};   // virtual ones-column: becomes l at the end
    const unsigned onesb[2] = {0x3C003C00u, 0x3C003C00u};

    {
        uint32_t kb = smB + FKB * 4;
        uint32_t vb = smB + FVB * 4;
#pragma unroll
        for (int i = 0; i < 2; i++) {
            CP16(kb + dKV + i * (32 * 144), gK + (long)i * 32 * QKVW * 2);
            CP16(vb + dKV + i * (32 * 144), gV + (long)i * 32 * QKVW * 2);
        }
        CP_COMMIT();
    }

    for (int tt = 0; tt < 64; tt++) {
        if (tt + 1 < 64) {
            long go = (long)(tt + 1) * 64 * QKVW * 2;
            uint32_t kb = smB + (FKB + ((tt + 1) & 1) * 2304) * 4;
            uint32_t vb = smB + (FVB + ((tt + 1) & 1) * 2304) * 4;
#pragma unroll
            for (int i = 0; i < 2; i++) {
                CP16(kb + dKV + i * (32 * 144), gK + go + (long)i * 32 * QKVW * 2);
                CP16(vb + dKV + i * (32 * 144), gV + go + (long)i * 32 * QKVW * 2);
            }
            CP_COMMIT();
            CP_WAIT1();
        } else {
            CP_WAIT0();
        }
        __syncthreads();
        uint32_t kb = smB + (FKB + (tt & 1) * 2304) * 4;
        uint32_t vb = smB + (FVB + (tt & 1) * 2304) * 4;

        // S = Q K^T (Q pre-scaled by 1/sqrt(d)*log2e)
        float s[8][4];
#pragma unroll
        for (int ni = 0; ni < 8; ni++)
#pragma unroll
            for (int j = 0; j < 4; j++) s[ni][j] = 0.f;

#pragma unroll
        for (int ks = 0; ks < 4; ks++) {
            unsigned ah[4];
            ldsm4(ah[0], ah[1], ah[2], ah[3], qFh + ks * 32);
#pragma unroll
            for (int p = 0; p < 4; p++) {
                unsigned bh[2][2];
                ldsm4(bh[0][0], bh[0][1], bh[1][0], bh[1][1], kb + kFo + p * 2304 + ks * 32);
                mma16816h(s[2*p],     ah, bh[0]);
                mma16816h(s[2*p + 1], ah, bh[1]);
            }
        }

        // online max (base-2 scores)
        float mx0 = -1e30f, mx1 = -1e30f;
#pragma unroll
        for (int ni = 0; ni < 8; ni++) {
            mx0 = fmaxf(mx0, fmaxf(s[ni][0], s[ni][1]));
            mx1 = fmaxf(mx1, fmaxf(s[ni][2], s[ni][3]));
        }
        mx0 = fmaxf(mx0, __shfl_xor_sync(0xffffffffu, mx0, 1));
        mx0 = fmaxf(mx0, __shfl_xor_sync(0xffffffffu, mx0, 2));
        mx1 = fmaxf(mx1, __shfl_xor_sync(0xffffffffu, mx1, 1));
        mx1 = fmaxf(mx1, __shfl_xor_sync(0xffffffffu, mx1, 2));
        float mn0 = fmaxf(m0, mx0), mn1 = fmaxf(m1, mx1);
        float sc0 = exp2f(m0 - mn0), sc1 = exp2f(m1 - mn1);
        m0 = mn0; m1 = mn1;
#pragma unroll
        for (int nd = 0; nd < 8; nd++) {
            o[nd][0] *= sc0; o[nd][1] *= sc0;
            o[nd][2] *= sc1; o[nd][3] *= sc1;
        }
        sAcc[0] *= sc0; sAcc[1] *= sc0;
        sAcc[2] *= sc1; sAcc[3] *= sc1;

        // P = exp2(S - m) in fp16x2; O += P V; l += P 1 (ones-mma)
#pragma unroll
        for (int ks = 0; ks < 4; ks++) {
            unsigned ph[4];
            ph[0] = h2e(s[2*ks][0]   - m0, s[2*ks][1]   - m0);
            ph[1] = h2e(s[2*ks][2]   - m1, s[2*ks][3]   - m1);
            ph[2] = h2e(s[2*ks+1][0] - m0, s[2*ks+1][1] - m0);
            ph[3] = h2e(s[2*ks+1][2] - m1, s[2*ks+1][3] - m1);
            mma16816h(sAcc, ph, onesb);
#pragma unroll
            for (int p = 0; p < 4; p++) {
                unsigned bh[2][2];
                ldsm4t(bh[0][0], bh[0][1], bh[1][0], bh[1][1], vb + vFo + ks * 2304 + p * 32);
                mma16816h(o[2*p],     ph, bh[0]);
                mma16816h(o[2*p + 1], ph, bh[1]);
            }
        }
        __syncthreads();
    }

    float inv0 = 1.f / sAcc[0], inv1 = 1.f / sAcc[2];
#pragma unroll
    for (int nd = 0; nd < 8; nd++) {
        int ccol = h * COH + nd * 8 + 2 * t;
        long r0q = q0 + mBase + g;
        *(unsigned*)&ath[r0q * CC + ccol]       = pack2h(o[nd][0] * inv0, o[nd][1] * inv0);
        *(unsigned*)&ath[(r0q + 8) * CC + ccol] = pack2h(o[nd][2] * inv1, o[nd][3] * inv1);
    }
}

// ---------------- launch ----------------
extern "C" void kernel_launch(void* const* d_in, const int* in_sizes, int n_in,
                              void* d_out, int out_size) {
    const float* x      = (const float*)d_in[0];
    const int*   ei     = (const int*)d_in[1];
    const float* gat_wl = (const float*)d_in[2];
    const float* gat_bl = (const float*)d_in[3];
    const float* gat_wr = (const float*)d_in[4];
    const float* gat_br = (const float*)d_in[5];
    const float* gat_at = (const float*)d_in[6];
    const float* gat_b  = (const float*)d_in[7];
    const float* in_w   = (const float*)d_in[8];
    const float* in_b   = (const float*)d_in[9];
    const float* out_w  = (const float*)d_in[10];
    const float* out_b  = (const float*)d_in[11];
    const float* ln1_g  = (const float*)d_in[12];
    const float* ln1_b  = (const float*)d_in[13];
    const float* ln2_g  = (const float*)d_in[14];
    const float* ln2_b  = (const float*)d_in[15];
    const float* ln3_g  = (const float*)d_in[16];
    const float* ln3_b  = (const float*)d_in[17];
    const float* w1     = (const float*)d_in[18];
    const float* b1     = (const float*)d_in[19];
    const float* w2     = (const float*)d_in[20];
    const float* b2     = (const float*)d_in[21];
    float* outp = (float*)d_out;

    float* gs = nullptr;
    cudaGetSymbolAddress((void**)&gs, g_scratch);
    __half* gh = nullptr;
    cudaGetSymbolAddress((void**)&gh, g_hf);

    cudaFuncSetAttribute(k_flash, cudaFuncAttributeMaxDynamicSharedMemorySize, FLASH_SMEM);
    cudaFuncSetAttribute(k_gemm<0>, cudaFuncAttributeMaxDynamicSharedMemorySize, G_SMEM0);
    cudaFuncSetAttribute(k_gemm<1>, cudaFuncAttributeMaxDynamicSharedMemorySize, G_SMEM0);
    cudaFuncSetAttribute(k_gemm<3>, cudaFuncAttributeMaxDynamicSharedMemorySize, G_SMEM0);

    __half *Xh = gh + ZX;
    __half *X1h = gh + ZX1;
    __half *Ath = gh + ZATT;
    __half *X2h = gh + ZX2;
    __half *Qh = gh + ZQKV;
    __half *Fh = gh + ZFFN;
    __half *WLRh = gh + ZWLR;
    __half *INh = gh + ZIN;
    __half *OWh = gh + ZOW;
    __half *W1h = gh + ZW1;
    __half *W2h = gh + ZW2;

    // CSR build + bias concat
    k_setup<<<16, 256>>>(gat_bl, gat_br, gs + S_BIAS);
    k_count<<<EE / 256, 256>>>(ei);
    k_scan<<<1, 1024>>>();
    k_scatter<<<EE / 256, 256>>>(ei);

    // one-shot convert: x + all weights
    k_convert<<<(int)((C_B6 + 255) / 256), 256>>>(x, gat_wl, gat_wr, in_w, out_w, w1, w2);

    // merged GAT projections
    dim3 glr(1024 / 64, NN / 128);
    k_gemm<0><<<glr, 256, G_SMEM0>>>(Xh, WLRh, gs + S_BIAS, gs + S_XLR, 0, 1024, CC);

    // fused GAT aggregation + residual + LN1
    k_gat_ln<<<NN, 256>>>(gs + S_XLR, gat_at, gat_b, x, ln1_g, ln1_b, gs + S_X1, X1h);

    // QKV (hi fp16 out, Q pre-scaled)
    dim3 gqkv(QKVW / 64, NN / 128);
    k_gemm<3><<<gqkv, 256, G_SMEM0>>>(X1h, INh, in_b, 0, Qh, QKVW, CC);

    // flash attention
    dim3 gfl(NN / 128, HH);
    k_flash<<<gfl, 256, FLASH_SMEM>>>(Qh, Ath);

    // out proj (fp32 out)
    dim3 g512(CC / 64, NN / 128);
    k_gemm<0><<<g512, 256, G_SMEM0>>>(Ath, OWh, out_b, gs + S_HB, 0, CC, CC);

    // x2 = LN(x1 + h_global), hi out
    k_add_ln<<<NN, 256>>>(gs + S_X1, gs + S_HB, ln2_g, ln2_b, gs + S_X2, X2h);

    // FFN1 (GELU, hi out)
    dim3 gffn1(4 * CC / 64, NN / 128);
    k_gemm<1><<<gffn1, 256, G_SMEM0>>>(X2h, W1h, b1, 0, Fh, 4 * CC, CC);
    // FFN2 (fp32 out)
    k_gemm<0><<<g512, 256, G_SMEM0>>>(Fh, W2h, b2, gs + S_HB, 0, CC, 4 * CC);

    // out = LN(x2 + ffn)
    k_add_ln<<<NN, 256>>>(gs + S_X2, gs + S_HB, ln3_g, ln3_b, outp, 0);
}